// round 5
// baseline (speedup 1.0000x reference)
#include <cuda_runtime.h>
#include <cuda_bf16.h>
#include <cstdint>

// Problem constants
#define Bn 4
#define Tn 2048
#define Cn 512
#define Hn 8
#define Dn 64
__device__ __constant__ float kScale = 0.04419417382415922f; // 512^-0.5

// ---------------------------------------------------------------------------
// Global scratch (bf16 hi/lo pairs; no allocation allowed)
// ---------------------------------------------------------------------------
#define NX  (Bn*Tn*Cn)
#define NW  (Hn*Cn*Dn)
#define NR  (Hn*Tn*Dn)
#define NP  (Cn*Cn)
#define NQ  (Bn*Hn*Tn*Dn)

__device__ __align__(16) __nv_bfloat16 g_xh[NX],  g_xl[NX];
__device__ __align__(16) __nv_bfloat16 g_wth[3*NW], g_wtl[3*NW];   // [mat][h][d][k]
__device__ __align__(16) __nv_bfloat16 g_relh[NR], g_rell[NR];
__device__ __align__(16) __nv_bfloat16 g_wpth[NP], g_wptl[NP];     // [n][k]
__device__ __align__(16) __nv_bfloat16 g_qh[NQ], g_ql[NQ];
__device__ __align__(16) __nv_bfloat16 g_kh[NQ], g_kl[NQ];
__device__ __align__(16) __nv_bfloat16 g_vh[NQ], g_vl[NQ];
__device__ __align__(16) __nv_bfloat16 g_atth[NX], g_attl[NX];

// ---------------------------------------------------------------------------
// helpers
// ---------------------------------------------------------------------------
__device__ __forceinline__ uint32_t smem_u32(const void* p) {
    uint32_t a;
    asm("{ .reg .u64 t; cvta.to.shared.u64 t, %1; cvt.u32.u64 %0, t; }"
        : "=r"(a) : "l"(p));
    return a;
}

__device__ __forceinline__ void ldmx4(uint32_t* r, uint32_t addr) {
    asm volatile("ldmatrix.sync.aligned.m8n8.x4.shared.b16 {%0,%1,%2,%3}, [%4];"
                 : "=r"(r[0]), "=r"(r[1]), "=r"(r[2]), "=r"(r[3]) : "r"(addr));
}
__device__ __forceinline__ void ldmx4t(uint32_t* r, uint32_t addr) {
    asm volatile("ldmatrix.sync.aligned.m8n8.x4.trans.shared.b16 {%0,%1,%2,%3}, [%4];"
                 : "=r"(r[0]), "=r"(r[1]), "=r"(r[2]), "=r"(r[3]) : "r"(addr));
}

__device__ __forceinline__ void mma16816(float* c, const uint32_t* a,
                                         uint32_t b0, uint32_t b1) {
    asm volatile(
        "mma.sync.aligned.m16n8k16.row.col.f32.bf16.bf16.f32 "
        "{%0,%1,%2,%3}, {%4,%5,%6,%7}, {%8,%9}, {%0,%1,%2,%3};"
        : "+f"(c[0]), "+f"(c[1]), "+f"(c[2]), "+f"(c[3])
        : "r"(a[0]), "r"(a[1]), "r"(a[2]), "r"(a[3]), "r"(b0), "r"(b1));
}

__device__ __forceinline__ void split2(float x0, float x1, uint32_t& hi2, uint32_t& lo2) {
    asm("cvt.rn.bf16x2.f32 %0, %1, %2;" : "=r"(hi2) : "f"(x1), "f"(x0));
    float h0 = __uint_as_float(hi2 << 16);
    float h1 = __uint_as_float(hi2 & 0xFFFF0000u);
    float l0 = x0 - h0, l1 = x1 - h1;
    asm("cvt.rn.bf16x2.f32 %0, %1, %2;" : "=r"(lo2) : "f"(l1), "f"(l0));
}

__device__ __forceinline__ void cpa16(uint32_t dst, const void* src) {
    asm volatile("cp.async.cg.shared.global [%0], [%1], 16;" :: "r"(dst), "l"(src));
}
__device__ __forceinline__ void cpa_wait_all() {
    asm volatile("cp.async.wait_all;" ::: "memory");
}

// bf16 smem tiles padded to 72 elems = 144B rows (9 x 16B phases, conflict-free)
#define LDT 144

// Copy one 64x64 bf16 tile (hi+lo) gmem->smem via cp.async. 256 threads.
__device__ __forceinline__ void tile_cp(uint32_t smH, uint32_t smL,
                                        const __nv_bfloat16* gh,
                                        const __nv_bfloat16* gl,
                                        size_t rowbase, int tid)
{
    #pragma unroll
    for (int i = 0; i < 2; i++) {
        int u = tid + i * 256;              // 512 chunks of 8 elems
        int row = u >> 3, g = u & 7;
        uint32_t d = (uint32_t)(row * LDT + g * 16);
        size_t s = rowbase + (size_t)row * Dn + g * 8;
        cpa16(smH + d, gh + s);
        cpa16(smL + d, gl + s);
    }
}

// ---------------------------------------------------------------------------
// Pre-split kernels
// ---------------------------------------------------------------------------
__global__ void split_f32(const float* __restrict__ src,
                          __nv_bfloat16* __restrict__ hi,
                          __nv_bfloat16* __restrict__ lo, int n4)
{
    int i = blockIdx.x * blockDim.x + threadIdx.x;
    if (i >= n4) return;
    float4 v = reinterpret_cast<const float4*>(src)[i];
    uint32_t ha, la, hb, lb;
    split2(v.x, v.y, ha, la);
    split2(v.z, v.w, hb, lb);
    reinterpret_cast<uint2*>(hi)[i] = make_uint2(ha, hb);
    reinterpret_cast<uint2*>(lo)[i] = make_uint2(la, lb);
}

__global__ void split_tr(const float* __restrict__ src,
                         __nv_bfloat16* __restrict__ hi,
                         __nv_bfloat16* __restrict__ lo, int rows, int cols)
{
    int b = blockIdx.y;
    int i = blockIdx.x * blockDim.x + threadIdx.x;
    if (i >= rows * cols) return;
    int r = i / cols, c = i % cols;
    float w = src[(size_t)b * rows * cols + i];
    __nv_bfloat16 hb = __float2bfloat16(w);
    __nv_bfloat16 lb = __float2bfloat16(w - __bfloat162float(hb));
    size_t o = (size_t)b * rows * cols + (size_t)c * rows + r;
    hi[o] = hb;
    lo[o] = lb;
}

// ---------------------------------------------------------------------------
// Kernel 1: fused QKV projection (q,k,v of one head share the A tile).
// grid = (64 m-tiles of 128, 8 heads), 256 threads. cp.async double-buffered.
// smem buffer: A hi/lo (128x64) + 3x B hi/lo (64x64) = 92160 B; x2 = 184320.
// ---------------------------------------------------------------------------
#define QB(b)   ((b) * 92160)
#define Q_AH    0
#define Q_AL    18432
#define Q_BH(w) (36864 + (w) * 18432)
#define Q_BL(w) (36864 + (w) * 18432 + 9216)
#define QKV_SMEM 184320

__global__ __launch_bounds__(256) void qkv_mm()
{
    extern __shared__ char smc[];
    const uint32_t smb = smem_u32(smc);
    const int tid = threadIdx.x;
    const int wm  = tid >> 5;
    const int lane = tid & 31;
    const int lr = lane & 15;
    const int lc = (lane >> 4) << 3;

    const int m0 = blockIdx.x * 128;
    const int h  = blockIdx.y;

    float c[3][8][4] = {};

    // issue loads for kb=0 into buf0
    {
        const int c0 = 0;
        #pragma unroll
        for (int i = 0; i < 4; i++) {
            int u = tid + i * 256;
            int row = u >> 3, g = u & 7;
            size_t src = (size_t)(m0 + row) * Cn + c0 + g * 8;
            uint32_t dst = QB(0) + (uint32_t)(row * LDT + g * 16);
            cpa16(smb + Q_AH + dst, g_xh + src);
            cpa16(smb + Q_AL + dst, g_xl + src);
        }
        #pragma unroll
        for (int w = 0; w < 3; w++) {
            const __nv_bfloat16* Wh = g_wth + (size_t)(w * 8 + h) * Cn * Dn;
            const __nv_bfloat16* Wl = g_wtl + (size_t)(w * 8 + h) * Cn * Dn;
            #pragma unroll
            for (int i = 0; i < 2; i++) {
                int u = tid + i * 256;
                int d = u >> 3, g = u & 7;
                size_t src = (size_t)d * Cn + c0 + g * 8;
                uint32_t dst = QB(0) + (uint32_t)(d * LDT + g * 16);
                cpa16(smb + Q_BH(w) + dst, Wh + src);
                cpa16(smb + Q_BL(w) + dst, Wl + src);
            }
        }
    }

    for (int kb = 0; kb < 8; kb++) {
        cpa_wait_all();
        __syncthreads();
        const uint32_t cur = QB(kb & 1);

        if (kb + 1 < 8) {
            const int c0 = (kb + 1) * 64;
            const uint32_t nb = QB((kb + 1) & 1);
            #pragma unroll
            for (int i = 0; i < 4; i++) {
                int u = tid + i * 256;
                int row = u >> 3, g = u & 7;
                size_t src = (size_t)(m0 + row) * Cn + c0 + g * 8;
                uint32_t dst = nb + (uint32_t)(row * LDT + g * 16);
                cpa16(smb + Q_AH + dst, g_xh + src);
                cpa16(smb + Q_AL + dst, g_xl + src);
            }
            #pragma unroll
            for (int w = 0; w < 3; w++) {
                const __nv_bfloat16* Wh = g_wth + (size_t)(w * 8 + h) * Cn * Dn;
                const __nv_bfloat16* Wl = g_wtl + (size_t)(w * 8 + h) * Cn * Dn;
                #pragma unroll
                for (int i = 0; i < 2; i++) {
                    int u = tid + i * 256;
                    int d = u >> 3, g = u & 7;
                    size_t src = (size_t)d * Cn + c0 + g * 8;
                    uint32_t dst = nb + (uint32_t)(d * LDT + g * 16);
                    cpa16(smb + Q_BH(w) + dst, Wh + src);
                    cpa16(smb + Q_BL(w) + dst, Wl + src);
                }
            }
        }

        #pragma unroll
        for (int ks = 0; ks < 4; ks++) {
            const int k0 = ks * 16;
            uint32_t a_hi[4], a_lo[4];
            uint32_t aoff = cur + (uint32_t)((wm * 16 + lr) * LDT + (k0 + lc) * 2);
            ldmx4(a_hi, smb + Q_AH + aoff);
            ldmx4(a_lo, smb + Q_AL + aoff);
            #pragma unroll
            for (int w = 0; w < 3; w++) {
                #pragma unroll
                for (int ng = 0; ng < 4; ng++) {
                    uint32_t bh[4], bl[4];
                    uint32_t boff = cur + (uint32_t)((ng * 16 + lr) * LDT + (k0 + lc) * 2);
                    ldmx4(bh, smb + Q_BH(w) + boff);
                    ldmx4(bl, smb + Q_BL(w) + boff);
                    mma16816(c[w][2*ng],   a_hi, bh[0], bh[2]);
                    mma16816(c[w][2*ng],   a_hi, bl[0], bl[2]);
                    mma16816(c[w][2*ng],   a_lo, bh[0], bh[2]);
                    mma16816(c[w][2*ng+1], a_hi, bh[1], bh[3]);
                    mma16816(c[w][2*ng+1], a_hi, bl[1], bl[3]);
                    mma16816(c[w][2*ng+1], a_lo, bh[1], bh[3]);
                }
            }
        }
        __syncthreads();
    }

    const int gid = lane >> 2, qc = (lane & 3) * 2;
    #pragma unroll
    for (int w = 0; w < 3; w++) {
        __nv_bfloat16* outh = (w == 0 ? g_qh : (w == 1 ? g_kh : g_vh));
        __nv_bfloat16* outl = (w == 0 ? g_ql : (w == 1 ? g_kl : g_vl));
        #pragma unroll
        for (int rr = 0; rr < 2; rr++) {
            int m = m0 + wm * 16 + gid + rr * 8;
            int b = m >> 11, t = m & 2047;
            size_t base = (((size_t)(b * Hn + h)) * Tn + t) * Dn;
            #pragma unroll
            for (int j = 0; j < 8; j++) {
                uint32_t hp, lp;
                split2(c[w][j][rr*2], c[w][j][rr*2 + 1], hp, lp);
                size_t e = base + j * 8 + qc;
                *reinterpret_cast<uint32_t*>(outh + e) = hp;
                *reinterpret_cast<uint32_t*>(outl + e) = lp;
            }
        }
    }
}

// ---------------------------------------------------------------------------
// Kernel 3: output projection + bias. (unchanged from R4)
// ---------------------------------------------------------------------------
#define OFF_AH 0
#define OFF_AL 18432
#define OFF_BH 36864
#define OFF_BL 46080
#define GEMM_SMEM 55296

__global__ __launch_bounds__(256) void proj_mm(
    const float* __restrict__ bp, float* __restrict__ outp)
{
    extern __shared__ char smc[];
    const uint32_t smb = smem_u32(smc);
    const int tid = threadIdx.x;
    const int wm  = tid >> 5;
    const int lane = tid & 31;

    const int m0 = blockIdx.x * 128;
    const int n0 = blockIdx.y * 64;

    float c[8][4] = {};
    const int lr = lane & 15;
    const int lc = (lane >> 4) << 3;

    for (int kb = 0; kb < 8; kb++) {
        const int c0 = kb * 64;
        #pragma unroll
        for (int i = 0; i < 4; i++) {
            int u = tid + i * 256;
            int row = u >> 3, g = u & 7;
            size_t src = (size_t)(m0 + row) * Cn + c0 + g * 8;
            uint32_t dst = (uint32_t)(row * LDT + g * 16);
            cpa16(smb + OFF_AH + dst, g_atth + src);
            cpa16(smb + OFF_AL + dst, g_attl + src);
        }
        #pragma unroll
        for (int i = 0; i < 2; i++) {
            int u = tid + i * 256;
            int d = u >> 3, g = u & 7;
            size_t src = (size_t)(n0 + d) * Cn + c0 + g * 8;
            uint32_t dst = (uint32_t)(d * LDT + g * 16);
            cpa16(smb + OFF_BH + dst, g_wpth + src);
            cpa16(smb + OFF_BL + dst, g_wptl + src);
        }
        cpa_wait_all();
        __syncthreads();

        #pragma unroll
        for (int ks = 0; ks < 4; ks++) {
            const int k0 = ks * 16;
            uint32_t a_hi[4], a_lo[4];
            uint32_t aoff = (uint32_t)((wm * 16 + lr) * LDT + (k0 + lc) * 2);
            ldmx4(a_hi, smb + OFF_AH + aoff);
            ldmx4(a_lo, smb + OFF_AL + aoff);
            #pragma unroll
            for (int ng = 0; ng < 4; ng++) {
                uint32_t bh[4], bl[4];
                uint32_t boff = (uint32_t)((ng * 16 + lr) * LDT + (k0 + lc) * 2);
                ldmx4(bh, smb + OFF_BH + boff);
                ldmx4(bl, smb + OFF_BL + boff);
                mma16816(c[2*ng],   a_hi, bh[0], bh[2]);
                mma16816(c[2*ng],   a_hi, bl[0], bl[2]);
                mma16816(c[2*ng],   a_lo, bh[0], bh[2]);
                mma16816(c[2*ng+1], a_hi, bh[1], bh[3]);
                mma16816(c[2*ng+1], a_hi, bl[1], bl[3]);
                mma16816(c[2*ng+1], a_lo, bh[1], bh[3]);
            }
        }
        __syncthreads();
    }

    const int gid = lane >> 2, qc = (lane & 3) * 2;
    #pragma unroll
    for (int rr = 0; rr < 2; rr++) {
        int m = m0 + wm * 16 + gid + rr * 8;
        float* op = outp + (size_t)m * Cn + n0;
        #pragma unroll
        for (int j = 0; j < 8; j++) {
            float2 bv = *reinterpret_cast<const float2*>(bp + n0 + j * 8 + qc);
            *reinterpret_cast<float2*>(op + j * 8 + qc) =
                make_float2(c[j][rr*2] + bv.x, c[j][rr*2 + 1] + bv.y);
        }
    }
}

// ---------------------------------------------------------------------------
// Kernel 2: flash attention, two query blocks per CTA (256 threads).
// Warps 0-3: q-block t0; warps 4-7: q-block t0+64. Shared K/V tiles; rel
// windows in a 3-deep rotating buffer (B reuses A's previous window).
// cp.async double-buffered K/V.
// ---------------------------------------------------------------------------
#define A_KB(b)  ((b) * 36864)          // KH +0, KL +9216, VH +18432, VL +27648
#define A_WB(w)  (73728 + (w) * 18432)  // WH +0, WL +9216
#define A_RA0 129024
#define A_RA1 145920
#define A_RB0 162816
#define A_RB1 179712
#define ATT_SMEM 196608
#define LDR 66

__global__ __launch_bounds__(256) void attn_mm(const float* __restrict__ rel)
{
    extern __shared__ char smc[];
    const uint32_t smb = smem_u32(smc);
    float* Rf = reinterpret_cast<float*>(smc);

    const int tid = threadIdx.x;
    const int wm  = tid >> 5;
    const int lane = tid & 31;
    const int lr = lane & 15;
    const int lc = (lane >> 4) << 3;
    const int gid = lane >> 2, qc = (lane & 3) * 2;
    const int grp = wm >> 2;            // 0: q-block t0, 1: q-block t0+64
    const int wg  = wm & 3;

    const int bh = blockIdx.x;
    const int h  = bh & (Hn - 1);
    const int b  = bh >> 3;
    const int pair = (int)(gridDim.y - 1 - blockIdx.y);
    const int t0 = pair * 128;
    const int tq = t0 + 64 * grp;

    const __nv_bfloat16* qgh = g_qh + (size_t)bh * Tn * Dn;
    const __nv_bfloat16* qgl = g_ql + (size_t)bh * Tn * Dn;
    const __nv_bfloat16* kgh = g_kh + (size_t)bh * Tn * Dn;
    const __nv_bfloat16* kgl = g_kl + (size_t)bh * Tn * Dn;
    const __nv_bfloat16* vgh = g_vh + (size_t)bh * Tn * Dn;
    const __nv_bfloat16* vgl = g_vl + (size_t)bh * Tn * Dn;
    const __nv_bfloat16* rgh = g_relh + (size_t)h * Tn * Dn;
    const __nv_bfloat16* rgl = g_rell + (size_t)h * Tn * Dn;
    const float*         relf = rel + (size_t)h * Tn * Dn;

    // ---- preload: Q (both groups) into KV buf1; P_B->WB1, P_A->WB2; K/V(0)->buf0; W(0)->WB0
    tile_cp(smb + A_KB(1) + 0,     smb + A_KB(1) + 9216,  qgh, qgl, (size_t)t0 * Dn, tid);
    tile_cp(smb + A_KB(1) + 18432, smb + A_KB(1) + 27648, qgh, qgl, (size_t)(t0 + 64) * Dn, tid);
    tile_cp(smb + A_WB(1), smb + A_WB(1) + 9216, rgh, rgl, (size_t)(Tn - 128 - t0) * Dn, tid);
    tile_cp(smb + A_WB(2), smb + A_WB(2) + 9216, rgh, rgl, (size_t)(Tn - 64 - t0) * Dn, tid);
    tile_cp(smb + A_KB(0) + 0,     smb + A_KB(0) + 9216,  kgh, kgl, 0, tid);
    tile_cp(smb + A_KB(0) + 18432, smb + A_KB(0) + 27648, vgh, vgl, 0, tid);
    if (t0 > 0)
        tile_cp(smb + A_WB(0), smb + A_WB(0) + 9216, rgh, rgl, (size_t)(Tn - t0) * Dn, tid);
    cpa_wait_all();
    __syncthreads();

    // Q fragments (group g reads its staged tile)
    uint32_t q_hi[4][4], q_lo[4][4];
    {
        uint32_t qb = smb + A_KB(1) + (grp ? 18432 : 0);
        #pragma unroll
        for (int ks = 0; ks < 4; ks++) {
            uint32_t aoff = (uint32_t)((wg * 16 + lr) * LDT + (ks * 16 + lc) * 2);
            ldmx4(q_hi[ks], qb + aoff);
            ldmx4(q_lo[ks], qb + 9216 + aoff);
        }
    }

    // preload R_low: group A from WB2 (P_A), group B from WB1 (P_B)
    int rprev = grp ? A_RB0 : A_RA0;
    int rnew  = grp ? A_RB1 : A_RA1;
    {
        uint32_t wb = smb + (grp ? A_WB(1) : A_WB(2));
        float c[8][4] = {};
        #pragma unroll
        for (int ks = 0; ks < 4; ks++) {
            #pragma unroll
            for (int ng = 0; ng < 4; ng++) {
                uint32_t bh4[4], bl4[4];
                uint32_t boff = (uint32_t)((ng * 16 + lr) * LDT + (ks * 16 + lc) * 2);
                ldmx4(bh4, wb + boff);
                ldmx4(bl4, wb + 9216 + boff);
                mma16816(c[2*ng],   q_hi[ks], bh4[0], bh4[2]);
                mma16816(c[2*ng],   q_hi[ks], bl4[0], bl4[2]);
                mma16816(c[2*ng],   q_lo[ks], bh4[0], bh4[2]);
                mma16816(c[2*ng+1], q_hi[ks], bh4[1], bh4[3]);
                mma16816(c[2*ng+1], q_hi[ks], bl4[1], bl4[3]);
                mma16816(c[2*ng+1], q_lo[ks], bh4[1], bh4[3]);
            }
        }
        float* Rp = Rf + rprev / 4;
        #pragma unroll
        for (int j = 0; j < 8; j++) {
            *reinterpret_cast<float2*>(Rp + (wg*16 + gid)     * LDR + j*8 + qc) =
                make_float2(c[j][0], c[j][1]);
            *reinterpret_cast<float2*>(Rp + (wg*16 + gid + 8) * LDR + j*8 + qc) =
                make_float2(c[j][2], c[j][3]);
        }
        __syncwarp();
    }
    __syncthreads();   // everyone done with KV buf1 (Q staging) before prefetch reuses it

    float o[8][4] = {};
    float mrow[2] = {-1e30f, -1e30f};
    float lrow[2] = {};

    const int ntiles = t0 / 64 + 2;
    for (int i = 0; i < ntiles; i++) {
        const int s0 = i * 64;
        if (i) cpa_wait_all();
        __syncthreads();

        // prefetch tile i+1
        if (i + 1 < ntiles) {
            const int s1 = s0 + 64;
            uint32_t nb = smb + A_KB((i + 1) & 1);
            tile_cp(nb + 0,     nb + 9216,  kgh, kgl, (size_t)s1 * Dn, tid);
            tile_cp(nb + 18432, nb + 27648, vgh, vgl, (size_t)s1 * Dn, tid);
            if (s1 < t0)
                tile_cp(smb + A_WB((i + 1) % 3), smb + A_WB((i + 1) % 3) + 9216,
                        rgh, rgl, (size_t)(Tn - t0 + s1) * Dn, tid);
        }

        const bool act  = (s0 <= tq);
        const bool hasR = (s0 < tq);
        const uint32_t kb = smb + A_KB(i & 1);

        if (act) {
            float c[8][4];

            // ---- R GEMM: Rnew = Q * Win^T ----
            if (hasR) {
                uint32_t wb = smb + (grp ? A_WB((i + 2) % 3) : A_WB(i % 3));
                #pragma unroll
                for (int j = 0; j < 8; j++)
                    #pragma unroll
                    for (int z = 0; z < 4; z++) c[j][z] = 0.f;
                #pragma unroll
                for (int ks = 0; ks < 4; ks++) {
                    #pragma unroll
                    for (int ng = 0; ng < 4; ng++) {
                        uint32_t bh4[4], bl4[4];
                        uint32_t boff = (uint32_t)((ng * 16 + lr) * LDT + (ks * 16 + lc) * 2);
                        ldmx4(bh4, wb + boff);
                        ldmx4(bl4, wb + 9216 + boff);
                        mma16816(c[2*ng],   q_hi[ks], bh4[0], bh4[2]);
                        mma16816(c[2*ng],   q_hi[ks], bl4[0], bl4[2]);
                        mma16816(c[2*ng],   q_lo[ks], bh4[0], bh4[2]);
                        mma16816(c[2*ng+1], q_hi[ks], bh4[1], bh4[3]);
                        mma16816(c[2*ng+1], q_hi[ks], bl4[1], bl4[3]);
                        mma16816(c[2*ng+1], q_lo[ks], bh4[1], bh4[3]);
                    }
                }
                float* Rp = Rf + rnew / 4;
                #pragma unroll
                for (int j = 0; j < 8; j++) {
                    *reinterpret_cast<float2*>(Rp + (wg*16 + gid)     * LDR + j*8 + qc) =
                        make_float2(c[j][0], c[j][1]);
                    *reinterpret_cast<float2*>(Rp + (wg*16 + gid + 8) * LDR + j*8 + qc) =
                        make_float2(c[j][2], c[j][3]);
                }
                __syncwarp();
            }

            // ---- S GEMM: S = Q * K^T ----
            #pragma unroll
            for (int j = 0; j < 8; j++)
                #pragma unroll
                for (int z = 0; z < 4; z++) c[j][z] = 0.f;
            #pragma unroll
            for (int ks = 0; ks < 4; ks++) {
                #pragma unroll
                for (int ng = 0; ng < 4; ng++) {
                    uint32_t bh4[4], bl4[4];
                    uint32_t boff = (uint32_t)((ng * 16 + lr) * LDT + (ks * 16 + lc) * 2);
                    ldmx4(bh4, kb + boff);
                    ldmx4(bl4, kb + 9216 + boff);
                    mma16816(c[2*ng],   q_hi[ks], bh4[0], bh4[2]);
                    mma16816(c[2*ng],   q_hi[ks], bl4[0], bl4[2]);
                    mma16816(c[2*ng],   q_lo[ks], bh4[0], bh4[2]);
                    mma16816(c[2*ng+1], q_hi[ks], bh4[1], bh4[3]);
                    mma16816(c[2*ng+1], q_hi[ks], bl4[1], bl4[3]);
                    mma16816(c[2*ng+1], q_lo[ks], bh4[1], bh4[3]);
                }
            }

            // ---- gather BD ----
            {
                const float* Rp = Rf + rprev / 4;
                const float* Rn = Rf + rnew / 4;
                #pragma unroll
                for (int rr = 0; rr < 2; rr++) {
                    int tl = wg*16 + gid + rr*8;
                    #pragma unroll
                    for (int j = 0; j < 8; j++) {
                        #pragma unroll
                        for (int z = 0; z < 2; z++) {
                            int sl = j*8 + qc + z;
                            int jj = sl - tl + 63;
                            if (jj < 64) c[j][rr*2 + z] += Rp[tl * LDR + jj];
                            else if (hasR) c[j][rr*2 + z] += Rn[tl * LDR + jj - 64];
                        }
                    }
                }
            }

            // ---- wrap corner (global tile 0,0 only) ----
            if (tq == 0 && s0 == 0 && wg == 0 && gid < 5) {
                int t = gid;
                #pragma unroll
                for (int z = 0; z < 2; z++) {
                    int s = qc + z;
                    if (s > t + 1 && s < 6) {
                        float bd = 0.f;
                        for (int d = 0; d < 64; d++) {
                            float qv = __bfloat162float(qgh[(t + 1) * Dn + d])
                                     + __bfloat162float(qgl[(t + 1) * Dn + d]);
                            bd += qv * relf[(size_t)(s - t - 2) * Dn + d];
                        }
                        c[0][z] += bd;
                    }
                }
            }

            // ---- mask + scale + online softmax ----
            #pragma unroll
            for (int rr = 0; rr < 2; rr++) {
                int t = tq + wg*16 + gid + rr*8;
                float rm = -1e30f;
                #pragma unroll
                for (int j = 0; j < 8; j++) {
                    #pragma unroll
                    for (int z = 0; z < 2; z++) {
                        int s = s0 + j*8 + qc + z;
                        float v = (s <= t || s < 6) ? c[j][rr*2+z] * kScale : -1e30f;
                        c[j][rr*2+z] = v;
                        rm = fmaxf(rm, v);
                    }
                }
                rm = fmaxf(rm, __shfl_xor_sync(0xffffffffu, rm, 1));
                rm = fmaxf(rm, __shfl_xor_sync(0xffffffffu, rm, 2));
                float mnew = fmaxf(mrow[rr], rm);
                float alpha = __expf(mrow[rr] - mnew);
                mrow[rr] = mnew;
                float rs = 0.f;
                #pragma unroll
                for (int j = 0; j < 8; j++) {
                    #pragma unroll
                    for (int z = 0; z < 2; z++) {
                        float p = __expf(c[j][rr*2+z] - mnew);
                        c[j][rr*2+z] = p;
                        rs += p;
                    }
                }
                rs += __shfl_xor_sync(0xffffffffu, rs, 1);
                rs += __shfl_xor_sync(0xffffffffu, rs, 2);
                lrow[rr] = lrow[rr] * alpha + rs;
                #pragma unroll
                for (int j = 0; j < 8; j++) {
                    o[j][rr*2]   *= alpha;
                    o[j][rr*2+1] *= alpha;
                }
            }

            // ---- P split ----
            uint32_t p_hi[4][4], p_lo[4][4];
            #pragma unroll
            for (int kc = 0; kc < 4; kc++) {
                split2(c[2*kc][0],   c[2*kc][1],   p_hi[kc][0], p_lo[kc][0]);
                split2(c[2*kc][2],   c[2*kc][3],   p_hi[kc][1], p_lo[kc][1]);
                split2(c[2*kc+1][0], c[2*kc+1][1], p_hi[kc][2], p_lo[kc][2]);
                split2(c[2*kc+1][2], c[2*kc+1][3], p_hi[kc][3], p_lo[kc][3]);
            }

            // ---- O += P * V ----
            #pragma unroll
            for (int kc = 0; kc < 4; kc++) {
                uint32_t vbase = (uint32_t)(kc*16 + (lane & 7) + ((lane & 16) >> 1)) * LDT;
                #pragma unroll
                for (int ng = 0; ng < 4; ng++) {
                    uint32_t bh4[4], bl4[4];
                    uint32_t voff = vbase + (uint32_t)(ng*16 + (lane & 8)) * 2;
                    ldmx4t(bh4, kb + 18432 + voff);
                    ldmx4t(bl4, kb + 27648 + voff);
                    mma16816(o[2*ng],   p_hi[kc], bh4[0], bh4[2]);
                    mma16816(o[2*ng],   p_hi[kc], bl4[0], bl4[2]);
                    mma16816(o[2*ng],   p_lo[kc], bh4[0], bh4[2]);
                    mma16816(o[2*ng+1], p_hi[kc], bh4[1], bh4[3]);
                    mma16816(o[2*ng+1], p_hi[kc], bl4[1], bl4[3]);
                    mma16816(o[2*ng+1], p_lo[kc], bh4[1], bh4[3]);
                }
            }

            if (hasR) { int tp = rprev; rprev = rnew; rnew = tp; }
        }
    }

    // ---- epilogue ----
    #pragma unroll
    for (int rr = 0; rr < 2; rr++) {
        int t = tq + wg*16 + gid + rr*8;
        float inv = 1.0f / lrow[rr];
        size_t base = ((size_t)b * Tn + t) * Cn + h * Dn;
        #pragma unroll
        for (int j = 0; j < 8; j++) {
            uint32_t hp, lp;
            split2(o[j][rr*2] * inv, o[j][rr*2+1] * inv, hp, lp);
            size_t e = base + j*8 + qc;
            *reinterpret_cast<uint32_t*>(g_atth + e) = hp;
            *reinterpret_cast<uint32_t*>(g_attl + e) = lp;
        }
    }
}

// ---------------------------------------------------------------------------
extern "C" void kernel_launch(void* const* d_in, const int* in_sizes, int n_in,
                              void* d_out, int out_size)
{
    const float* x   = (const float*)d_in[0];
    const float* Wq  = (const float*)d_in[1];
    const float* Wk  = (const float*)d_in[2];
    const float* Wv  = (const float*)d_in[3];
    const float* rel = (const float*)d_in[4];
    const float* Wp  = (const float*)d_in[5];
    const float* bp  = (const float*)d_in[6];
    float* out = (float*)d_out;

    static __nv_bfloat16 *h_xh, *h_xl, *h_wth, *h_wtl, *h_relh, *h_rell,
                         *h_wpth, *h_wptl;
    static bool init = false;
    if (!init) {
        cudaGetSymbolAddress((void**)&h_xh, g_xh);
        cudaGetSymbolAddress((void**)&h_xl, g_xl);
        cudaGetSymbolAddress((void**)&h_wth, g_wth);
        cudaGetSymbolAddress((void**)&h_wtl, g_wtl);
        cudaGetSymbolAddress((void**)&h_relh, g_relh);
        cudaGetSymbolAddress((void**)&h_rell, g_rell);
        cudaGetSymbolAddress((void**)&h_wpth, g_wpth);
        cudaGetSymbolAddress((void**)&h_wptl, g_wptl);
        cudaFuncSetAttribute(qkv_mm,  cudaFuncAttributeMaxDynamicSharedMemorySize, QKV_SMEM);
        cudaFuncSetAttribute(proj_mm, cudaFuncAttributeMaxDynamicSharedMemorySize, GEMM_SMEM);
        cudaFuncSetAttribute(attn_mm, cudaFuncAttributeMaxDynamicSharedMemorySize, ATT_SMEM);
        init = true;
    }

    split_f32<<<(NX/4 + 255)/256, 256>>>(x, h_xh, h_xl, NX/4);
    split_f32<<<(NR/4 + 255)/256, 256>>>(rel, h_relh, h_rell, NR/4);
    split_tr<<<dim3((Cn*Dn + 255)/256, Hn), 256>>>(Wq, h_wth,        h_wtl,        Cn, Dn);
    split_tr<<<dim3((Cn*Dn + 255)/256, Hn), 256>>>(Wk, h_wth + NW,   h_wtl + NW,   Cn, Dn);
    split_tr<<<dim3((Cn*Dn + 255)/256, Hn), 256>>>(Wv, h_wth + 2*NW, h_wtl + 2*NW, Cn, Dn);
    split_tr<<<dim3((Cn*Cn + 255)/256, 1), 256>>>(Wp, h_wpth, h_wptl, Cn, Cn);

    qkv_mm<<<dim3(64, 8), 256, QKV_SMEM>>>();
    attn_mm<<<dim3(Bn * Hn, Tn / 128), 256, ATT_SMEM>>>(rel);
    proj_mm<<<dim3(64, 8), 256, GEMM_SMEM>>>(bp, out);
}

// round 6
// speedup vs baseline: 1.1790x; 1.1790x over previous
#include <cuda_runtime.h>
#include <cuda_fp16.h>
#include <cstdint>

// Problem constants
#define Bn 4
#define Tn 2048
#define Cn 512
#define Hn 8
#define Dn 64
__device__ __constant__ float kScale = 0.04419417382415922f; // 512^-0.5

// ---------------------------------------------------------------------------
// Global scratch (fp16; hi/lo split only where the output depends linearly)
// ---------------------------------------------------------------------------
#define NX  (Bn*Tn*Cn)
#define NW  (Hn*Cn*Dn)
#define NR  (Hn*Tn*Dn)
#define NP  (Cn*Cn)
#define NQ  (Bn*Hn*Tn*Dn)

__device__ __align__(16) __half g_xh[NX],  g_xl[NX];
__device__ __align__(16) __half g_wth[3*NW];         // [mat][h][d][k] hi (q,k,v)
__device__ __align__(16) __half g_wvl[NW];           // v lo
__device__ __align__(16) __half g_relh[NR];          // hi only
__device__ __align__(16) __half g_wpth[NP], g_wptl[NP];
__device__ __align__(16) __half g_q[NQ], g_k[NQ];    // single fp16
__device__ __align__(16) __half g_vh[NQ], g_vl[NQ];
__device__ __align__(16) __half g_atth[NX], g_attl[NX];

// ---------------------------------------------------------------------------
// helpers
// ---------------------------------------------------------------------------
__device__ __forceinline__ uint32_t smem_u32(const void* p) {
    uint32_t a;
    asm("{ .reg .u64 t; cvta.to.shared.u64 t, %1; cvt.u32.u64 %0, t; }"
        : "=r"(a) : "l"(p));
    return a;
}

__device__ __forceinline__ void ldmx4(uint32_t* r, uint32_t addr) {
    asm volatile("ldmatrix.sync.aligned.m8n8.x4.shared.b16 {%0,%1,%2,%3}, [%4];"
                 : "=r"(r[0]), "=r"(r[1]), "=r"(r[2]), "=r"(r[3]) : "r"(addr));
}
__device__ __forceinline__ void ldmx4t(uint32_t* r, uint32_t addr) {
    asm volatile("ldmatrix.sync.aligned.m8n8.x4.trans.shared.b16 {%0,%1,%2,%3}, [%4];"
                 : "=r"(r[0]), "=r"(r[1]), "=r"(r[2]), "=r"(r[3]) : "r"(addr));
}

__device__ __forceinline__ void mma16816(float* c, const uint32_t* a,
                                         uint32_t b0, uint32_t b1) {
    asm volatile(
        "mma.sync.aligned.m16n8k16.row.col.f32.f16.f16.f32 "
        "{%0,%1,%2,%3}, {%4,%5,%6,%7}, {%8,%9}, {%0,%1,%2,%3};"
        : "+f"(c[0]), "+f"(c[1]), "+f"(c[2]), "+f"(c[3])
        : "r"(a[0]), "r"(a[1]), "r"(a[2]), "r"(a[3]), "r"(b0), "r"(b1));
}

__device__ __forceinline__ uint32_t pack2h(float x0, float x1) {
    __half h0 = __float2half_rn(x0), h1 = __float2half_rn(x1);
    return (uint32_t)__half_as_ushort(h0) | ((uint32_t)__half_as_ushort(h1) << 16);
}

__device__ __forceinline__ void split2h(float x0, float x1, uint32_t& hi2, uint32_t& lo2) {
    __half h0 = __float2half_rn(x0), h1 = __float2half_rn(x1);
    float l0 = x0 - __half2float(h0), l1 = x1 - __half2float(h1);
    hi2 = (uint32_t)__half_as_ushort(h0) | ((uint32_t)__half_as_ushort(h1) << 16);
    lo2 = (uint32_t)__half_as_ushort(__float2half_rn(l0))
        | ((uint32_t)__half_as_ushort(__float2half_rn(l1)) << 16);
}

__device__ __forceinline__ void cpa16(uint32_t dst, const void* src) {
    asm volatile("cp.async.cg.shared.global [%0], [%1], 16;" :: "r"(dst), "l"(src));
}
__device__ __forceinline__ void cpa_wait_all() {
    asm volatile("cp.async.wait_all;" ::: "memory");
}

// fp16 smem rows: 64 elems = 128B, padded to 144B (9 x 16B phases -> conflict-free)
#define LDT 144

// ---------------------------------------------------------------------------
// Pre-split kernels (lo may be null -> hi-only)
// ---------------------------------------------------------------------------
__global__ void split_f32h(const float* __restrict__ src,
                           __half* __restrict__ hi,
                           __half* __restrict__ lo, int n4)
{
    int i = blockIdx.x * blockDim.x + threadIdx.x;
    if (i >= n4) return;
    float4 v = reinterpret_cast<const float4*>(src)[i];
    if (lo) {
        uint32_t ha, la, hb, lb;
        split2h(v.x, v.y, ha, la);
        split2h(v.z, v.w, hb, lb);
        reinterpret_cast<uint2*>(hi)[i] = make_uint2(ha, hb);
        reinterpret_cast<uint2*>(lo)[i] = make_uint2(la, lb);
    } else {
        reinterpret_cast<uint2*>(hi)[i] =
            make_uint2(pack2h(v.x, v.y), pack2h(v.z, v.w));
    }
}

// Transposed split: src[b][r][c] -> dst[b][c][r]
__global__ void split_trh(const float* __restrict__ src,
                          __half* __restrict__ hi,
                          __half* __restrict__ lo, int rows, int cols)
{
    int b = blockIdx.y;
    int i = blockIdx.x * blockDim.x + threadIdx.x;
    if (i >= rows * cols) return;
    int r = i / cols, c = i % cols;
    float w = src[(size_t)b * rows * cols + i];
    __half hb = __float2half_rn(w);
    size_t o = (size_t)b * rows * cols + (size_t)c * rows + r;
    hi[o] = hb;
    if (lo) lo[o] = __float2half_rn(w - __half2float(hb));
}

// ---------------------------------------------------------------------------
// Kernel 1: QKV projection. grid = (64 m-tiles of 128, 24 = {q,k,v} x head),
// 256 threads, 55 KB smem -> 4 CTAs/SM. q,k: single fp16 (1 MMA); v: split (3).
// ---------------------------------------------------------------------------
#define Q_AH 0
#define Q_AL 18432
#define Q_BH 36864
#define Q_BL 46080
#define GEMM_SMEM 55296

__global__ __launch_bounds__(256) void qkv_mm()
{
    extern __shared__ char smc[];
    const uint32_t smb = smem_u32(smc);
    const int tid = threadIdx.x;
    const int wm  = tid >> 5;
    const int lane = tid & 31;
    const int lr = lane & 15;
    const int lc = (lane >> 4) << 3;

    const int m0   = blockIdx.x * 128;
    const int wsel = blockIdx.y >> 3;
    const int h    = blockIdx.y & 7;
    const __half* Wh = g_wth + (size_t)(wsel * 8 + h) * Cn * Dn;
    const __half* Wl = g_wvl + (size_t)h * Cn * Dn;

    float c[8][4] = {};

    for (int kb = 0; kb < 8; kb++) {
        const int c0 = kb * 64;
        #pragma unroll
        for (int i = 0; i < 4; i++) {
            int u = tid + i * 256;
            int row = u >> 3, g = u & 7;
            size_t src = (size_t)(m0 + row) * Cn + c0 + g * 8;
            uint32_t dst = (uint32_t)(row * LDT + g * 16);
            cpa16(smb + Q_AH + dst, g_xh + src);
            if (wsel == 2) cpa16(smb + Q_AL + dst, g_xl + src);
        }
        #pragma unroll
        for (int i = 0; i < 2; i++) {
            int u = tid + i * 256;
            int d = u >> 3, g = u & 7;
            size_t src = (size_t)d * Cn + c0 + g * 8;
            uint32_t dst = (uint32_t)(d * LDT + g * 16);
            cpa16(smb + Q_BH + dst, Wh + src);
            if (wsel == 2) cpa16(smb + Q_BL + dst, Wl + src);
        }
        cpa_wait_all();
        __syncthreads();

        if (wsel == 2) {
            #pragma unroll
            for (int ks = 0; ks < 4; ks++) {
                const int k0 = ks * 16;
                uint32_t a_hi[4], a_lo[4];
                uint32_t aoff = (uint32_t)((wm * 16 + lr) * LDT + (k0 + lc) * 2);
                ldmx4(a_hi, smb + Q_AH + aoff);
                ldmx4(a_lo, smb + Q_AL + aoff);
                #pragma unroll
                for (int ng = 0; ng < 4; ng++) {
                    uint32_t bh[4], bl[4];
                    uint32_t boff = (uint32_t)((ng * 16 + lr) * LDT + (k0 + lc) * 2);
                    ldmx4(bh, smb + Q_BH + boff);
                    ldmx4(bl, smb + Q_BL + boff);
                    mma16816(c[2*ng],   a_hi, bh[0], bh[2]);
                    mma16816(c[2*ng],   a_hi, bl[0], bl[2]);
                    mma16816(c[2*ng],   a_lo, bh[0], bh[2]);
                    mma16816(c[2*ng+1], a_hi, bh[1], bh[3]);
                    mma16816(c[2*ng+1], a_hi, bl[1], bl[3]);
                    mma16816(c[2*ng+1], a_lo, bh[1], bh[3]);
                }
            }
        } else {
            #pragma unroll
            for (int ks = 0; ks < 4; ks++) {
                const int k0 = ks * 16;
                uint32_t a_hi[4];
                uint32_t aoff = (uint32_t)((wm * 16 + lr) * LDT + (k0 + lc) * 2);
                ldmx4(a_hi, smb + Q_AH + aoff);
                #pragma unroll
                for (int ng = 0; ng < 4; ng++) {
                    uint32_t bh[4];
                    uint32_t boff = (uint32_t)((ng * 16 + lr) * LDT + (k0 + lc) * 2);
                    ldmx4(bh, smb + Q_BH + boff);
                    mma16816(c[2*ng],   a_hi, bh[0], bh[2]);
                    mma16816(c[2*ng+1], a_hi, bh[1], bh[3]);
                }
            }
        }
        __syncthreads();
    }

    const int gid = lane >> 2, qc = (lane & 3) * 2;
    if (wsel < 2) {
        __half* out = (wsel == 0) ? g_q : g_k;
        #pragma unroll
        for (int rr = 0; rr < 2; rr++) {
            int m = m0 + wm * 16 + gid + rr * 8;
            int b = m >> 11, t = m & 2047;
            size_t base = (((size_t)(b * Hn + h)) * Tn + t) * Dn;
            #pragma unroll
            for (int j = 0; j < 8; j++)
                *reinterpret_cast<uint32_t*>(out + base + j * 8 + qc) =
                    pack2h(c[j][rr*2], c[j][rr*2 + 1]);
        }
    } else {
        #pragma unroll
        for (int rr = 0; rr < 2; rr++) {
            int m = m0 + wm * 16 + gid + rr * 8;
            int b = m >> 11, t = m & 2047;
            size_t base = (((size_t)(b * Hn + h)) * Tn + t) * Dn;
            #pragma unroll
            for (int j = 0; j < 8; j++) {
                uint32_t hp, lp;
                split2h(c[j][rr*2], c[j][rr*2 + 1], hp, lp);
                size_t e = base + j * 8 + qc;
                *reinterpret_cast<uint32_t*>(g_vh + e) = hp;
                *reinterpret_cast<uint32_t*>(g_vl + e) = lp;
            }
        }
    }
}

// ---------------------------------------------------------------------------
// Kernel 3: output projection + bias (split fp16, 3-MMA).
// ---------------------------------------------------------------------------
__global__ __launch_bounds__(256) void proj_mm(
    const float* __restrict__ bp, float* __restrict__ outp)
{
    extern __shared__ char smc[];
    const uint32_t smb = smem_u32(smc);
    const int tid = threadIdx.x;
    const int wm  = tid >> 5;
    const int lane = tid & 31;

    const int m0 = blockIdx.x * 128;
    const int n0 = blockIdx.y * 64;

    float c[8][4] = {};
    const int lr = lane & 15;
    const int lc = (lane >> 4) << 3;

    for (int kb = 0; kb < 8; kb++) {
        const int c0 = kb * 64;
        #pragma unroll
        for (int i = 0; i < 4; i++) {
            int u = tid + i * 256;
            int row = u >> 3, g = u & 7;
            size_t src = (size_t)(m0 + row) * Cn + c0 + g * 8;
            uint32_t dst = (uint32_t)(row * LDT + g * 16);
            cpa16(smb + Q_AH + dst, g_atth + src);
            cpa16(smb + Q_AL + dst, g_attl + src);
        }
        #pragma unroll
        for (int i = 0; i < 2; i++) {
            int u = tid + i * 256;
            int d = u >> 3, g = u & 7;
            size_t src = (size_t)(n0 + d) * Cn + c0 + g * 8;
            uint32_t dst = (uint32_t)(d * LDT + g * 16);
            cpa16(smb + Q_BH + dst, g_wpth + src);
            cpa16(smb + Q_BL + dst, g_wptl + src);
        }
        cpa_wait_all();
        __syncthreads();

        #pragma unroll
        for (int ks = 0; ks < 4; ks++) {
            const int k0 = ks * 16;
            uint32_t a_hi[4], a_lo[4];
            uint32_t aoff = (uint32_t)((wm * 16 + lr) * LDT + (k0 + lc) * 2);
            ldmx4(a_hi, smb + Q_AH + aoff);
            ldmx4(a_lo, smb + Q_AL + aoff);
            #pragma unroll
            for (int ng = 0; ng < 4; ng++) {
                uint32_t bh[4], bl[4];
                uint32_t boff = (uint32_t)((ng * 16 + lr) * LDT + (k0 + lc) * 2);
                ldmx4(bh, smb + Q_BH + boff);
                ldmx4(bl, smb + Q_BL + boff);
                mma16816(c[2*ng],   a_hi, bh[0], bh[2]);
                mma16816(c[2*ng],   a_hi, bl[0], bl[2]);
                mma16816(c[2*ng],   a_lo, bh[0], bh[2]);
                mma16816(c[2*ng+1], a_hi, bh[1], bh[3]);
                mma16816(c[2*ng+1], a_hi, bl[1], bl[3]);
                mma16816(c[2*ng+1], a_lo, bh[1], bh[3]);
            }
        }
        __syncthreads();
    }

    const int gid = lane >> 2, qc = (lane & 3) * 2;
    #pragma unroll
    for (int rr = 0; rr < 2; rr++) {
        int m = m0 + wm * 16 + gid + rr * 8;
        float* op = outp + (size_t)m * Cn + n0;
        #pragma unroll
        for (int j = 0; j < 8; j++) {
            float2 bv = *reinterpret_cast<const float2*>(bp + n0 + j * 8 + qc);
            *reinterpret_cast<float2*>(op + j * 8 + qc) =
                make_float2(c[j][rr*2] + bv.x, c[j][rr*2 + 1] + bv.y);
        }
    }
}

// ---------------------------------------------------------------------------
// Kernel 2: flash attention (R4 structure). 128 threads, grid (32,32).
// S,R: single fp16 (1 MMA). PV: split fp16 (3 MMA). ~80 KB smem -> 2 CTAs/SM.
// ---------------------------------------------------------------------------
#define A_Q  0
#define A_K  9216
#define A_VH 18432
#define A_VL 27648
#define A_W  36864
#define A_R0 46080          // fp32, pitch 66
#define A_R1 62976
#define ATT_SMEM 79872
#define LDR 66

__global__ __launch_bounds__(128) void attn_mm()
{
    extern __shared__ char smc[];
    const uint32_t smb = smem_u32(smc);
    float* Rf = reinterpret_cast<float*>(smc);

    const int tid = threadIdx.x;
    const int wm  = tid >> 5;
    const int lane = tid & 31;
    const int lr = lane & 15;
    const int lc = (lane >> 4) << 3;
    const int gid = lane >> 2, qc = (lane & 3) * 2;

    const int bh = blockIdx.x;
    const int h  = bh & (Hn - 1);
    const int b  = bh >> 3;
    const int t0 = (int)(gridDim.y - 1 - blockIdx.y) * 64;

    const __half* qg  = g_q  + (size_t)bh * Tn * Dn;
    const __half* kg  = g_k  + (size_t)bh * Tn * Dn;
    const __half* vgh = g_vh + (size_t)bh * Tn * Dn;
    const __half* vgl = g_vl + (size_t)bh * Tn * Dn;
    const __half* rg  = g_relh + (size_t)h * Tn * Dn;

    // ---- preload Q + first rel window ----
    const int jbase0 = Tn - 64 - t0;
    #pragma unroll
    for (int i = 0; i < 4; i++) {
        int u = tid + i * 128;
        int row = u >> 3, g = u & 7;
        uint32_t dst = (uint32_t)(row * LDT + g * 16);
        cpa16(smb + A_Q + dst, qg + (size_t)(t0 + row) * Dn + g * 8);
        cpa16(smb + A_W + dst, rg + (size_t)(jbase0 + row) * Dn + g * 8);
    }
    cpa_wait_all();
    __syncthreads();

    uint32_t q4[4][4];
    #pragma unroll
    for (int ks = 0; ks < 4; ks++) {
        uint32_t aoff = (uint32_t)((wm * 16 + lr) * LDT + (ks * 16 + lc) * 2);
        ldmx4(q4[ks], smb + A_Q + aoff);
    }

    // ---- preload Rprev = Q * RelWin0^T (single fp16) ----
    int rprev = A_R0, rnew = A_R1;
    {
        float c[8][4] = {};
        #pragma unroll
        for (int ks = 0; ks < 4; ks++) {
            #pragma unroll
            for (int ng = 0; ng < 4; ng++) {
                uint32_t bh4[4];
                uint32_t boff = (uint32_t)((ng * 16 + lr) * LDT + (ks * 16 + lc) * 2);
                ldmx4(bh4, smb + A_W + boff);
                mma16816(c[2*ng],   q4[ks], bh4[0], bh4[2]);
                mma16816(c[2*ng+1], q4[ks], bh4[1], bh4[3]);
            }
        }
        float* Rp = Rf + rprev / 4;
        #pragma unroll
        for (int j = 0; j < 8; j++) {
            *reinterpret_cast<float2*>(Rp + (wm*16 + gid)     * LDR + j*8 + qc) =
                make_float2(c[j][0], c[j][1]);
            *reinterpret_cast<float2*>(Rp + (wm*16 + gid + 8) * LDR + j*8 + qc) =
                make_float2(c[j][2], c[j][3]);
        }
        __syncwarp();
    }

    float o[8][4] = {};
    float mrow[2] = {-1e30f, -1e30f};
    float lrow[2] = {};

    for (int s0 = 0; s0 <= t0; s0 += 64) {
        const bool diag = (s0 == t0);
        __syncthreads();     // WAR: previous tile fully consumed

        #pragma unroll
        for (int i = 0; i < 4; i++) {
            int u = tid + i * 128;
            int row = u >> 3, g = u & 7;
            uint32_t dst = (uint32_t)(row * LDT + g * 16);
            size_t s = (size_t)(s0 + row) * Dn + g * 8;
            cpa16(smb + A_K  + dst, kg  + s);
            cpa16(smb + A_VH + dst, vgh + s);
            cpa16(smb + A_VL + dst, vgl + s);
        }
        if (!diag) {
            const int jb = s0 - t0 + Tn;
            #pragma unroll
            for (int i = 0; i < 4; i++) {
                int u = tid + i * 128;
                int row = u >> 3, g = u & 7;
                uint32_t dst = (uint32_t)(row * LDT + g * 16);
                cpa16(smb + A_W + dst, rg + (size_t)(jb + row) * Dn + g * 8);
            }
        }
        cpa_wait_all();
        __syncthreads();

        float c[8][4];

        // ---- R GEMM (off-diag, single fp16) ----
        if (!diag) {
            #pragma unroll
            for (int j = 0; j < 8; j++)
                #pragma unroll
                for (int z = 0; z < 4; z++) c[j][z] = 0.f;
            #pragma unroll
            for (int ks = 0; ks < 4; ks++) {
                #pragma unroll
                for (int ng = 0; ng < 4; ng++) {
                    uint32_t bh4[4];
                    uint32_t boff = (uint32_t)((ng * 16 + lr) * LDT + (ks * 16 + lc) * 2);
                    ldmx4(bh4, smb + A_W + boff);
                    mma16816(c[2*ng],   q4[ks], bh4[0], bh4[2]);
                    mma16816(c[2*ng+1], q4[ks], bh4[1], bh4[3]);
                }
            }
            float* Rp = Rf + rnew / 4;
            #pragma unroll
            for (int j = 0; j < 8; j++) {
                *reinterpret_cast<float2*>(Rp + (wm*16 + gid)     * LDR + j*8 + qc) =
                    make_float2(c[j][0], c[j][1]);
                *reinterpret_cast<float2*>(Rp + (wm*16 + gid + 8) * LDR + j*8 + qc) =
                    make_float2(c[j][2], c[j][3]);
            }
            __syncwarp();
        }

        // ---- S GEMM (single fp16) ----
        #pragma unroll
        for (int j = 0; j < 8; j++)
            #pragma unroll
            for (int z = 0; z < 4; z++) c[j][z] = 0.f;
        #pragma unroll
        for (int ks = 0; ks < 4; ks++) {
            #pragma unroll
            for (int ng = 0; ng < 4; ng++) {
                uint32_t bh4[4];
                uint32_t boff = (uint32_t)((ng * 16 + lr) * LDT + (ks * 16 + lc) * 2);
                ldmx4(bh4, smb + A_K + boff);
                mma16816(c[2*ng],   q4[ks], bh4[0], bh4[2]);
                mma16816(c[2*ng+1], q4[ks], bh4[1], bh4[3]);
            }
        }

        // ---- gather BD ----
        {
            const float* Rp = Rf + rprev / 4;
            const float* Rn = Rf + rnew / 4;
            #pragma unroll
            for (int rr = 0; rr < 2; rr++) {
                int tl = wm*16 + gid + rr*8;
                #pragma unroll
                for (int j = 0; j < 8; j++) {
                    #pragma unroll
                    for (int z = 0; z < 2; z++) {
                        int sl = j*8 + qc + z;
                        int jj = sl - tl + 63;
                        if (jj < 64) c[j][rr*2 + z] += Rp[tl * LDR + jj];
                        else if (!diag) c[j][rr*2 + z] += Rn[tl * LDR + jj - 64];
                    }
                }
            }
        }

        // ---- wrap corner (tile 0,0 only) ----
        if (t0 == 0 && s0 == 0 && wm == 0 && gid < 5) {
            int t = gid;
            #pragma unroll
            for (int z = 0; z < 2; z++) {
                int s = qc + z;
                if (s > t + 1 && s < 6) {
                    float bd = 0.f;
                    for (int d = 0; d < 64; d++)
                        bd += __half2float(qg[(t + 1) * Dn + d])
                            * __half2float(rg[(size_t)(s - t - 2) * Dn + d]);
                    c[0][z] += bd;
                }
            }
        }

        // ---- mask + scale + online softmax ----
        #pragma unroll
        for (int rr = 0; rr < 2; rr++) {
            int t = t0 + wm*16 + gid + rr*8;
            float rm = -1e30f;
            #pragma unroll
            for (int j = 0; j < 8; j++) {
                #pragma unroll
                for (int z = 0; z < 2; z++) {
                    int s = s0 + j*8 + qc + z;
                    float v = (s <= t || s < 6) ? c[j][rr*2+z] * kScale : -1e30f;
                    c[j][rr*2+z] = v;
                    rm = fmaxf(rm, v);
                }
            }
            rm = fmaxf(rm, __shfl_xor_sync(0xffffffffu, rm, 1));
            rm = fmaxf(rm, __shfl_xor_sync(0xffffffffu, rm, 2));
            float mnew = fmaxf(mrow[rr], rm);
            float alpha = __expf(mrow[rr] - mnew);
            mrow[rr] = mnew;
            float rs = 0.f;
            #pragma unroll
            for (int j = 0; j < 8; j++) {
                #pragma unroll
                for (int z = 0; z < 2; z++) {
                    float p = __expf(c[j][rr*2+z] - mnew);
                    c[j][rr*2+z] = p;
                    rs += p;
                }
            }
            rs += __shfl_xor_sync(0xffffffffu, rs, 1);
            rs += __shfl_xor_sync(0xffffffffu, rs, 2);
            lrow[rr] = lrow[rr] * alpha + rs;
            #pragma unroll
            for (int j = 0; j < 8; j++) {
                o[j][rr*2]   *= alpha;
                o[j][rr*2+1] *= alpha;
            }
        }

        // ---- P split (fp16 hi/lo) ----
        uint32_t p_hi[4][4], p_lo[4][4];
        #pragma unroll
        for (int kc = 0; kc < 4; kc++) {
            split2h(c[2*kc][0],   c[2*kc][1],   p_hi[kc][0], p_lo[kc][0]);
            split2h(c[2*kc][2],   c[2*kc][3],   p_hi[kc][1], p_lo[kc][1]);
            split2h(c[2*kc+1][0], c[2*kc+1][1], p_hi[kc][2], p_lo[kc][2]);
            split2h(c[2*kc+1][2], c[2*kc+1][3], p_hi[kc][3], p_lo[kc][3]);
        }

        // ---- O += P * V (3-MMA split) ----
        #pragma unroll
        for (int kc = 0; kc < 4; kc++) {
            uint32_t vbase = (uint32_t)(kc*16 + (lane & 7) + ((lane & 16) >> 1)) * LDT;
            #pragma unroll
            for (int ng = 0; ng < 4; ng++) {
                uint32_t bh4[4], bl4[4];
                uint32_t voff = vbase + (uint32_t)(ng*16 + (lane & 8)) * 2;
                ldmx4t(bh4, smb + A_VH + voff);
                ldmx4t(bl4, smb + A_VL + voff);
                mma16816(o[2*ng],   p_hi[kc], bh4[0], bh4[2]);
                mma16816(o[2*ng],   p_hi[kc], bl4[0], bl4[2]);
                mma16816(o[2*ng],   p_lo[kc], bh4[0], bh4[2]);
                mma16816(o[2*ng+1], p_hi[kc], bh4[1], bh4[3]);
                mma16816(o[2*ng+1], p_hi[kc], bl4[1], bl4[3]);
                mma16816(o[2*ng+1], p_lo[kc], bh4[1], bh4[3]);
            }
        }

        if (!diag) { int tp = rprev; rprev = rnew; rnew = tp; }
    }

    // ---- epilogue: att = O / l -> split fp16 ----
    #pragma unroll
    for (int rr = 0; rr < 2; rr++) {
        int t = t0 + wm*16 + gid + rr*8;
        float inv = 1.0f / lrow[rr];
        size_t base = ((size_t)b * Tn + t) * Cn + h * Dn;
        #pragma unroll
        for (int j = 0; j < 8; j++) {
            uint32_t hp, lp;
            split2h(o[j][rr*2] * inv, o[j][rr*2+1] * inv, hp, lp);
            size_t e = base + j*8 + qc;
            *reinterpret_cast<uint32_t*>(g_atth + e) = hp;
            *reinterpret_cast<uint32_t*>(g_attl + e) = lp;
        }
    }
}

// ---------------------------------------------------------------------------
extern "C" void kernel_launch(void* const* d_in, const int* in_sizes, int n_in,
                              void* d_out, int out_size)
{
    const float* x   = (const float*)d_in[0];
    const float* Wq  = (const float*)d_in[1];
    const float* Wk  = (const float*)d_in[2];
    const float* Wv  = (const float*)d_in[3];
    const float* rel = (const float*)d_in[4];
    const float* Wp  = (const float*)d_in[5];
    const float* bp  = (const float*)d_in[6];
    float* out = (float*)d_out;

    static __half *h_xh, *h_xl, *h_wth, *h_wvl, *h_relh, *h_wpth, *h_wptl;
    static bool init = false;
    if (!init) {
        cudaGetSymbolAddress((void**)&h_xh, g_xh);
        cudaGetSymbolAddress((void**)&h_xl, g_xl);
        cudaGetSymbolAddress((void**)&h_wth, g_wth);
        cudaGetSymbolAddress((void**)&h_wvl, g_wvl);
        cudaGetSymbolAddress((void**)&h_relh, g_relh);
        cudaGetSymbolAddress((void**)&h_wpth, g_wpth);
        cudaGetSymbolAddress((void**)&h_wptl, g_wptl);
        cudaFuncSetAttribute(qkv_mm,  cudaFuncAttributeMaxDynamicSharedMemorySize, GEMM_SMEM);
        cudaFuncSetAttribute(proj_mm, cudaFuncAttributeMaxDynamicSharedMemorySize, GEMM_SMEM);
        cudaFuncSetAttribute(attn_mm, cudaFuncAttributeMaxDynamicSharedMemorySize, ATT_SMEM);
        init = true;
    }

    split_f32h<<<(NX/4 + 255)/256, 256>>>(x, h_xh, h_xl, NX/4);
    split_f32h<<<(NR/4 + 255)/256, 256>>>(rel, h_relh, nullptr, NR/4);
    split_trh<<<dim3((Cn*Dn + 255)/256, Hn), 256>>>(Wq, h_wth,        nullptr, Cn, Dn);
    split_trh<<<dim3((Cn*Dn + 255)/256, Hn), 256>>>(Wk, h_wth + NW,   nullptr, Cn, Dn);
    split_trh<<<dim3((Cn*Dn + 255)/256, Hn), 256>>>(Wv, h_wth + 2*NW, h_wvl,   Cn, Dn);
    split_trh<<<dim3((Cn*Cn + 255)/256, 1), 256>>>(Wp, h_wpth, h_wptl, Cn, Cn);

    qkv_mm<<<dim3(64, 24), 256, GEMM_SMEM>>>();
    attn_mm<<<dim3(Bn * Hn, Tn / 64), 128, ATT_SMEM>>>();
    proj_mm<<<dim3(64, 8), 256, GEMM_SMEM>>>(bp, out);
}

// round 7
// speedup vs baseline: 1.3498x; 1.1448x over previous
#include <cuda_runtime.h>
#include <cuda_fp16.h>
#include <cstdint>

// Problem constants
#define Bn 4
#define Tn 2048
#define Cn 512
#define Hn 8
#define Dn 64
__device__ __constant__ float kScale = 0.04419417382415922f; // 512^-0.5

// ---------------------------------------------------------------------------
// Global scratch (fp16; hi/lo split only where the output depends linearly)
// ---------------------------------------------------------------------------
#define NX  (Bn*Tn*Cn)
#define NW  (Hn*Cn*Dn)
#define NR  (Hn*Tn*Dn)
#define NP  (Cn*Cn)
#define NQ  (Bn*Hn*Tn*Dn)

__device__ __align__(16) __half g_xh[NX],  g_xl[NX];
__device__ __align__(16) __half g_wth[3*NW];         // [mat][h][d][k] hi (q,k,v)
__device__ __align__(16) __half g_wvl[NW];           // v lo
__device__ __align__(16) __half g_relh[NR];          // hi only
__device__ __align__(16) __half g_wpth[NP], g_wptl[NP];
__device__ __align__(16) __half g_q[NQ], g_k[NQ];    // single fp16
__device__ __align__(16) __half g_vh[NQ], g_vl[NQ];
__device__ __align__(16) __half g_atth[NX], g_attl[NX];

// ---------------------------------------------------------------------------
// helpers
// ---------------------------------------------------------------------------
__device__ __forceinline__ uint32_t smem_u32(const void* p) {
    uint32_t a;
    asm("{ .reg .u64 t; cvta.to.shared.u64 t, %1; cvt.u32.u64 %0, t; }"
        : "=r"(a) : "l"(p));
    return a;
}

__device__ __forceinline__ void ldmx4(uint32_t* r, uint32_t addr) {
    asm volatile("ldmatrix.sync.aligned.m8n8.x4.shared.b16 {%0,%1,%2,%3}, [%4];"
                 : "=r"(r[0]), "=r"(r[1]), "=r"(r[2]), "=r"(r[3]) : "r"(addr));
}
__device__ __forceinline__ void ldmx4t(uint32_t* r, uint32_t addr) {
    asm volatile("ldmatrix.sync.aligned.m8n8.x4.trans.shared.b16 {%0,%1,%2,%3}, [%4];"
                 : "=r"(r[0]), "=r"(r[1]), "=r"(r[2]), "=r"(r[3]) : "r"(addr));
}

__device__ __forceinline__ void mma16816(float* c, const uint32_t* a,
                                         uint32_t b0, uint32_t b1) {
    asm volatile(
        "mma.sync.aligned.m16n8k16.row.col.f32.f16.f16.f32 "
        "{%0,%1,%2,%3}, {%4,%5,%6,%7}, {%8,%9}, {%0,%1,%2,%3};"
        : "+f"(c[0]), "+f"(c[1]), "+f"(c[2]), "+f"(c[3])
        : "r"(a[0]), "r"(a[1]), "r"(a[2]), "r"(a[3]), "r"(b0), "r"(b1));
}

__device__ __forceinline__ uint32_t pack2h(float x0, float x1) {
    __half h0 = __float2half_rn(x0), h1 = __float2half_rn(x1);
    return (uint32_t)__half_as_ushort(h0) | ((uint32_t)__half_as_ushort(h1) << 16);
}

__device__ __forceinline__ void split2h(float x0, float x1, uint32_t& hi2, uint32_t& lo2) {
    __half h0 = __float2half_rn(x0), h1 = __float2half_rn(x1);
    float l0 = x0 - __half2float(h0), l1 = x1 - __half2float(h1);
    hi2 = (uint32_t)__half_as_ushort(h0) | ((uint32_t)__half_as_ushort(h1) << 16);
    lo2 = (uint32_t)__half_as_ushort(__float2half_rn(l0))
        | ((uint32_t)__half_as_ushort(__float2half_rn(l1)) << 16);
}

__device__ __forceinline__ void cpa16(uint32_t dst, const void* src) {
    asm volatile("cp.async.cg.shared.global [%0], [%1], 16;" :: "r"(dst), "l"(src));
}
__device__ __forceinline__ void cpa_wait_all() {
    asm volatile("cp.async.wait_all;" ::: "memory");
}
__device__ __forceinline__ void cpa_commit() {
    asm volatile("cp.async.commit_group;" ::: "memory");
}
__device__ __forceinline__ void cpa_wait1() {
    asm volatile("cp.async.wait_group 1;" ::: "memory");
}

// fp16 smem rows: 64 elems = 128B, padded to 144B (9 x 16B phases -> conflict-free)
#define LDT 144

// ---------------------------------------------------------------------------
// Pre-split kernels (lo may be null -> hi-only)
// ---------------------------------------------------------------------------
__global__ void split_f32h(const float* __restrict__ src,
                           __half* __restrict__ hi,
                           __half* __restrict__ lo, int n4)
{
    int i = blockIdx.x * blockDim.x + threadIdx.x;
    if (i >= n4) return;
    float4 v = reinterpret_cast<const float4*>(src)[i];
    if (lo) {
        uint32_t ha, la, hb, lb;
        split2h(v.x, v.y, ha, la);
        split2h(v.z, v.w, hb, lb);
        reinterpret_cast<uint2*>(hi)[i] = make_uint2(ha, hb);
        reinterpret_cast<uint2*>(lo)[i] = make_uint2(la, lb);
    } else {
        reinterpret_cast<uint2*>(hi)[i] =
            make_uint2(pack2h(v.x, v.y), pack2h(v.z, v.w));
    }
}

__global__ void split_trh(const float* __restrict__ src,
                          __half* __restrict__ hi,
                          __half* __restrict__ lo, int rows, int cols)
{
    int b = blockIdx.y;
    int i = blockIdx.x * blockDim.x + threadIdx.x;
    if (i >= rows * cols) return;
    int r = i / cols, c = i % cols;
    float w = src[(size_t)b * rows * cols + i];
    __half hb = __float2half_rn(w);
    size_t o = (size_t)b * rows * cols + (size_t)c * rows + r;
    hi[o] = hb;
    if (lo) lo[o] = __float2half_rn(w - __half2float(hb));
}

// ---------------------------------------------------------------------------
// Kernel 1: QKV projection. grid = (64 m-tiles of 128, 24 = {q,k,v} x head),
// 256 threads, 55 KB smem -> 4 CTAs/SM. q,k: single fp16 (1 MMA); v: split (3).
// ---------------------------------------------------------------------------
#define Q_AH 0
#define Q_AL 18432
#define Q_BH 36864
#define Q_BL 46080
#define GEMM_SMEM 55296

__global__ __launch_bounds__(256) void qkv_mm()
{
    extern __shared__ char smc[];
    const uint32_t smb = smem_u32(smc);
    const int tid = threadIdx.x;
    const int wm  = tid >> 5;
    const int lane = tid & 31;
    const int lr = lane & 15;
    const int lc = (lane >> 4) << 3;

    const int m0   = blockIdx.x * 128;
    const int wsel = blockIdx.y >> 3;
    const int h    = blockIdx.y & 7;
    const __half* Wh = g_wth + (size_t)(wsel * 8 + h) * Cn * Dn;
    const __half* Wl = g_wvl + (size_t)h * Cn * Dn;

    float c[8][4] = {};

    for (int kb = 0; kb < 8; kb++) {
        const int c0 = kb * 64;
        #pragma unroll
        for (int i = 0; i < 4; i++) {
            int u = tid + i * 256;
            int row = u >> 3, g = u & 7;
            size_t src = (size_t)(m0 + row) * Cn + c0 + g * 8;
            uint32_t dst = (uint32_t)(row * LDT + g * 16);
            cpa16(smb + Q_AH + dst, g_xh + src);
            if (wsel == 2) cpa16(smb + Q_AL + dst, g_xl + src);
        }
        #pragma unroll
        for (int i = 0; i < 2; i++) {
            int u = tid + i * 256;
            int d = u >> 3, g = u & 7;
            size_t src = (size_t)d * Cn + c0 + g * 8;
            uint32_t dst = (uint32_t)(d * LDT + g * 16);
            cpa16(smb + Q_BH + dst, Wh + src);
            if (wsel == 2) cpa16(smb + Q_BL + dst, Wl + src);
        }
        cpa_wait_all();
        __syncthreads();

        if (wsel == 2) {
            #pragma unroll
            for (int ks = 0; ks < 4; ks++) {
                const int k0 = ks * 16;
                uint32_t a_hi[4], a_lo[4];
                uint32_t aoff = (uint32_t)((wm * 16 + lr) * LDT + (k0 + lc) * 2);
                ldmx4(a_hi, smb + Q_AH + aoff);
                ldmx4(a_lo, smb + Q_AL + aoff);
                #pragma unroll
                for (int ng = 0; ng < 4; ng++) {
                    uint32_t bh[4], bl[4];
                    uint32_t boff = (uint32_t)((ng * 16 + lr) * LDT + (k0 + lc) * 2);
                    ldmx4(bh, smb + Q_BH + boff);
                    ldmx4(bl, smb + Q_BL + boff);
                    mma16816(c[2*ng],   a_hi, bh[0], bh[2]);
                    mma16816(c[2*ng],   a_hi, bl[0], bl[2]);
                    mma16816(c[2*ng],   a_lo, bh[0], bh[2]);
                    mma16816(c[2*ng+1], a_hi, bh[1], bh[3]);
                    mma16816(c[2*ng+1], a_hi, bl[1], bl[3]);
                    mma16816(c[2*ng+1], a_lo, bh[1], bh[3]);
                }
            }
        } else {
            #pragma unroll
            for (int ks = 0; ks < 4; ks++) {
                const int k0 = ks * 16;
                uint32_t a_hi[4];
                uint32_t aoff = (uint32_t)((wm * 16 + lr) * LDT + (k0 + lc) * 2);
                ldmx4(a_hi, smb + Q_AH + aoff);
                #pragma unroll
                for (int ng = 0; ng < 4; ng++) {
                    uint32_t bh[4];
                    uint32_t boff = (uint32_t)((ng * 16 + lr) * LDT + (k0 + lc) * 2);
                    ldmx4(bh, smb + Q_BH + boff);
                    mma16816(c[2*ng],   a_hi, bh[0], bh[2]);
                    mma16816(c[2*ng+1], a_hi, bh[1], bh[3]);
                }
            }
        }
        __syncthreads();
    }

    const int gid = lane >> 2, qc = (lane & 3) * 2;
    if (wsel < 2) {
        __half* out = (wsel == 0) ? g_q : g_k;
        #pragma unroll
        for (int rr = 0; rr < 2; rr++) {
            int m = m0 + wm * 16 + gid + rr * 8;
            int b = m >> 11, t = m & 2047;
            size_t base = (((size_t)(b * Hn + h)) * Tn + t) * Dn;
            #pragma unroll
            for (int j = 0; j < 8; j++)
                *reinterpret_cast<uint32_t*>(out + base + j * 8 + qc) =
                    pack2h(c[j][rr*2], c[j][rr*2 + 1]);
        }
    } else {
        #pragma unroll
        for (int rr = 0; rr < 2; rr++) {
            int m = m0 + wm * 16 + gid + rr * 8;
            int b = m >> 11, t = m & 2047;
            size_t base = (((size_t)(b * Hn + h)) * Tn + t) * Dn;
            #pragma unroll
            for (int j = 0; j < 8; j++) {
                uint32_t hp, lp;
                split2h(c[j][rr*2], c[j][rr*2 + 1], hp, lp);
                size_t e = base + j * 8 + qc;
                *reinterpret_cast<uint32_t*>(g_vh + e) = hp;
                *reinterpret_cast<uint32_t*>(g_vl + e) = lp;
            }
        }
    }
}

// ---------------------------------------------------------------------------
// Kernel 3: output projection + bias (split fp16, 3-MMA).
// ---------------------------------------------------------------------------
__global__ __launch_bounds__(256) void proj_mm(
    const float* __restrict__ bp, float* __restrict__ outp)
{
    extern __shared__ char smc[];
    const uint32_t smb = smem_u32(smc);
    const int tid = threadIdx.x;
    const int wm  = tid >> 5;
    const int lane = tid & 31;

    const int m0 = blockIdx.x * 128;
    const int n0 = blockIdx.y * 64;

    float c[8][4] = {};
    const int lr = lane & 15;
    const int lc = (lane >> 4) << 3;

    for (int kb = 0; kb < 8; kb++) {
        const int c0 = kb * 64;
        #pragma unroll
        for (int i = 0; i < 4; i++) {
            int u = tid + i * 256;
            int row = u >> 3, g = u & 7;
            size_t src = (size_t)(m0 + row) * Cn + c0 + g * 8;
            uint32_t dst = (uint32_t)(row * LDT + g * 16);
            cpa16(smb + Q_AH + dst, g_atth + src);
            cpa16(smb + Q_AL + dst, g_attl + src);
        }
        #pragma unroll
        for (int i = 0; i < 2; i++) {
            int u = tid + i * 256;
            int d = u >> 3, g = u & 7;
            size_t src = (size_t)(n0 + d) * Cn + c0 + g * 8;
            uint32_t dst = (uint32_t)(d * LDT + g * 16);
            cpa16(smb + Q_BH + dst, g_wpth + src);
            cpa16(smb + Q_BL + dst, g_wptl + src);
        }
        cpa_wait_all();
        __syncthreads();

        #pragma unroll
        for (int ks = 0; ks < 4; ks++) {
            const int k0 = ks * 16;
            uint32_t a_hi[4], a_lo[4];
            uint32_t aoff = (uint32_t)((wm * 16 + lr) * LDT + (k0 + lc) * 2);
            ldmx4(a_hi, smb + Q_AH + aoff);
            ldmx4(a_lo, smb + Q_AL + aoff);
            #pragma unroll
            for (int ng = 0; ng < 4; ng++) {
                uint32_t bh[4], bl[4];
                uint32_t boff = (uint32_t)((ng * 16 + lr) * LDT + (k0 + lc) * 2);
                ldmx4(bh, smb + Q_BH + boff);
                ldmx4(bl, smb + Q_BL + boff);
                mma16816(c[2*ng],   a_hi, bh[0], bh[2]);
                mma16816(c[2*ng],   a_hi, bl[0], bl[2]);
                mma16816(c[2*ng],   a_lo, bh[0], bh[2]);
                mma16816(c[2*ng+1], a_hi, bh[1], bh[3]);
                mma16816(c[2*ng+1], a_hi, bl[1], bl[3]);
                mma16816(c[2*ng+1], a_lo, bh[1], bh[3]);
            }
        }
        __syncthreads();
    }

    const int gid = lane >> 2, qc = (lane & 3) * 2;
    #pragma unroll
    for (int rr = 0; rr < 2; rr++) {
        int m = m0 + wm * 16 + gid + rr * 8;
        float* op = outp + (size_t)m * Cn + n0;
        #pragma unroll
        for (int j = 0; j < 8; j++) {
            float2 bv = *reinterpret_cast<const float2*>(bp + n0 + j * 8 + qc);
            *reinterpret_cast<float2*>(op + j * 8 + qc) =
                make_float2(c[j][rr*2] + bv.x, c[j][rr*2 + 1] + bv.y);
        }
    }
}

// ---------------------------------------------------------------------------
// Kernel 2: flash attention, cp.async 2-stage pipelined. 128 threads.
// S,R: single fp16 MMA. PV: split fp16 (3 MMA). R scratch in fp16.
// smem = 2x36864 (K,VH,VL,W stages) + Q 9216 + 2x8448 (R) = 99840 -> 2 CTAs/SM.
// ---------------------------------------------------------------------------
#define SBUF(s) ((s) * 36864)
#define SB_K  0
#define SB_VH 9216
#define SB_VL 18432
#define SB_W  27648
#define A_Q   73728
#define A_R0  82944
#define A_R1  91392
#define ATT_SMEM 99840
#define LDRH 66

__global__ __launch_bounds__(128) void attn_mm()
{
    extern __shared__ char smc[];
    const uint32_t smb = smem_u32(smc);
    __half* Rh = reinterpret_cast<__half*>(smc);

    const int tid = threadIdx.x;
    const int wm  = tid >> 5;
    const int lane = tid & 31;
    const int lr = lane & 15;
    const int lc = (lane >> 4) << 3;
    const int gid = lane >> 2, qc = (lane & 3) * 2;

    const int bh = blockIdx.x;
    const int h  = bh & (Hn - 1);
    const int b  = bh >> 3;
    const int t0 = (int)(gridDim.y - 1 - blockIdx.y) * 64;
    const int ntiles = t0 / 64 + 1;

    const __half* qg  = g_q  + (size_t)bh * Tn * Dn;
    const __half* kg  = g_k  + (size_t)bh * Tn * Dn;
    const __half* vgh = g_vh + (size_t)bh * Tn * Dn;
    const __half* vgl = g_vl + (size_t)bh * Tn * Dn;
    const __half* rg  = g_relh + (size_t)h * Tn * Dn;

    // ---- prologue: Q, preload-window (stage1 W slot), tile0 K/V(+W) (stage0)
    #pragma unroll
    for (int i = 0; i < 4; i++) {
        int u = tid + i * 128;
        int row = u >> 3, g = u & 7;
        uint32_t dst = (uint32_t)(row * LDT + g * 16);
        cpa16(smb + A_Q + dst, qg + (size_t)(t0 + row) * Dn + g * 8);
        cpa16(smb + SBUF(1) + SB_W + dst,
              rg + (size_t)(Tn - 64 - t0 + row) * Dn + g * 8);
        size_t s = (size_t)row * Dn + g * 8;
        cpa16(smb + SBUF(0) + SB_K  + dst, kg  + s);
        cpa16(smb + SBUF(0) + SB_VH + dst, vgh + s);
        cpa16(smb + SBUF(0) + SB_VL + dst, vgl + s);
        if (ntiles > 1)
            cpa16(smb + SBUF(0) + SB_W + dst,
                  rg + (size_t)(Tn - t0 + row) * Dn + g * 8);
    }
    cpa_wait_all();
    __syncthreads();

    uint32_t q4[4][4];
    #pragma unroll
    for (int ks = 0; ks < 4; ks++) {
        uint32_t aoff = (uint32_t)((wm * 16 + lr) * LDT + (ks * 16 + lc) * 2);
        ldmx4(q4[ks], smb + A_Q + aoff);
    }

    // ---- preload Rprev = Q * RelWin0^T (reads stage1 W slot; fp16 store) ----
    int rprev = A_R0, rnew = A_R1;
    {
        const uint32_t wb = smb + SBUF(1) + SB_W;
        float c[8][4] = {};
        #pragma unroll
        for (int ks = 0; ks < 4; ks++) {
            #pragma unroll
            for (int ng = 0; ng < 4; ng++) {
                uint32_t bh4[4];
                uint32_t boff = (uint32_t)((ng * 16 + lr) * LDT + (ks * 16 + lc) * 2);
                ldmx4(bh4, wb + boff);
                mma16816(c[2*ng],   q4[ks], bh4[0], bh4[2]);
                mma16816(c[2*ng+1], q4[ks], bh4[1], bh4[3]);
            }
        }
        __half* Rp = Rh + rprev / 2;
        #pragma unroll
        for (int j = 0; j < 8; j++) {
            *reinterpret_cast<uint32_t*>(Rp + (wm*16 + gid)     * LDRH + j*8 + qc) =
                pack2h(c[j][0], c[j][1]);
            *reinterpret_cast<uint32_t*>(Rp + (wm*16 + gid + 8) * LDRH + j*8 + qc) =
                pack2h(c[j][2], c[j][3]);
        }
        __syncwarp();
    }
    __syncthreads();   // preload window consumed before stage1 prefetch overwrites

    float o[8][4] = {};
    float mrow[2] = {-1e30f, -1e30f};
    float lrow[2] = {};

    for (int i = 0; i < ntiles; i++) {
        const int s0 = i * 64;
        const bool diag = (i == ntiles - 1);

        // prefetch tile i+1 into stage (i+1)&1
        if (!diag) {
            const int s1 = s0 + 64;
            const uint32_t nb = smb + SBUF((i + 1) & 1);
            #pragma unroll
            for (int u4 = 0; u4 < 4; u4++) {
                int u = tid + u4 * 128;
                int row = u >> 3, g = u & 7;
                uint32_t dst = (uint32_t)(row * LDT + g * 16);
                size_t s = (size_t)(s1 + row) * Dn + g * 8;
                cpa16(nb + SB_K  + dst, kg  + s);
                cpa16(nb + SB_VH + dst, vgh + s);
                cpa16(nb + SB_VL + dst, vgl + s);
                if (i + 1 < ntiles - 1)
                    cpa16(nb + SB_W + dst,
                          rg + (size_t)(Tn - t0 + s1 + row) * Dn + g * 8);
            }
        }
        cpa_commit();
        cpa_wait1();        // tile i's stage is complete
        __syncthreads();

        const uint32_t kb = smb + SBUF(i & 1);
        float c[8][4];

        // ---- R GEMM (off-diag, single fp16) ----
        if (!diag) {
            #pragma unroll
            for (int j = 0; j < 8; j++)
                #pragma unroll
                for (int z = 0; z < 4; z++) c[j][z] = 0.f;
            #pragma unroll
            for (int ks = 0; ks < 4; ks++) {
                #pragma unroll
                for (int ng = 0; ng < 4; ng++) {
                    uint32_t bh4[4];
                    uint32_t boff = (uint32_t)((ng * 16 + lr) * LDT + (ks * 16 + lc) * 2);
                    ldmx4(bh4, kb + SB_W + boff);
                    mma16816(c[2*ng],   q4[ks], bh4[0], bh4[2]);
                    mma16816(c[2*ng+1], q4[ks], bh4[1], bh4[3]);
                }
            }
            __half* Rp = Rh + rnew / 2;
            #pragma unroll
            for (int j = 0; j < 8; j++) {
                *reinterpret_cast<uint32_t*>(Rp + (wm*16 + gid)     * LDRH + j*8 + qc) =
                    pack2h(c[j][0], c[j][1]);
                *reinterpret_cast<uint32_t*>(Rp + (wm*16 + gid + 8) * LDRH + j*8 + qc) =
                    pack2h(c[j][2], c[j][3]);
            }
            __syncwarp();
        }

        // ---- S GEMM (single fp16) ----
        #pragma unroll
        for (int j = 0; j < 8; j++)
            #pragma unroll
            for (int z = 0; z < 4; z++) c[j][z] = 0.f;
        #pragma unroll
        for (int ks = 0; ks < 4; ks++) {
            #pragma unroll
            for (int ng = 0; ng < 4; ng++) {
                uint32_t bh4[4];
                uint32_t boff = (uint32_t)((ng * 16 + lr) * LDT + (ks * 16 + lc) * 2);
                ldmx4(bh4, kb + SB_K + boff);
                mma16816(c[2*ng],   q4[ks], bh4[0], bh4[2]);
                mma16816(c[2*ng+1], q4[ks], bh4[1], bh4[3]);
            }
        }

        // ---- gather BD (fp16 R) ----
        {
            const __half* Rp = Rh + rprev / 2;
            const __half* Rn = Rh + rnew / 2;
            #pragma unroll
            for (int rr = 0; rr < 2; rr++) {
                int tl = wm*16 + gid + rr*8;
                #pragma unroll
                for (int j = 0; j < 8; j++) {
                    #pragma unroll
                    for (int z = 0; z < 2; z++) {
                        int sl = j*8 + qc + z;
                        int jj = sl - tl + 63;
                        if (jj < 64) c[j][rr*2 + z] += __half2float(Rp[tl * LDRH + jj]);
                        else if (!diag) c[j][rr*2 + z] += __half2float(Rn[tl * LDRH + jj - 64]);
                    }
                }
            }
        }

        // ---- wrap corner (tile 0,0 only) ----
        if (t0 == 0 && s0 == 0 && wm == 0 && gid < 5) {
            int t = gid;
            #pragma unroll
            for (int z = 0; z < 2; z++) {
                int s = qc + z;
                if (s > t + 1 && s < 6) {
                    float bd = 0.f;
                    for (int d = 0; d < 64; d++)
                        bd += __half2float(qg[(t + 1) * Dn + d])
                            * __half2float(rg[(size_t)(s - t - 2) * Dn + d]);
                    c[0][z] += bd;
                }
            }
        }

        // ---- mask + scale + online softmax ----
        #pragma unroll
        for (int rr = 0; rr < 2; rr++) {
            int t = t0 + wm*16 + gid + rr*8;
            float rm = -1e30f;
            #pragma unroll
            for (int j = 0; j < 8; j++) {
                #pragma unroll
                for (int z = 0; z < 2; z++) {
                    int s = s0 + j*8 + qc + z;
                    float v = (s <= t || s < 6) ? c[j][rr*2+z] * kScale : -1e30f;
                    c[j][rr*2+z] = v;
                    rm = fmaxf(rm, v);
                }
            }
            rm = fmaxf(rm, __shfl_xor_sync(0xffffffffu, rm, 1));
            rm = fmaxf(rm, __shfl_xor_sync(0xffffffffu, rm, 2));
            float mnew = fmaxf(mrow[rr], rm);
            float alpha = __expf(mrow[rr] - mnew);
            mrow[rr] = mnew;
            float rs = 0.f;
            #pragma unroll
            for (int j = 0; j < 8; j++) {
                #pragma unroll
                for (int z = 0; z < 2; z++) {
                    float p = __expf(c[j][rr*2+z] - mnew);
                    c[j][rr*2+z] = p;
                    rs += p;
                }
            }
            rs += __shfl_xor_sync(0xffffffffu, rs, 1);
            rs += __shfl_xor_sync(0xffffffffu, rs, 2);
            lrow[rr] = lrow[rr] * alpha + rs;
            #pragma unroll
            for (int j = 0; j < 8; j++) {
                o[j][rr*2]   *= alpha;
                o[j][rr*2+1] *= alpha;
            }
        }

        // ---- P split (fp16 hi/lo) ----
        uint32_t p_hi[4][4], p_lo[4][4];
        #pragma unroll
        for (int kc = 0; kc < 4; kc++) {
            split2h(c[2*kc][0],   c[2*kc][1],   p_hi[kc][0], p_lo[kc][0]);
            split2h(c[2*kc][2],   c[2*kc][3],   p_hi[kc][1], p_lo[kc][1]);
            split2h(c[2*kc+1][0], c[2*kc+1][1], p_hi[kc][2], p_lo[kc][2]);
            split2h(c[2*kc+1][2], c[2*kc+1][3], p_hi[kc][3], p_lo[kc][3]);
        }

        // ---- O += P * V (3-MMA split) ----
        #pragma unroll
        for (int kc = 0; kc < 4; kc++) {
            uint32_t vbase = (uint32_t)(kc*16 + (lane & 7) + ((lane & 16) >> 1)) * LDT;
            #pragma unroll
            for (int ng = 0; ng < 4; ng++) {
                uint32_t bh4[4], bl4[4];
                uint32_t voff = vbase + (uint32_t)(ng*16 + (lane & 8)) * 2;
                ldmx4t(bh4, kb + SB_VH + voff);
                ldmx4t(bl4, kb + SB_VL + voff);
                mma16816(o[2*ng],   p_hi[kc], bh4[0], bh4[2]);
                mma16816(o[2*ng],   p_hi[kc], bl4[0], bl4[2]);
                mma16816(o[2*ng],   p_lo[kc], bh4[0], bh4[2]);
                mma16816(o[2*ng+1], p_hi[kc], bh4[1], bh4[3]);
                mma16816(o[2*ng+1], p_hi[kc], bl4[1], bl4[3]);
                mma16816(o[2*ng+1], p_lo[kc], bh4[1], bh4[3]);
            }
        }

        if (!diag) { int tp = rprev; rprev = rnew; rnew = tp; }
        __syncthreads();     // WAR: stage consumed before next iter's prefetch
    }

    // ---- epilogue: att = O / l -> split fp16 ----
    #pragma unroll
    for (int rr = 0; rr < 2; rr++) {
        int t = t0 + wm*16 + gid + rr*8;
        float inv = 1.0f / lrow[rr];
        size_t base = ((size_t)b * Tn + t) * Cn + h * Dn;
        #pragma unroll
        for (int j = 0; j < 8; j++) {
            uint32_t hp, lp;
            split2h(o[j][rr*2] * inv, o[j][rr*2+1] * inv, hp, lp);
            size_t e = base + j*8 + qc;
            *reinterpret_cast<uint32_t*>(g_atth + e) = hp;
            *reinterpret_cast<uint32_t*>(g_attl + e) = lp;
        }
    }
}

// ---------------------------------------------------------------------------
extern "C" void kernel_launch(void* const* d_in, const int* in_sizes, int n_in,
                              void* d_out, int out_size)
{
    const float* x   = (const float*)d_in[0];
    const float* Wq  = (const float*)d_in[1];
    const float* Wk  = (const float*)d_in[2];
    const float* Wv  = (const float*)d_in[3];
    const float* rel = (const float*)d_in[4];
    const float* Wp  = (const float*)d_in[5];
    const float* bp  = (const float*)d_in[6];
    float* out = (float*)d_out;

    static __half *h_xh, *h_xl, *h_wth, *h_wvl, *h_relh, *h_wpth, *h_wptl;
    static bool init = false;
    if (!init) {
        cudaGetSymbolAddress((void**)&h_xh, g_xh);
        cudaGetSymbolAddress((void**)&h_xl, g_xl);
        cudaGetSymbolAddress((void**)&h_wth, g_wth);
        cudaGetSymbolAddress((void**)&h_wvl, g_wvl);
        cudaGetSymbolAddress((void**)&h_relh, g_relh);
        cudaGetSymbolAddress((void**)&h_wpth, g_wpth);
        cudaGetSymbolAddress((void**)&h_wptl, g_wptl);
        cudaFuncSetAttribute(qkv_mm,  cudaFuncAttributeMaxDynamicSharedMemorySize, GEMM_SMEM);
        cudaFuncSetAttribute(proj_mm, cudaFuncAttributeMaxDynamicSharedMemorySize, GEMM_SMEM);
        cudaFuncSetAttribute(attn_mm, cudaFuncAttributeMaxDynamicSharedMemorySize, ATT_SMEM);
        init = true;
    }

    split_f32h<<<(NX/4 + 255)/256, 256>>>(x, h_xh, h_xl, NX/4);
    split_f32h<<<(NR/4 + 255)/256, 256>>>(rel, h_relh, nullptr, NR/4);
    split_trh<<<dim3((Cn*Dn + 255)/256, Hn), 256>>>(Wq, h_wth,        nullptr, Cn, Dn);
    split_trh<<<dim3((Cn*Dn + 255)/256, Hn), 256>>>(Wk, h_wth + NW,   nullptr, Cn, Dn);
    split_trh<<<dim3((Cn*Dn + 255)/256, Hn), 256>>>(Wv, h_wth + 2*NW, h_wvl,   Cn, Dn);
    split_trh<<<dim3((Cn*Cn + 255)/256, 1), 256>>>(Wp, h_wpth, h_wptl, Cn, Cn);

    qkv_mm<<<dim3(64, 24), 256, GEMM_SMEM>>>();
    attn_mm<<<dim3(Bn * Hn, Tn / 64), 128, ATT_SMEM>>>();
    proj_mm<<<dim3(64, 8), 256, GEMM_SMEM>>>(bp, out);
}

// round 9
// speedup vs baseline: 1.6319x; 1.2090x over previous
#include <cuda_runtime.h>
#include <cuda_fp16.h>
#include <cstdint>

// Problem constants
#define Bn 4
#define Tn 2048
#define Cn 512
#define Hn 8
#define Dn 64
__device__ __constant__ float kScale = 0.04419417382415922f; // 512^-0.5

// ---------------------------------------------------------------------------
// Global scratch (fp16)
// ---------------------------------------------------------------------------
#define NX  (Bn*Tn*Cn)
#define NW  (Hn*Cn*Dn)
#define NR  (Hn*Tn*Dn)
#define NP  (Cn*Cn)
#define NQ  (Bn*Hn*Tn*Dn)

__device__ __align__(16) __half g_xh[NX];
__device__ __align__(16) __half g_wth[3*NW];         // [mat][h][d][k]
__device__ __align__(16) __half g_relh[NR];
__device__ __align__(16) __half g_wpth[NP], g_wptl[NP];
__device__ __align__(16) __half g_q[NQ], g_k[NQ], g_v[NQ];
__device__ __align__(16) __half g_att[NX];

// ---------------------------------------------------------------------------
// helpers
// ---------------------------------------------------------------------------
__device__ __forceinline__ uint32_t smem_u32(const void* p) {
    uint32_t a;
    asm("{ .reg .u64 t; cvta.to.shared.u64 t, %1; cvt.u32.u64 %0, t; }"
        : "=r"(a) : "l"(p));
    return a;
}

__device__ __forceinline__ void ldmx4(uint32_t* r, uint32_t addr) {
    asm volatile("ldmatrix.sync.aligned.m8n8.x4.shared.b16 {%0,%1,%2,%3}, [%4];"
                 : "=r"(r[0]), "=r"(r[1]), "=r"(r[2]), "=r"(r[3]) : "r"(addr));
}
__device__ __forceinline__ void ldmx4t(uint32_t* r, uint32_t addr) {
    asm volatile("ldmatrix.sync.aligned.m8n8.x4.trans.shared.b16 {%0,%1,%2,%3}, [%4];"
                 : "=r"(r[0]), "=r"(r[1]), "=r"(r[2]), "=r"(r[3]) : "r"(addr));
}

__device__ __forceinline__ void mma16816(float* c, const uint32_t* a,
                                         uint32_t b0, uint32_t b1) {
    asm volatile(
        "mma.sync.aligned.m16n8k16.row.col.f32.f16.f16.f32 "
        "{%0,%1,%2,%3}, {%4,%5,%6,%7}, {%8,%9}, {%0,%1,%2,%3};"
        : "+f"(c[0]), "+f"(c[1]), "+f"(c[2]), "+f"(c[3])
        : "r"(a[0]), "r"(a[1]), "r"(a[2]), "r"(a[3]), "r"(b0), "r"(b1));
}

__device__ __forceinline__ uint32_t pack2h(float x0, float x1) {
    __half h0 = __float2half_rn(x0), h1 = __float2half_rn(x1);
    return (uint32_t)__half_as_ushort(h0) | ((uint32_t)__half_as_ushort(h1) << 16);
}

__device__ __forceinline__ void split2h(float x0, float x1, uint32_t& hi2, uint32_t& lo2) {
    __half h0 = __float2half_rn(x0), h1 = __float2half_rn(x1);
    float l0 = x0 - __half2float(h0), l1 = x1 - __half2float(h1);
    hi2 = (uint32_t)__half_as_ushort(h0) | ((uint32_t)__half_as_ushort(h1) << 16);
    lo2 = (uint32_t)__half_as_ushort(__float2half_rn(l0))
        | ((uint32_t)__half_as_ushort(__float2half_rn(l1)) << 16);
}

__device__ __forceinline__ void cpa16(uint32_t dst, const void* src) {
    asm volatile("cp.async.cg.shared.global [%0], [%1], 16;" :: "r"(dst), "l"(src));
}
__device__ __forceinline__ void cpa_wait_all() {
    asm volatile("cp.async.wait_all;" ::: "memory");
}
__device__ __forceinline__ void cpa_commit() {
    asm volatile("cp.async.commit_group;" ::: "memory");
}
__device__ __forceinline__ void cpa_wait1() {
    asm volatile("cp.async.wait_group 1;" ::: "memory");
}

// fp16 smem rows: 64 elems = 128B, padded to 144B (9 x 16B phases -> conflict-free)
#define LDT 144

// ---------------------------------------------------------------------------
// Pre-convert kernels
// ---------------------------------------------------------------------------
__global__ void conv_f16(const float* __restrict__ src,
                         __half* __restrict__ dst, int n4)
{
    int i = blockIdx.x * blockDim.x + threadIdx.x;
    if (i >= n4) return;
    float4 v = reinterpret_cast<const float4*>(src)[i];
    reinterpret_cast<uint2*>(dst)[i] = make_uint2(pack2h(v.x, v.y), pack2h(v.z, v.w));
}

// Transposed convert, 3 matrices in one launch (z = matrix)
__global__ void conv_tr3(const float* __restrict__ s0,
                         const float* __restrict__ s1,
                         const float* __restrict__ s2)
{
    int z = blockIdx.z;
    int b = blockIdx.y;
    int i = blockIdx.x * blockDim.x + threadIdx.x;
    if (i >= Cn * Dn) return;
    const float* src = (z == 0 ? s0 : (z == 1 ? s1 : s2));
    int r = i / Dn, c = i % Dn;
    float w = src[(size_t)b * Cn * Dn + i];
    g_wth[(size_t)(z * Hn + b) * Cn * Dn + (size_t)c * Cn + r] = __float2half_rn(w);
}

// Transposed split (hi/lo) for Wp
__global__ void split_trp(const float* __restrict__ src)
{
    int i = blockIdx.x * blockDim.x + threadIdx.x;
    if (i >= Cn * Cn) return;
    int r = i / Cn, c = i % Cn;
    float w = src[i];
    __half hb = __float2half_rn(w);
    size_t o = (size_t)c * Cn + r;
    g_wpth[o] = hb;
    g_wptl[o] = __float2half_rn(w - __half2float(hb));
}

// ---------------------------------------------------------------------------
// Kernel 1: QKV projection, all single fp16.
// grid = (64 m-tiles of 128, 16): y<8 -> fused q+k head y; y>=8 -> v head y-8.
// 256 threads, 36864 B smem.
// ---------------------------------------------------------------------------
#define Q_A  0
#define Q_B0 18432
#define Q_B1 27648
#define QKV_SMEM 36864

__global__ __launch_bounds__(256) void qkv_mm()
{
    extern __shared__ char smc[];
    const uint32_t smb = smem_u32(smc);
    const int tid = threadIdx.x;
    const int wm  = tid >> 5;
    const int lane = tid & 31;
    const int lr = lane & 15;
    const int lc = (lane >> 4) << 3;

    const int m0   = blockIdx.x * 128;
    const bool isqk = blockIdx.y < 8;
    const int h    = blockIdx.y & 7;
    const __half* W0 = g_wth + (size_t)(isqk ? h : 16 + h) * Cn * Dn;
    const __half* W1 = g_wth + (size_t)(8 + h) * Cn * Dn;   // k weights (qk path)

    float c0[8][4] = {};
    float c1[8][4] = {};    // only used in qk path

    for (int kb = 0; kb < 8; kb++) {
        const int c0k = kb * 64;
        #pragma unroll
        for (int i = 0; i < 4; i++) {
            int u = tid + i * 256;
            int row = u >> 3, g = u & 7;
            cpa16(smb + Q_A + (uint32_t)(row * LDT + g * 16),
                  g_xh + (size_t)(m0 + row) * Cn + c0k + g * 8);
        }
        #pragma unroll
        for (int i = 0; i < 2; i++) {
            int u = tid + i * 256;
            int d = u >> 3, g = u & 7;
            uint32_t dst = (uint32_t)(d * LDT + g * 16);
            size_t src = (size_t)d * Cn + c0k + g * 8;
            cpa16(smb + Q_B0 + dst, W0 + src);
            if (isqk) cpa16(smb + Q_B1 + dst, W1 + src);
        }
        cpa_wait_all();
        __syncthreads();

        #pragma unroll
        for (int ks = 0; ks < 4; ks++) {
            const int k0 = ks * 16;
            uint32_t a4[4];
            uint32_t aoff = (uint32_t)((wm * 16 + lr) * LDT + (k0 + lc) * 2);
            ldmx4(a4, smb + Q_A + aoff);
            #pragma unroll
            for (int ng = 0; ng < 4; ng++) {
                uint32_t b4[4];
                uint32_t boff = (uint32_t)((ng * 16 + lr) * LDT + (k0 + lc) * 2);
                ldmx4(b4, smb + Q_B0 + boff);
                mma16816(c0[2*ng],   a4, b4[0], b4[2]);
                mma16816(c0[2*ng+1], a4, b4[1], b4[3]);
                if (isqk) {
                    uint32_t bk[4];
                    ldmx4(bk, smb + Q_B1 + boff);
                    mma16816(c1[2*ng],   a4, bk[0], bk[2]);
                    mma16816(c1[2*ng+1], a4, bk[1], bk[3]);
                }
            }
        }
        __syncthreads();
    }

    const int gid = lane >> 2, qc = (lane & 3) * 2;
    #pragma unroll
    for (int rr = 0; rr < 2; rr++) {
        int m = m0 + wm * 16 + gid + rr * 8;
        int b = m >> 11, t = m & 2047;
        size_t base = (((size_t)(b * Hn + h)) * Tn + t) * Dn;
        if (isqk) {
            #pragma unroll
            for (int j = 0; j < 8; j++) {
                *reinterpret_cast<uint32_t*>(g_q + base + j * 8 + qc) =
                    pack2h(c0[j][rr*2], c0[j][rr*2 + 1]);
                *reinterpret_cast<uint32_t*>(g_k + base + j * 8 + qc) =
                    pack2h(c1[j][rr*2], c1[j][rr*2 + 1]);
            }
        } else {
            #pragma unroll
            for (int j = 0; j < 8; j++)
                *reinterpret_cast<uint32_t*>(g_v + base + j * 8 + qc) =
                    pack2h(c0[j][rr*2], c0[j][rr*2 + 1]);
        }
    }
}

// ---------------------------------------------------------------------------
// Kernel 3: output projection + bias. att single fp16; Wp split (2-MMA).
// grid = (64, 8), 256 threads, 36864 B smem.
// ---------------------------------------------------------------------------
__global__ __launch_bounds__(256) void proj_mm(
    const float* __restrict__ bp, float* __restrict__ outp)
{
    extern __shared__ char smc[];
    const uint32_t smb = smem_u32(smc);
    const int tid = threadIdx.x;
    const int wm  = tid >> 5;
    const int lane = tid & 31;
    const int lr = lane & 15;
    const int lc = (lane >> 4) << 3;

    const int m0 = blockIdx.x * 128;
    const int n0 = blockIdx.y * 64;

    float c[8][4] = {};

    for (int kb = 0; kb < 8; kb++) {
        const int c0 = kb * 64;
        #pragma unroll
        for (int i = 0; i < 4; i++) {
            int u = tid + i * 256;
            int row = u >> 3, g = u & 7;
            cpa16(smb + Q_A + (uint32_t)(row * LDT + g * 16),
                  g_att + (size_t)(m0 + row) * Cn + c0 + g * 8);
        }
        #pragma unroll
        for (int i = 0; i < 2; i++) {
            int u = tid + i * 256;
            int d = u >> 3, g = u & 7;
            uint32_t dst = (uint32_t)(d * LDT + g * 16);
            size_t src = (size_t)(n0 + d) * Cn + c0 + g * 8;
            cpa16(smb + Q_B0 + dst, g_wpth + src);
            cpa16(smb + Q_B1 + dst, g_wptl + src);
        }
        cpa_wait_all();
        __syncthreads();

        #pragma unroll
        for (int ks = 0; ks < 4; ks++) {
            const int k0 = ks * 16;
            uint32_t a4[4];
            uint32_t aoff = (uint32_t)((wm * 16 + lr) * LDT + (k0 + lc) * 2);
            ldmx4(a4, smb + Q_A + aoff);
            #pragma unroll
            for (int ng = 0; ng < 4; ng++) {
                uint32_t bh[4], bl[4];
                uint32_t boff = (uint32_t)((ng * 16 + lr) * LDT + (k0 + lc) * 2);
                ldmx4(bh, smb + Q_B0 + boff);
                ldmx4(bl, smb + Q_B1 + boff);
                mma16816(c[2*ng],   a4, bh[0], bh[2]);
                mma16816(c[2*ng],   a4, bl[0], bl[2]);
                mma16816(c[2*ng+1], a4, bh[1], bh[3]);
                mma16816(c[2*ng+1], a4, bl[1], bl[3]);
            }
        }
        __syncthreads();
    }

    const int gid = lane >> 2, qc = (lane & 3) * 2;
    #pragma unroll
    for (int rr = 0; rr < 2; rr++) {
        int m = m0 + wm * 16 + gid + rr * 8;
        float* op = outp + (size_t)m * Cn + n0;
        #pragma unroll
        for (int j = 0; j < 8; j++) {
            float2 bv = *reinterpret_cast<const float2*>(bp + n0 + j * 8 + qc);
            *reinterpret_cast<float2*>(op + j * 8 + qc) =
                make_float2(c[j][rr*2] + bv.x, c[j][rr*2 + 1] + bv.y);
        }
    }
}

// ---------------------------------------------------------------------------
// Kernel 2: flash attention, cp.async 2-stage pipelined. 128 threads.
// S,R: single fp16 MMA. PV: 2 MMA (P hi/lo x single V). R scratch fp16.
// smem = 2x27648 + Q 9216 + 2x8448 = 81408 -> 2 CTAs/SM.
// ---------------------------------------------------------------------------
#define SBUF(s) ((s) * 27648)
#define SB_K  0
#define SB_V  9216
#define SB_W  18432
#define A_Q   55296
#define A_R0  64512
#define A_R1  72960
#define ATT_SMEM 81408
#define LDRH 66

__global__ __launch_bounds__(128) void attn_mm()
{
    extern __shared__ char smc[];
    const uint32_t smb = smem_u32(smc);
    __half* Rh = reinterpret_cast<__half*>(smc);

    const int tid = threadIdx.x;
    const int wm  = tid >> 5;
    const int lane = tid & 31;
    const int lr = lane & 15;
    const int lc = (lane >> 4) << 3;
    const int gid = lane >> 2, qc = (lane & 3) * 2;

    const int bh = blockIdx.x;
    const int h  = bh & (Hn - 1);
    const int b  = bh >> 3;
    const int t0 = (int)(gridDim.y - 1 - blockIdx.y) * 64;
    const int ntiles = t0 / 64 + 1;

    const __half* qg = g_q + (size_t)bh * Tn * Dn;
    const __half* kg = g_k + (size_t)bh * Tn * Dn;
    const __half* vg = g_v + (size_t)bh * Tn * Dn;
    const __half* rg = g_relh + (size_t)h * Tn * Dn;

    // ---- prologue: Q, preload-window (stage1 W slot), tile0 K/V(+W) (stage0)
    #pragma unroll
    for (int i = 0; i < 4; i++) {
        int u = tid + i * 128;
        int row = u >> 3, g = u & 7;
        uint32_t dst = (uint32_t)(row * LDT + g * 16);
        cpa16(smb + A_Q + dst, qg + (size_t)(t0 + row) * Dn + g * 8);
        cpa16(smb + SBUF(1) + SB_W + dst,
              rg + (size_t)(Tn - 64 - t0 + row) * Dn + g * 8);
        size_t s = (size_t)row * Dn + g * 8;
        cpa16(smb + SBUF(0) + SB_K + dst, kg + s);
        cpa16(smb + SBUF(0) + SB_V + dst, vg + s);
        if (ntiles > 1)
            cpa16(smb + SBUF(0) + SB_W + dst,
                  rg + (size_t)(Tn - t0 + row) * Dn + g * 8);
    }
    cpa_wait_all();
    __syncthreads();

    uint32_t q4[4][4];
    #pragma unroll
    for (int ks = 0; ks < 4; ks++) {
        uint32_t aoff = (uint32_t)((wm * 16 + lr) * LDT + (ks * 16 + lc) * 2);
        ldmx4(q4[ks], smb + A_Q + aoff);
    }

    // ---- preload Rprev = Q * RelWin0^T ----
    int rprev = A_R0, rnew = A_R1;
    {
        const uint32_t wb = smb + SBUF(1) + SB_W;
        float c[8][4] = {};
        #pragma unroll
        for (int ks = 0; ks < 4; ks++) {
            #pragma unroll
            for (int ng = 0; ng < 4; ng++) {
                uint32_t bh4[4];
                uint32_t boff = (uint32_t)((ng * 16 + lr) * LDT + (ks * 16 + lc) * 2);
                ldmx4(bh4, wb + boff);
                mma16816(c[2*ng],   q4[ks], bh4[0], bh4[2]);
                mma16816(c[2*ng+1], q4[ks], bh4[1], bh4[3]);
            }
        }
        __half* Rp = Rh + rprev / 2;
        #pragma unroll
        for (int j = 0; j < 8; j++) {
            *reinterpret_cast<uint32_t*>(Rp + (wm*16 + gid)     * LDRH + j*8 + qc) =
                pack2h(c[j][0], c[j][1]);
            *reinterpret_cast<uint32_t*>(Rp + (wm*16 + gid + 8) * LDRH + j*8 + qc) =
                pack2h(c[j][2], c[j][3]);
        }
        __syncwarp();
    }
    __syncthreads();   // preload window consumed before stage1 prefetch overwrites

    float o[8][4] = {};
    float mrow[2] = {-1e30f, -1e30f};
    float lrow[2] = {};

    for (int i = 0; i < ntiles; i++) {
        const int s0 = i * 64;
        const bool diag = (i == ntiles - 1);

        // prefetch tile i+1 into stage (i+1)&1
        if (!diag) {
            const int s1 = s0 + 64;
            const uint32_t nb = smb + SBUF((i + 1) & 1);
            #pragma unroll
            for (int u4 = 0; u4 < 4; u4++) {
                int u = tid + u4 * 128;
                int row = u >> 3, g = u & 7;
                uint32_t dst = (uint32_t)(row * LDT + g * 16);
                size_t s = (size_t)(s1 + row) * Dn + g * 8;
                cpa16(nb + SB_K + dst, kg + s);
                cpa16(nb + SB_V + dst, vg + s);
                if (i + 1 < ntiles - 1)
                    cpa16(nb + SB_W + dst,
                          rg + (size_t)(Tn - t0 + s1 + row) * Dn + g * 8);
            }
        }
        cpa_commit();
        cpa_wait1();        // tile i's stage is complete
        __syncthreads();

        const uint32_t kb = smb + SBUF(i & 1);
        float c[8][4];

        // ---- R GEMM (off-diag, single fp16) ----
        if (!diag) {
            #pragma unroll
            for (int j = 0; j < 8; j++)
                #pragma unroll
                for (int z = 0; z < 4; z++) c[j][z] = 0.f;
            #pragma unroll
            for (int ks = 0; ks < 4; ks++) {
                #pragma unroll
                for (int ng = 0; ng < 4; ng++) {
                    uint32_t bh4[4];
                    uint32_t boff = (uint32_t)((ng * 16 + lr) * LDT + (ks * 16 + lc) * 2);
                    ldmx4(bh4, kb + SB_W + boff);
                    mma16816(c[2*ng],   q4[ks], bh4[0], bh4[2]);
                    mma16816(c[2*ng+1], q4[ks], bh4[1], bh4[3]);
                }
            }
            __half* Rp = Rh + rnew / 2;
            #pragma unroll
            for (int j = 0; j < 8; j++) {
                *reinterpret_cast<uint32_t*>(Rp + (wm*16 + gid)     * LDRH + j*8 + qc) =
                    pack2h(c[j][0], c[j][1]);
                *reinterpret_cast<uint32_t*>(Rp + (wm*16 + gid + 8) * LDRH + j*8 + qc) =
                    pack2h(c[j][2], c[j][3]);
            }
            __syncwarp();
        }

        // ---- S GEMM (single fp16) ----
        #pragma unroll
        for (int j = 0; j < 8; j++)
            #pragma unroll
            for (int z = 0; z < 4; z++) c[j][z] = 0.f;
        #pragma unroll
        for (int ks = 0; ks < 4; ks++) {
            #pragma unroll
            for (int ng = 0; ng < 4; ng++) {
                uint32_t bh4[4];
                uint32_t boff = (uint32_t)((ng * 16 + lr) * LDT + (ks * 16 + lc) * 2);
                ldmx4(bh4, kb + SB_K + boff);
                mma16816(c[2*ng],   q4[ks], bh4[0], bh4[2]);
                mma16816(c[2*ng+1], q4[ks], bh4[1], bh4[3]);
            }
        }

        // ---- gather BD (fp16 R) ----
        {
            const __half* Rp = Rh + rprev / 2;
            const __half* Rn = Rh + rnew / 2;
            #pragma unroll
            for (int rr = 0; rr < 2; rr++) {
                int tl = wm*16 + gid + rr*8;
                #pragma unroll
                for (int j = 0; j < 8; j++) {
                    #pragma unroll
                    for (int z = 0; z < 2; z++) {
                        int sl = j*8 + qc + z;
                        int jj = sl - tl + 63;
                        if (jj < 64) c[j][rr*2 + z] += __half2float(Rp[tl * LDRH + jj]);
                        else if (!diag) c[j][rr*2 + z] += __half2float(Rn[tl * LDRH + jj - 64]);
                    }
                }
            }
        }

        // ---- wrap corner (tile 0,0 only) ----
        if (t0 == 0 && s0 == 0 && wm == 0 && gid < 5) {
            int t = gid;
            #pragma unroll
            for (int z = 0; z < 2; z++) {
                int s = qc + z;
                if (s > t + 1 && s < 6) {
                    float bd = 0.f;
                    for (int d = 0; d < 64; d++)
                        bd += __half2float(qg[(t + 1) * Dn + d])
                            * __half2float(rg[(size_t)(s - t - 2) * Dn + d]);
                    c[0][z] += bd;
                }
            }
        }

        // ---- mask + scale + online softmax ----
        #pragma unroll
        for (int rr = 0; rr < 2; rr++) {
            int t = t0 + wm*16 + gid + rr*8;
            float rm = -1e30f;
            #pragma unroll
            for (int j = 0; j < 8; j++) {
                #pragma unroll
                for (int z = 0; z < 2; z++) {
                    int s = s0 + j*8 + qc + z;
                    float v = (s <= t || s < 6) ? c[j][rr*2+z] * kScale : -1e30f;
                    c[j][rr*2+z] = v;
                    rm = fmaxf(rm, v);
                }
            }
            rm = fmaxf(rm, __shfl_xor_sync(0xffffffffu, rm, 1));
            rm = fmaxf(rm, __shfl_xor_sync(0xffffffffu, rm, 2));
            float mnew = fmaxf(mrow[rr], rm);
            float alpha = __expf(mrow[rr] - mnew);
            mrow[rr] = mnew;
            float rs = 0.f;
            #pragma unroll
            for (int j = 0; j < 8; j++) {
                #pragma unroll
                for (int z = 0; z < 2; z++) {
                    float p = __expf(c[j][rr*2+z] - mnew);
                    c[j][rr*2+z] = p;
                    rs += p;
                }
            }
            rs += __shfl_xor_sync(0xffffffffu, rs, 1);
            rs += __shfl_xor_sync(0xffffffffu, rs, 2);
            lrow[rr] = lrow[rr] * alpha + rs;
            #pragma unroll
            for (int j = 0; j < 8; j++) {
                o[j][rr*2]   *= alpha;
                o[j][rr*2+1] *= alpha;
            }
        }

        // ---- P split (fp16 hi/lo) ----
        uint32_t p_hi[4][4], p_lo[4][4];
        #pragma unroll
        for (int kc = 0; kc < 4; kc++) {
            split2h(c[2*kc][0],   c[2*kc][1],   p_hi[kc][0], p_lo[kc][0]);
            split2h(c[2*kc][2],   c[2*kc][3],   p_hi[kc][1], p_lo[kc][1]);
            split2h(c[2*kc+1][0], c[2*kc+1][1], p_hi[kc][2], p_lo[kc][2]);
            split2h(c[2*kc+1][2], c[2*kc+1][3], p_hi[kc][3], p_lo[kc][3]);
        }

        // ---- O += P * V (2-MMA: (P_hi + P_lo) x V) ----
        #pragma unroll
        for (int kc = 0; kc < 4; kc++) {
            uint32_t vbase = (uint32_t)(kc*16 + (lane & 7) + ((lane & 16) >> 1)) * LDT;
            #pragma unroll
            for (int ng = 0; ng < 4; ng++) {
                uint32_t bv4[4];
                uint32_t voff = vbase + (uint32_t)(ng*16 + (lane & 8)) * 2;
                ldmx4t(bv4, kb + SB_V + voff);
                mma16816(o[2*ng],   p_hi[kc], bv4[0], bv4[2]);
                mma16816(o[2*ng],   p_lo[kc], bv4[0], bv4[2]);
                mma16816(o[2*ng+1], p_hi[kc], bv4[1], bv4[3]);
                mma16816(o[2*ng+1], p_lo[kc], bv4[1], bv4[3]);
            }
        }

        if (!diag) { int tp = rprev; rprev = rnew; rnew = tp; }
        __syncthreads();     // WAR: stage consumed before next iter's prefetch
    }

    // ---- epilogue: att = O / l -> single fp16 ----
    #pragma unroll
    for (int rr = 0; rr < 2; rr++) {
        int t = t0 + wm*16 + gid + rr*8;
        float inv = 1.0f / lrow[rr];
        size_t base = ((size_t)b * Tn + t) * Cn + h * Dn;
        #pragma unroll
        for (int j = 0; j < 8; j++)
            *reinterpret_cast<uint32_t*>(g_att + base + j*8 + qc) =
                pack2h(o[j][rr*2] * inv, o[j][rr*2+1] * inv);
    }
}

// ---------------------------------------------------------------------------
extern "C" void kernel_launch(void* const* d_in, const int* in_sizes, int n_in,
                              void* d_out, int out_size)
{
    const float* x   = (const float*)d_in[0];
    const float* Wq  = (const float*)d_in[1];
    const float* Wk  = (const float*)d_in[2];
    const float* Wv  = (const float*)d_in[3];
    const float* rel = (const float*)d_in[4];
    const float* Wp  = (const float*)d_in[5];
    const float* bp  = (const float*)d_in[6];
    float* out = (float*)d_out;

    static __half *h_xh, *h_relh;
    static bool init = false;
    if (!init) {
        cudaGetSymbolAddress((void**)&h_xh, g_xh);
        cudaGetSymbolAddress((void**)&h_relh, g_relh);
        cudaFuncSetAttribute(qkv_mm,  cudaFuncAttributeMaxDynamicSharedMemorySize, QKV_SMEM);
        cudaFuncSetAttribute(proj_mm, cudaFuncAttributeMaxDynamicSharedMemorySize, QKV_SMEM);
        cudaFuncSetAttribute(attn_mm, cudaFuncAttributeMaxDynamicSharedMemorySize, ATT_SMEM);
        init = true;
    }

    conv_f16<<<(NX/4 + 255)/256, 256>>>(x, h_xh, NX/4);
    conv_f16<<<(NR/4 + 255)/256, 256>>>(rel, h_relh, NR/4);
    conv_tr3<<<dim3((Cn*Dn + 255)/256, Hn, 3), 256>>>(Wq, Wk, Wv);
    split_trp<<<(Cn*Cn + 255)/256, 256>>>(Wp);

    qkv_mm<<<dim3(64, 16), 256, QKV_SMEM>>>();
    attn_mm<<<dim3(Bn * Hn, Tn / 64), 128, ATT_SMEM>>>();
    proj_mm<<<dim3(64, 8), 256, QKV_SMEM>>>(bp, out);
}

// round 11
// speedup vs baseline: 1.8204x; 1.1155x over previous
#include <cuda_runtime.h>
#include <cuda_fp16.h>
#include <cstdint>

// Problem constants
#define Bn 4
#define Tn 2048
#define Cn 512
#define Hn 8
#define Dn 64
__device__ __constant__ float kScale = 0.04419417382415922f; // 512^-0.5

// ---------------------------------------------------------------------------
// Global scratch (fp16)
// ---------------------------------------------------------------------------
#define NX  (Bn*Tn*Cn)
#define NW  (Hn*Cn*Dn)
#define NR  (Hn*Tn*Dn)
#define NP  (Cn*Cn)
#define NQ  (Bn*Hn*Tn*Dn)

__device__ __align__(16) __half g_xh[NX];
__device__ __align__(16) __half g_wth[3*NW];         // [mat][h][d][k]
__device__ __align__(16) __half g_relh[NR];
__device__ __align__(16) __half g_wpth[NP], g_wptl[NP];
__device__ __align__(16) __half g_q[NQ], g_k[NQ], g_v[NQ];
__device__ __align__(16) __half g_att[NX];

// ---------------------------------------------------------------------------
// helpers
// ---------------------------------------------------------------------------
__device__ __forceinline__ uint32_t smem_u32(const void* p) {
    uint32_t a;
    asm("{ .reg .u64 t; cvta.to.shared.u64 t, %1; cvt.u32.u64 %0, t; }"
        : "=r"(a) : "l"(p));
    return a;
}

__device__ __forceinline__ void ldmx4(uint32_t* r, uint32_t addr) {
    asm volatile("ldmatrix.sync.aligned.m8n8.x4.shared.b16 {%0,%1,%2,%3}, [%4];"
                 : "=r"(r[0]), "=r"(r[1]), "=r"(r[2]), "=r"(r[3]) : "r"(addr));
}
__device__ __forceinline__ void ldmx4t(uint32_t* r, uint32_t addr) {
    asm volatile("ldmatrix.sync.aligned.m8n8.x4.trans.shared.b16 {%0,%1,%2,%3}, [%4];"
                 : "=r"(r[0]), "=r"(r[1]), "=r"(r[2]), "=r"(r[3]) : "r"(addr));
}

__device__ __forceinline__ void mma16816(float* c, const uint32_t* a,
                                         uint32_t b0, uint32_t b1) {
    asm volatile(
        "mma.sync.aligned.m16n8k16.row.col.f32.f16.f16.f32 "
        "{%0,%1,%2,%3}, {%4,%5,%6,%7}, {%8,%9}, {%0,%1,%2,%3};"
        : "+f"(c[0]), "+f"(c[1]), "+f"(c[2]), "+f"(c[3])
        : "r"(a[0]), "r"(a[1]), "r"(a[2]), "r"(a[3]), "r"(b0), "r"(b1));
}

__device__ __forceinline__ uint32_t pack2h(float x0, float x1) {
    __half h0 = __float2half_rn(x0), h1 = __float2half_rn(x1);
    return (uint32_t)__half_as_ushort(h0) | ((uint32_t)__half_as_ushort(h1) << 16);
}

__device__ __forceinline__ void split2h(float x0, float x1, uint32_t& hi2, uint32_t& lo2) {
    __half h0 = __float2half_rn(x0), h1 = __float2half_rn(x1);
    float l0 = x0 - __half2float(h0), l1 = x1 - __half2float(h1);
    hi2 = (uint32_t)__half_as_ushort(h0) | ((uint32_t)__half_as_ushort(h1) << 16);
    lo2 = (uint32_t)__half_as_ushort(__float2half_rn(l0))
        | ((uint32_t)__half_as_ushort(__float2half_rn(l1)) << 16);
}

__device__ __forceinline__ void cpa16(uint32_t dst, const void* src) {
    asm volatile("cp.async.cg.shared.global [%0], [%1], 16;" :: "r"(dst), "l"(src));
}
__device__ __forceinline__ void cpa_wait_all() {
    asm volatile("cp.async.wait_all;" ::: "memory");
}
__device__ __forceinline__ void cpa_commit() {
    asm volatile("cp.async.commit_group;" ::: "memory");
}
__device__ __forceinline__ void cpa_wait1() {
    asm volatile("cp.async.wait_group 1;" ::: "memory");
}

// fp16 smem rows: 64 elems = 128B, padded to 144B (9 x 16B phases -> conflict-free)
#define LDT 144

// ---------------------------------------------------------------------------
// Pre-convert kernels
// ---------------------------------------------------------------------------
__global__ void conv_f16(const float* __restrict__ src,
                         __half* __restrict__ dst, int n4)
{
    int i = blockIdx.x * blockDim.x + threadIdx.x;
    if (i >= n4) return;
    float4 v = reinterpret_cast<const float4*>(src)[i];
    reinterpret_cast<uint2*>(dst)[i] = make_uint2(pack2h(v.x, v.y), pack2h(v.z, v.w));
}

// Transposed convert, 3 matrices in one launch (z = matrix)
__global__ void conv_tr3(const float* __restrict__ s0,
                         const float* __restrict__ s1,
                         const float* __restrict__ s2)
{
    int z = blockIdx.z;
    int b = blockIdx.y;
    int i = blockIdx.x * blockDim.x + threadIdx.x;
    if (i >= Cn * Dn) return;
    const float* src = (z == 0 ? s0 : (z == 1 ? s1 : s2));
    int r = i / Dn, c = i % Dn;
    float w = src[(size_t)b * Cn * Dn + i];
    g_wth[(size_t)(z * Hn + b) * Cn * Dn + (size_t)c * Cn + r] = __float2half_rn(w);
}

// Transposed split (hi/lo) for Wp
__global__ void split_trp(const float* __restrict__ src)
{
    int i = blockIdx.x * blockDim.x + threadIdx.x;
    if (i >= Cn * Cn) return;
    int r = i / Cn, c = i % Cn;
    float w = src[i];
    __half hb = __float2half_rn(w);
    size_t o = (size_t)c * Cn + r;
    g_wpth[o] = hb;
    g_wptl[o] = __float2half_rn(w - __half2float(hb));
}

// ---------------------------------------------------------------------------
// Kernel 1: QKV projection, all single fp16. (unchanged from R9)
// ---------------------------------------------------------------------------
#define Q_A  0
#define Q_B0 18432
#define Q_B1 27648
#define QKV_SMEM 36864

__global__ __launch_bounds__(256) void qkv_mm()
{
    extern __shared__ char smc[];
    const uint32_t smb = smem_u32(smc);
    const int tid = threadIdx.x;
    const int wm  = tid >> 5;
    const int lane = tid & 31;
    const int lr = lane & 15;
    const int lc = (lane >> 4) << 3;

    const int m0   = blockIdx.x * 128;
    const bool isqk = blockIdx.y < 8;
    const int h    = blockIdx.y & 7;
    const __half* W0 = g_wth + (size_t)(isqk ? h : 16 + h) * Cn * Dn;
    const __half* W1 = g_wth + (size_t)(8 + h) * Cn * Dn;

    float c0[8][4] = {};
    float c1[8][4] = {};

    for (int kb = 0; kb < 8; kb++) {
        const int c0k = kb * 64;
        #pragma unroll
        for (int i = 0; i < 4; i++) {
            int u = tid + i * 256;
            int row = u >> 3, g = u & 7;
            cpa16(smb + Q_A + (uint32_t)(row * LDT + g * 16),
                  g_xh + (size_t)(m0 + row) * Cn + c0k + g * 8);
        }
        #pragma unroll
        for (int i = 0; i < 2; i++) {
            int u = tid + i * 256;
            int d = u >> 3, g = u & 7;
            uint32_t dst = (uint32_t)(d * LDT + g * 16);
            size_t src = (size_t)d * Cn + c0k + g * 8;
            cpa16(smb + Q_B0 + dst, W0 + src);
            if (isqk) cpa16(smb + Q_B1 + dst, W1 + src);
        }
        cpa_wait_all();
        __syncthreads();

        #pragma unroll
        for (int ks = 0; ks < 4; ks++) {
            const int k0 = ks * 16;
            uint32_t a4[4];
            uint32_t aoff = (uint32_t)((wm * 16 + lr) * LDT + (k0 + lc) * 2);
            ldmx4(a4, smb + Q_A + aoff);
            #pragma unroll
            for (int ng = 0; ng < 4; ng++) {
                uint32_t b4[4];
                uint32_t boff = (uint32_t)((ng * 16 + lr) * LDT + (k0 + lc) * 2);
                ldmx4(b4, smb + Q_B0 + boff);
                mma16816(c0[2*ng],   a4, b4[0], b4[2]);
                mma16816(c0[2*ng+1], a4, b4[1], b4[3]);
                if (isqk) {
                    uint32_t bk[4];
                    ldmx4(bk, smb + Q_B1 + boff);
                    mma16816(c1[2*ng],   a4, bk[0], bk[2]);
                    mma16816(c1[2*ng+1], a4, bk[1], bk[3]);
                }
            }
        }
        __syncthreads();
    }

    const int gid = lane >> 2, qc = (lane & 3) * 2;
    #pragma unroll
    for (int rr = 0; rr < 2; rr++) {
        int m = m0 + wm * 16 + gid + rr * 8;
        int b = m >> 11, t = m & 2047;
        size_t base = (((size_t)(b * Hn + h)) * Tn + t) * Dn;
        if (isqk) {
            #pragma unroll
            for (int j = 0; j < 8; j++) {
                *reinterpret_cast<uint32_t*>(g_q + base + j * 8 + qc) =
                    pack2h(c0[j][rr*2], c0[j][rr*2 + 1]);
                *reinterpret_cast<uint32_t*>(g_k + base + j * 8 + qc) =
                    pack2h(c1[j][rr*2], c1[j][rr*2 + 1]);
            }
        } else {
            #pragma unroll
            for (int j = 0; j < 8; j++)
                *reinterpret_cast<uint32_t*>(g_v + base + j * 8 + qc) =
                    pack2h(c0[j][rr*2], c0[j][rr*2 + 1]);
        }
    }
}

// ---------------------------------------------------------------------------
// Kernel 3: output projection + bias. (unchanged from R9)
// ---------------------------------------------------------------------------
__global__ __launch_bounds__(256) void proj_mm(
    const float* __restrict__ bp, float* __restrict__ outp)
{
    extern __shared__ char smc[];
    const uint32_t smb = smem_u32(smc);
    const int tid = threadIdx.x;
    const int wm  = tid >> 5;
    const int lane = tid & 31;
    const int lr = lane & 15;
    const int lc = (lane >> 4) << 3;

    const int m0 = blockIdx.x * 128;
    const int n0 = blockIdx.y * 64;

    float c[8][4] = {};

    for (int kb = 0; kb < 8; kb++) {
        const int c0 = kb * 64;
        #pragma unroll
        for (int i = 0; i < 4; i++) {
            int u = tid + i * 256;
            int row = u >> 3, g = u & 7;
            cpa16(smb + Q_A + (uint32_t)(row * LDT + g * 16),
                  g_att + (size_t)(m0 + row) * Cn + c0 + g * 8);
        }
        #pragma unroll
        for (int i = 0; i < 2; i++) {
            int u = tid + i * 256;
            int d = u >> 3, g = u & 7;
            uint32_t dst = (uint32_t)(d * LDT + g * 16);
            size_t src = (size_t)(n0 + d) * Cn + c0 + g * 8;
            cpa16(smb + Q_B0 + dst, g_wpth + src);
            cpa16(smb + Q_B1 + dst, g_wptl + src);
        }
        cpa_wait_all();
        __syncthreads();

        #pragma unroll
        for (int ks = 0; ks < 4; ks++) {
            const int k0 = ks * 16;
            uint32_t a4[4];
            uint32_t aoff = (uint32_t)((wm * 16 + lr) * LDT + (k0 + lc) * 2);
            ldmx4(a4, smb + Q_A + aoff);
            #pragma unroll
            for (int ng = 0; ng < 4; ng++) {
                uint32_t bh[4], bl[4];
                uint32_t boff = (uint32_t)((ng * 16 + lr) * LDT + (k0 + lc) * 2);
                ldmx4(bh, smb + Q_B0 + boff);
                ldmx4(bl, smb + Q_B1 + boff);
                mma16816(c[2*ng],   a4, bh[0], bh[2]);
                mma16816(c[2*ng],   a4, bl[0], bl[2]);
                mma16816(c[2*ng+1], a4, bh[1], bh[3]);
                mma16816(c[2*ng+1], a4, bl[1], bl[3]);
            }
        }
        __syncthreads();
    }

    const int gid = lane >> 2, qc = (lane & 3) * 2;
    #pragma unroll
    for (int rr = 0; rr < 2; rr++) {
        int m = m0 + wm * 16 + gid + rr * 8;
        float* op = outp + (size_t)m * Cn + n0;
        #pragma unroll
        for (int j = 0; j < 8; j++) {
            float2 bv = *reinterpret_cast<const float2*>(bp + n0 + j * 8 + qc);
            *reinterpret_cast<float2*>(op + j * 8 + qc) =
                make_float2(c[j][rr*2] + bv.x, c[j][rr*2 + 1] + bv.y);
        }
    }
}

// ---------------------------------------------------------------------------
// Kernel 2: flash attention, TWO query blocks per CTA (256 threads, 8 warps).
// Warps 0-3: rows t0..t0+63; warps 4-7: rows t0+64..t0+127. Shared K/V
// (2-stage cp.async); rel windows in a 3-slot ring (W'B_i == W'A_{i-1}).
// Q staged aliased into the R region (consumed before first R write).
// smem = 36864 (KV x2) + 27648 (W ring) + 33792 (R x4) = 98304 -> 2 CTAs/SM.
// ---------------------------------------------------------------------------
#define SBUF(s)   ((s) * 18432)             // K +0, V +9216
#define SB_K      0
#define SB_V      9216
#define W_SLOT(w) (36864 + (w) * 9216)
#define R_BASE    64512                     // 4 x 8448; also Q staging alias
#define ATT_SMEM  98304
#define LDRH 66

__global__ __launch_bounds__(256, 2) void attn_mm()
{
    extern __shared__ char smc[];
    const uint32_t smb = smem_u32(smc);
    __half* Rh = reinterpret_cast<__half*>(smc);

    const int tid = threadIdx.x;
    const int wm  = tid >> 5;
    const int lane = tid & 31;
    const int grp = wm >> 2;               // 0: rows t0, 1: rows t0+64
    const int wg  = wm & 3;
    const int lr = lane & 15;
    const int lc = (lane >> 4) << 3;
    const int gid = lane >> 2, qc = (lane & 3) * 2;

    const int bh = blockIdx.x;
    const int h  = bh & (Hn - 1);
    const int b  = bh >> 3;
    const int t0 = (int)(gridDim.y - 1 - blockIdx.y) * 128;
    const int tq = t0 + 64 * grp;
    const int ntiles = t0 / 64 + 2;

    const __half* qg = g_q + (size_t)bh * Tn * Dn;
    const __half* kg = g_k + (size_t)bh * Tn * Dn;
    const __half* vg = g_v + (size_t)bh * Tn * Dn;
    const __half* rg = g_relh + (size_t)h * Tn * Dn;

    const int jm1 = Tn - 128 - t0;   // >= 0 (t0 <= Tn-128); W'A_j rows = jm1 + 64(j+1)

    // ---- prologue: Q(128 rows -> R region), W'A_{-1}->slot2, W'A_0->slot0,
    //      W'A_1->slot1 (if t0>=64), K0/V0 -> stage0
    #pragma unroll
    for (int i = 0; i < 4; i++) {
        int u = tid + i * 256;              // 1024 chunks (128 rows x 8)
        int row = u >> 3, g = u & 7;
        cpa16(smb + R_BASE + (uint32_t)(row * LDT + g * 16),
              qg + (size_t)(t0 + row) * Dn + g * 8);
    }
    #pragma unroll
    for (int i = 0; i < 2; i++) {
        int u = tid + i * 256;              // 512 chunks (64 rows x 8)
        int row = u >> 3, g = u & 7;
        uint32_t dst = (uint32_t)(row * LDT + g * 16);
        cpa16(smb + W_SLOT(2) + dst, rg + (size_t)(jm1 + row) * Dn + g * 8);
        cpa16(smb + W_SLOT(0) + dst, rg + (size_t)(jm1 + 64 + row) * Dn + g * 8);
        if (t0 >= 64)
            cpa16(smb + W_SLOT(1) + dst, rg + (size_t)(jm1 + 128 + row) * Dn + g * 8);
        size_t s = (size_t)row * Dn + g * 8;
        cpa16(smb + SBUF(0) + SB_K + dst, kg + s);
        cpa16(smb + SBUF(0) + SB_V + dst, vg + s);
    }
    cpa_wait_all();
    __syncthreads();

    // ---- Q fragments (group's 64-row slice of the staged 128 rows)
    uint32_t q4[4][4];
    #pragma unroll
    for (int ks = 0; ks < 4; ks++) {
        uint32_t aoff = (uint32_t)((grp * 64 + wg * 16 + lr) * LDT + (ks * 16 + lc) * 2);
        ldmx4(q4[ks], smb + R_BASE + aoff);
    }
    __syncthreads();   // Q staging consumed; R region may be written now

    // ---- R preload: group A from W'A_0 (slot0), group B from W'A_{-1} (slot2)
    int rprev = R_BASE + grp * 16896;
    int rnew  = rprev + 8448;
    {
        const uint32_t wb = smb + (grp ? W_SLOT(2) : W_SLOT(0));
        float c[8][4] = {};
        #pragma unroll
        for (int ks = 0; ks < 4; ks++) {
            #pragma unroll
            for (int ng = 0; ng < 4; ng++) {
                uint32_t bh4[4];
                uint32_t boff = (uint32_t)((ng * 16 + lr) * LDT + (ks * 16 + lc) * 2);
                ldmx4(bh4, wb + boff);
                mma16816(c[2*ng],   q4[ks], bh4[0], bh4[2]);
                mma16816(c[2*ng+1], q4[ks], bh4[1], bh4[3]);
            }
        }
        __half* Rp = Rh + rprev / 2;
        #pragma unroll
        for (int j = 0; j < 8; j++) {
            *reinterpret_cast<uint32_t*>(Rp + (wg*16 + gid)     * LDRH + j*8 + qc) =
                pack2h(c[j][0], c[j][1]);
            *reinterpret_cast<uint32_t*>(Rp + (wg*16 + gid + 8) * LDRH + j*8 + qc) =
                pack2h(c[j][2], c[j][3]);
        }
        __syncwarp();
    }
    __syncthreads();   // slot2 consumed before tile-0 prefetch may overwrite it

    float o[8][4] = {};
    float mrow[2] = {-1e30f, -1e30f};
    float lrow[2] = {};

    for (int i = 0; i < ntiles; i++) {
        const int s0 = i * 64;

        // prefetch tile i+1: K/V into stage (i+1)&1, window W'A_{i+2} -> slot (i+2)%3
        if (i + 1 < ntiles) {
            const int s1 = s0 + 64;
            const uint32_t nb = smb + SBUF((i + 1) & 1);
            const bool needW = (64 * (i + 2) <= t0);
            #pragma unroll
            for (int u2 = 0; u2 < 2; u2++) {
                int u = tid + u2 * 256;
                int row = u >> 3, g = u & 7;
                uint32_t dst = (uint32_t)(row * LDT + g * 16);
                size_t s = (size_t)(s1 + row) * Dn + g * 8;
                cpa16(nb + SB_K + dst, kg + s);
                cpa16(nb + SB_V + dst, vg + s);
                if (needW)
                    cpa16(smb + W_SLOT((i + 2) % 3) + dst,
                          rg + (size_t)(jm1 + 64 * (i + 3) + row) * Dn + g * 8);
            }
        }
        cpa_commit();
        cpa_wait1();        // tile i's stage complete
        __syncthreads();

        const uint32_t kb = smb + SBUF(i & 1);
        const bool act  = (s0 <= tq);
        const bool hasR = (s0 < tq);

        if (act) {
            float c[8][4];

            // ---- R GEMM: group A window W'A_{i+1}, group B window W'A_i ----
            if (hasR) {
                const uint32_t wb = smb + W_SLOT((i + 1 - grp) % 3);
                #pragma unroll
                for (int j = 0; j < 8; j++)
                    #pragma unroll
                    for (int z = 0; z < 4; z++) c[j][z] = 0.f;
                #pragma unroll
                for (int ks = 0; ks < 4; ks++) {
                    #pragma unroll
                    for (int ng = 0; ng < 4; ng++) {
                        uint32_t bh4[4];
                        uint32_t boff = (uint32_t)((ng * 16 + lr) * LDT + (ks * 16 + lc) * 2);
                        ldmx4(bh4, wb + boff);
                        mma16816(c[2*ng],   q4[ks], bh4[0], bh4[2]);
                        mma16816(c[2*ng+1], q4[ks], bh4[1], bh4[3]);
                    }
                }
                __half* Rp = Rh + rnew / 2;
                #pragma unroll
                for (int j = 0; j < 8; j++) {
                    *reinterpret_cast<uint32_t*>(Rp + (wg*16 + gid)     * LDRH + j*8 + qc) =
                        pack2h(c[j][0], c[j][1]);
                    *reinterpret_cast<uint32_t*>(Rp + (wg*16 + gid + 8) * LDRH + j*8 + qc) =
                        pack2h(c[j][2], c[j][3]);
                }
                __syncwarp();
            }

            // ---- S GEMM ----
            #pragma unroll
            for (int j = 0; j < 8; j++)
                #pragma unroll
                for (int z = 0; z < 4; z++) c[j][z] = 0.f;
            #pragma unroll
            for (int ks = 0; ks < 4; ks++) {
                #pragma unroll
                for (int ng = 0; ng < 4; ng++) {
                    uint32_t bh4[4];
                    uint32_t boff = (uint32_t)((ng * 16 + lr) * LDT + (ks * 16 + lc) * 2);
                    ldmx4(bh4, kb + SB_K + boff);
                    mma16816(c[2*ng],   q4[ks], bh4[0], bh4[2]);
                    mma16816(c[2*ng+1], q4[ks], bh4[1], bh4[3]);
                }
            }

            // ---- gather BD (fp16 R; rows are warp-local) ----
            {
                const __half* Rp = Rh + rprev / 2;
                const __half* Rn = Rh + rnew / 2;
                #pragma unroll
                for (int rr = 0; rr < 2; rr++) {
                    int tl = wg*16 + gid + rr*8;
                    #pragma unroll
                    for (int j = 0; j < 8; j++) {
                        #pragma unroll
                        for (int z = 0; z < 2; z++) {
                            int sl = j*8 + qc + z;
                            int jj = sl - tl + 63;
                            if (jj < 64) c[j][rr*2 + z] += __half2float(Rp[tl * LDRH + jj]);
                            else if (hasR) c[j][rr*2 + z] += __half2float(Rn[tl * LDRH + jj - 64]);
                        }
                    }
                }
            }

            // ---- wrap corner (global tile 0,0 only) ----
            if (tq == 0 && s0 == 0 && wg == 0 && gid < 5) {
                int t = gid;
                #pragma unroll
                for (int z = 0; z < 2; z++) {
                    int s = qc + z;
                    if (s > t + 1 && s < 6) {
                        float bd = 0.f;
                        for (int d = 0; d < 64; d++)
                            bd += __half2float(qg[(t + 1) * Dn + d])
                                * __half2float(rg[(size_t)(s - t - 2) * Dn + d]);
                        c[0][z] += bd;
                    }
                }
            }

            // ---- mask + scale + online softmax ----
            #pragma unroll
            for (int rr = 0; rr < 2; rr++) {
                int t = tq + wg*16 + gid + rr*8;
                float rm = -1e30f;
                #pragma unroll
                for (int j = 0; j < 8; j++) {
                    #pragma unroll
                    for (int z = 0; z < 2; z++) {
                        int s = s0 + j*8 + qc + z;
                        float v = (s <= t || s < 6) ? c[j][rr*2+z] * kScale : -1e30f;
                        c[j][rr*2+z] = v;
                        rm = fmaxf(rm, v);
                    }
                }
                rm = fmaxf(rm, __shfl_xor_sync(0xffffffffu, rm, 1));
                rm = fmaxf(rm, __shfl_xor_sync(0xffffffffu, rm, 2));
                float mnew = fmaxf(mrow[rr], rm);
                float alpha = __expf(mrow[rr] - mnew);
                mrow[rr] = mnew;
                float rs = 0.f;
                #pragma unroll
                for (int j = 0; j < 8; j++) {
                    #pragma unroll
                    for (int z = 0; z < 2; z++) {
                        float p = __expf(c[j][rr*2+z] - mnew);
                        c[j][rr*2+z] = p;
                        rs += p;
                    }
                }
                rs += __shfl_xor_sync(0xffffffffu, rs, 1);
                rs += __shfl_xor_sync(0xffffffffu, rs, 2);
                lrow[rr] = lrow[rr] * alpha + rs;
                #pragma unroll
                for (int j = 0; j < 8; j++) {
                    o[j][rr*2]   *= alpha;
                    o[j][rr*2+1] *= alpha;
                }
            }

            // ---- O += P * V (2-MMA: (P_hi + P_lo) x V); split per-kc ----
            #pragma unroll
            for (int kc = 0; kc < 4; kc++) {
                uint32_t p_hi[4], p_lo[4];
                split2h(c[2*kc][0],   c[2*kc][1],   p_hi[0], p_lo[0]);
                split2h(c[2*kc][2],   c[2*kc][3],   p_hi[1], p_lo[1]);
                split2h(c[2*kc+1][0], c[2*kc+1][1], p_hi[2], p_lo[2]);
                split2h(c[2*kc+1][2], c[2*kc+1][3], p_hi[3], p_lo[3]);
                uint32_t vbase = (uint32_t)(kc*16 + (lane & 7) + ((lane & 16) >> 1)) * LDT;
                #pragma unroll
                for (int ng = 0; ng < 4; ng++) {
                    uint32_t bv4[4];
                    uint32_t voff = vbase + (uint32_t)(ng*16 + (lane & 8)) * 2;
                    ldmx4t(bv4, kb + SB_V + voff);
                    mma16816(o[2*ng],   p_hi, bv4[0], bv4[2]);
                    mma16816(o[2*ng],   p_lo, bv4[0], bv4[2]);
                    mma16816(o[2*ng+1], p_hi, bv4[1], bv4[3]);
                    mma16816(o[2*ng+1], p_lo, bv4[1], bv4[3]);
                }
            }

            if (hasR) { int tp = rprev; rprev = rnew; rnew = tp; }
        }
        __syncthreads();     // stage + W slots consumed before next prefetch
    }

    // ---- epilogue: att = O / l -> single fp16 ----
    #pragma unroll
    for (int rr = 0; rr < 2; rr++) {
        int t = tq + wg*16 + gid + rr*8;
        float inv = 1.0f / lrow[rr];
        size_t base = ((size_t)b * Tn + t) * Cn + h * Dn;
        #pragma unroll
        for (int j = 0; j < 8; j++)
            *reinterpret_cast<uint32_t*>(g_att + base + j*8 + qc) =
                pack2h(o[j][rr*2] * inv, o[j][rr*2+1] * inv);
    }
}

// ---------------------------------------------------------------------------
extern "C" void kernel_launch(void* const* d_in, const int* in_sizes, int n_in,
                              void* d_out, int out_size)
{
    const float* x   = (const float*)d_in[0];
    const float* Wq  = (const float*)d_in[1];
    const float* Wk  = (const float*)d_in[2];
    const float* Wv  = (const float*)d_in[3];
    const float* rel = (const float*)d_in[4];
    const float* Wp  = (const float*)d_in[5];
    const float* bp  = (const float*)d_in[6];
    float* out = (float*)d_out;

    static __half *h_xh, *h_relh;
    static bool init = false;
    if (!init) {
        cudaGetSymbolAddress((void**)&h_xh, g_xh);
        cudaGetSymbolAddress((void**)&h_relh, g_relh);
        cudaFuncSetAttribute(qkv_mm,  cudaFuncAttributeMaxDynamicSharedMemorySize, QKV_SMEM);
        cudaFuncSetAttribute(proj_mm, cudaFuncAttributeMaxDynamicSharedMemorySize, QKV_SMEM);
        cudaFuncSetAttribute(attn_mm, cudaFuncAttributeMaxDynamicSharedMemorySize, ATT_SMEM);
        init = true;
    }

    conv_f16<<<(NX/4 + 255)/256, 256>>>(x, h_xh, NX/4);
    conv_f16<<<(NR/4 + 255)/256, 256>>>(rel, h_relh, NR/4);
    conv_tr3<<<dim3((Cn*Dn + 255)/256, Hn, 3), 256>>>(Wq, Wk, Wv);
    split_trp<<<(Cn*Cn + 255)/256, 256>>>(Wp);

    qkv_mm<<<dim3(64, 16), 256, QKV_SMEM>>>();
    attn_mm<<<dim3(Bn * Hn, Tn / 128), 256, ATT_SMEM>>>();
    proj_mm<<<dim3(64, 8), 256, QKV_SMEM>>>(bp, out);
}

// round 13
// speedup vs baseline: 1.8542x; 1.0186x over previous
#include <cuda_runtime.h>
#include <cuda_fp16.h>
#include <cstdint>

// Problem constants
#define Bn 4
#define Tn 2048
#define Cn 512
#define Hn 8
#define Dn 64
__device__ __constant__ float kScale = 0.04419417382415922f; // 512^-0.5

// ---------------------------------------------------------------------------
// Global scratch (fp16)
// ---------------------------------------------------------------------------
#define NX  (Bn*Tn*Cn)
#define NW  (Hn*Cn*Dn)
#define NR  (Hn*Tn*Dn)
#define NP  (Cn*Cn)
#define NQ  (Bn*Hn*Tn*Dn)

__device__ __align__(16) __half g_xh[NX];
__device__ __align__(16) __half g_wth[3*NW];         // [mat][h][d][k]
__device__ __align__(16) __half g_relh[NR];
__device__ __align__(16) __half g_wpth[NP], g_wptl[NP];
__device__ __align__(16) __half g_q[NQ], g_k[NQ], g_v[NQ];
__device__ __align__(16) __half g_att[NX];

// ---------------------------------------------------------------------------
// helpers
// ---------------------------------------------------------------------------
__device__ __forceinline__ uint32_t smem_u32(const void* p) {
    uint32_t a;
    asm("{ .reg .u64 t; cvta.to.shared.u64 t, %1; cvt.u32.u64 %0, t; }"
        : "=r"(a) : "l"(p));
    return a;
}

__device__ __forceinline__ void ldmx4(uint32_t* r, uint32_t addr) {
    asm volatile("ldmatrix.sync.aligned.m8n8.x4.shared.b16 {%0,%1,%2,%3}, [%4];"
                 : "=r"(r[0]), "=r"(r[1]), "=r"(r[2]), "=r"(r[3]) : "r"(addr));
}
__device__ __forceinline__ void ldmx4t(uint32_t* r, uint32_t addr) {
    asm volatile("ldmatrix.sync.aligned.m8n8.x4.trans.shared.b16 {%0,%1,%2,%3}, [%4];"
                 : "=r"(r[0]), "=r"(r[1]), "=r"(r[2]), "=r"(r[3]) : "r"(addr));
}

__device__ __forceinline__ void mma16816(float* c, const uint32_t* a,
                                         uint32_t b0, uint32_t b1) {
    asm volatile(
        "mma.sync.aligned.m16n8k16.row.col.f32.f16.f16.f32 "
        "{%0,%1,%2,%3}, {%4,%5,%6,%7}, {%8,%9}, {%0,%1,%2,%3};"
        : "+f"(c[0]), "+f"(c[1]), "+f"(c[2]), "+f"(c[3])
        : "r"(a[0]), "r"(a[1]), "r"(a[2]), "r"(a[3]), "r"(b0), "r"(b1));
}

__device__ __forceinline__ uint32_t pack2h(float x0, float x1) {
    __half h0 = __float2half_rn(x0), h1 = __float2half_rn(x1);
    return (uint32_t)__half_as_ushort(h0) | ((uint32_t)__half_as_ushort(h1) << 16);
}

__device__ __forceinline__ void split2h(float x0, float x1, uint32_t& hi2, uint32_t& lo2) {
    __half h0 = __float2half_rn(x0), h1 = __float2half_rn(x1);
    float l0 = x0 - __half2float(h0), l1 = x1 - __half2float(h1);
    hi2 = (uint32_t)__half_as_ushort(h0) | ((uint32_t)__half_as_ushort(h1) << 16);
    lo2 = (uint32_t)__half_as_ushort(__float2half_rn(l0))
        | ((uint32_t)__half_as_ushort(__float2half_rn(l1)) << 16);
}

__device__ __forceinline__ void cpa16(uint32_t dst, const void* src) {
    asm volatile("cp.async.cg.shared.global [%0], [%1], 16;" :: "r"(dst), "l"(src));
}
__device__ __forceinline__ void cpa_wait_all() {
    asm volatile("cp.async.wait_all;" ::: "memory");
}
__device__ __forceinline__ void cpa_commit() {
    asm volatile("cp.async.commit_group;" ::: "memory");
}
__device__ __forceinline__ void cpa_wait1() {
    asm volatile("cp.async.wait_group 1;" ::: "memory");
}

// fp16 smem rows: 64 elems = 128B, padded to 144B (9 x 16B phases -> conflict-free)
#define LDT 144

// ---------------------------------------------------------------------------
// Pre-convert kernels
// ---------------------------------------------------------------------------
// Merged x + rel conversion: flattened float4 index over [x | rel].
__global__ void conv_f16_2(const float* __restrict__ sa, __half* __restrict__ da,
                           int n4a,
                           const float* __restrict__ sb, __half* __restrict__ db,
                           int n4b)
{
    int i = blockIdx.x * blockDim.x + threadIdx.x;
    const float* s;
    __half* d;
    if (i < n4a) { s = sa; d = da; }
    else         { i -= n4a; if (i >= n4b) return; s = sb; d = db; }
    float4 v = reinterpret_cast<const float4*>(s)[i];
    reinterpret_cast<uint2*>(d)[i] = make_uint2(pack2h(v.x, v.y), pack2h(v.z, v.w));
}

// Transposed convert, 3 matrices in one launch (z = matrix)
__global__ void conv_tr3(const float* __restrict__ s0,
                         const float* __restrict__ s1,
                         const float* __restrict__ s2)
{
    int z = blockIdx.z;
    int b = blockIdx.y;
    int i = blockIdx.x * blockDim.x + threadIdx.x;
    if (i >= Cn * Dn) return;
    const float* src = (z == 0 ? s0 : (z == 1 ? s1 : s2));
    int r = i / Dn, c = i % Dn;
    float w = src[(size_t)b * Cn * Dn + i];
    g_wth[(size_t)(z * Hn + b) * Cn * Dn + (size_t)c * Cn + r] = __float2half_rn(w);
}

// Transposed split (hi/lo) for Wp
__global__ void split_trp(const float* __restrict__ src)
{
    int i = blockIdx.x * blockDim.x + threadIdx.x;
    if (i >= Cn * Cn) return;
    int r = i / Cn, c = i % Cn;
    float w = src[i];
    __half hb = __float2half_rn(w);
    size_t o = (size_t)c * Cn + r;
    g_wpth[o] = hb;
    g_wptl[o] = __float2half_rn(w - __half2float(hb));
}

// ---------------------------------------------------------------------------
// Kernel 1: QKV projection, all single fp16, 2-stage cp.async pipeline.
// grid = (64 m-tiles of 128, 16): y<8 -> fused q+k head y; y>=8 -> v head y-8.
// stage = A 18432 + B0 9216 + B1 9216 = 36864; x2 = 73728 -> 3 CTAs/SM.
// ---------------------------------------------------------------------------
#define GST(s) ((s) * 36864)
#define G_A  0
#define G_B0 18432
#define G_B1 27648
#define GEMM_SMEM 73728

__global__ __launch_bounds__(256) void qkv_mm()
{
    extern __shared__ char smc[];
    const uint32_t smb = smem_u32(smc);
    const int tid = threadIdx.x;
    const int wm  = tid >> 5;
    const int lane = tid & 31;
    const int lr = lane & 15;
    const int lc = (lane >> 4) << 3;

    const int m0   = blockIdx.x * 128;
    const bool isqk = blockIdx.y < 8;
    const int h    = blockIdx.y & 7;
    const __half* W0 = g_wth + (size_t)(isqk ? h : 16 + h) * Cn * Dn;
    const __half* W1 = g_wth + (size_t)(8 + h) * Cn * Dn;

    float c0[8][4] = {};
    float c1[8][4] = {};

    // prologue: load kb=0 into stage 0, committed as its OWN group
    {
        const uint32_t st = smb + GST(0);
        #pragma unroll
        for (int i = 0; i < 4; i++) {
            int u = tid + i * 256;
            int row = u >> 3, g = u & 7;
            cpa16(st + G_A + (uint32_t)(row * LDT + g * 16),
                  g_xh + (size_t)(m0 + row) * Cn + g * 8);
        }
        #pragma unroll
        for (int i = 0; i < 2; i++) {
            int u = tid + i * 256;
            int d = u >> 3, g = u & 7;
            uint32_t dst = (uint32_t)(d * LDT + g * 16);
            size_t src = (size_t)d * Cn + g * 8;
            cpa16(st + G_B0 + dst, W0 + src);
            if (isqk) cpa16(st + G_B1 + dst, W1 + src);
        }
        cpa_commit();   // FIX (R12 NaN): prologue must be its own group
    }

    for (int kb = 0; kb < 8; kb++) {
        // prefetch kb+1 into the other stage
        if (kb + 1 < 8) {
            const int c1k = (kb + 1) * 64;
            const uint32_t st = smb + GST((kb + 1) & 1);
            #pragma unroll
            for (int i = 0; i < 4; i++) {
                int u = tid + i * 256;
                int row = u >> 3, g = u & 7;
                cpa16(st + G_A + (uint32_t)(row * LDT + g * 16),
                      g_xh + (size_t)(m0 + row) * Cn + c1k + g * 8);
            }
            #pragma unroll
            for (int i = 0; i < 2; i++) {
                int u = tid + i * 256;
                int d = u >> 3, g = u & 7;
                uint32_t dst = (uint32_t)(d * LDT + g * 16);
                size_t src = (size_t)d * Cn + c1k + g * 8;
                cpa16(st + G_B0 + dst, W0 + src);
                if (isqk) cpa16(st + G_B1 + dst, W1 + src);
            }
        }
        cpa_commit();
        cpa_wait1();       // current stage's group drained; prefetch still in flight
        __syncthreads();

        const uint32_t st = smb + GST(kb & 1);
        #pragma unroll
        for (int ks = 0; ks < 4; ks++) {
            const int k0 = ks * 16;
            uint32_t a4[4];
            uint32_t aoff = (uint32_t)((wm * 16 + lr) * LDT + (k0 + lc) * 2);
            ldmx4(a4, st + G_A + aoff);
            #pragma unroll
            for (int ng = 0; ng < 4; ng++) {
                uint32_t b4[4];
                uint32_t boff = (uint32_t)((ng * 16 + lr) * LDT + (k0 + lc) * 2);
                ldmx4(b4, st + G_B0 + boff);
                mma16816(c0[2*ng],   a4, b4[0], b4[2]);
                mma16816(c0[2*ng+1], a4, b4[1], b4[3]);
                if (isqk) {
                    uint32_t bk[4];
                    ldmx4(bk, st + G_B1 + boff);
                    mma16816(c1[2*ng],   a4, bk[0], bk[2]);
                    mma16816(c1[2*ng+1], a4, bk[1], bk[3]);
                }
            }
        }
        __syncthreads();    // stage consumed before the next prefetch overwrites
    }

    const int gid = lane >> 2, qc = (lane & 3) * 2;
    #pragma unroll
    for (int rr = 0; rr < 2; rr++) {
        int m = m0 + wm * 16 + gid + rr * 8;
        int b = m >> 11, t = m & 2047;
        size_t base = (((size_t)(b * Hn + h)) * Tn + t) * Dn;
        if (isqk) {
            #pragma unroll
            for (int j = 0; j < 8; j++) {
                *reinterpret_cast<uint32_t*>(g_q + base + j * 8 + qc) =
                    pack2h(c0[j][rr*2], c0[j][rr*2 + 1]);
                *reinterpret_cast<uint32_t*>(g_k + base + j * 8 + qc) =
                    pack2h(c1[j][rr*2], c1[j][rr*2 + 1]);
            }
        } else {
            #pragma unroll
            for (int j = 0; j < 8; j++)
                *reinterpret_cast<uint32_t*>(g_v + base + j * 8 + qc) =
                    pack2h(c0[j][rr*2], c0[j][rr*2 + 1]);
        }
    }
}

// ---------------------------------------------------------------------------
// Kernel 3: output projection + bias, 2-stage cp.async pipeline.
// grid = (64, 8). att single fp16; Wp split (2-MMA). 73728 B -> 3 CTAs/SM.
// ---------------------------------------------------------------------------
__global__ __launch_bounds__(256) void proj_mm(
    const float* __restrict__ bp, float* __restrict__ outp)
{
    extern __shared__ char smc[];
    const uint32_t smb = smem_u32(smc);
    const int tid = threadIdx.x;
    const int wm  = tid >> 5;
    const int lane = tid & 31;
    const int lr = lane & 15;
    const int lc = (lane >> 4) << 3;

    const int m0 = blockIdx.x * 128;
    const int n0 = blockIdx.y * 64;

    float c[8][4] = {};

    // prologue: kb=0 -> stage 0, committed as its OWN group
    {
        const uint32_t st = smb + GST(0);
        #pragma unroll
        for (int i = 0; i < 4; i++) {
            int u = tid + i * 256;
            int row = u >> 3, g = u & 7;
            cpa16(st + G_A + (uint32_t)(row * LDT + g * 16),
                  g_att + (size_t)(m0 + row) * Cn + g * 8);
        }
        #pragma unroll
        for (int i = 0; i < 2; i++) {
            int u = tid + i * 256;
            int d = u >> 3, g = u & 7;
            uint32_t dst = (uint32_t)(d * LDT + g * 16);
            size_t src = (size_t)(n0 + d) * Cn + g * 8;
            cpa16(st + G_B0 + dst, g_wpth + src);
            cpa16(st + G_B1 + dst, g_wptl + src);
        }
        cpa_commit();   // FIX (R12 NaN): prologue must be its own group
    }

    for (int kb = 0; kb < 8; kb++) {
        if (kb + 1 < 8) {
            const int c1k = (kb + 1) * 64;
            const uint32_t st = smb + GST((kb + 1) & 1);
            #pragma unroll
            for (int i = 0; i < 4; i++) {
                int u = tid + i * 256;
                int row = u >> 3, g = u & 7;
                cpa16(st + G_A + (uint32_t)(row * LDT + g * 16),
                      g_att + (size_t)(m0 + row) * Cn + c1k + g * 8);
            }
            #pragma unroll
            for (int i = 0; i < 2; i++) {
                int u = tid + i * 256;
                int d = u >> 3, g = u & 7;
                uint32_t dst = (uint32_t)(d * LDT + g * 16);
                size_t src = (size_t)(n0 + d) * Cn + c1k + g * 8;
                cpa16(st + G_B0 + dst, g_wpth + src);
                cpa16(st + G_B1 + dst, g_wptl + src);
            }
        }
        cpa_commit();
        cpa_wait1();
        __syncthreads();

        const uint32_t st = smb + GST(kb & 1);
        #pragma unroll
        for (int ks = 0; ks < 4; ks++) {
            const int k0 = ks * 16;
            uint32_t a4[4];
            uint32_t aoff = (uint32_t)((wm * 16 + lr) * LDT + (k0 + lc) * 2);
            ldmx4(a4, st + G_A + aoff);
            #pragma unroll
            for (int ng = 0; ng < 4; ng++) {
                uint32_t bh[4], bl[4];
                uint32_t boff = (uint32_t)((ng * 16 + lr) * LDT + (k0 + lc) * 2);
                ldmx4(bh, st + G_B0 + boff);
                ldmx4(bl, st + G_B1 + boff);
                mma16816(c[2*ng],   a4, bh[0], bh[2]);
                mma16816(c[2*ng],   a4, bl[0], bl[2]);
                mma16816(c[2*ng+1], a4, bh[1], bh[3]);
                mma16816(c[2*ng+1], a4, bl[1], bl[3]);
            }
        }
        __syncthreads();
    }

    const int gid = lane >> 2, qc = (lane & 3) * 2;
    #pragma unroll
    for (int rr = 0; rr < 2; rr++) {
        int m = m0 + wm * 16 + gid + rr * 8;
        float* op = outp + (size_t)m * Cn + n0;
        #pragma unroll
        for (int j = 0; j < 8; j++) {
            float2 bv = *reinterpret_cast<const float2*>(bp + n0 + j * 8 + qc);
            *reinterpret_cast<float2*>(op + j * 8 + qc) =
                make_float2(c[j][rr*2] + bv.x, c[j][rr*2 + 1] + bv.y);
        }
    }
}

// ---------------------------------------------------------------------------
// Kernel 2: flash attention, TWO query blocks per CTA. (unchanged from R11)
// smem = 36864 (KV x2) + 27648 (W ring) + 33792 (R x4) = 98304 -> 2 CTAs/SM.
// ---------------------------------------------------------------------------
#define SBUF(s)   ((s) * 18432)             // K +0, V +9216
#define SB_K      0
#define SB_V      9216
#define W_SLOT(w) (36864 + (w) * 9216)
#define R_BASE    64512                     // 4 x 8448; also Q staging alias
#define ATT_SMEM  98304
#define LDRH 66

__global__ __launch_bounds__(256, 2) void attn_mm()
{
    extern __shared__ char smc[];
    const uint32_t smb = smem_u32(smc);
    __half* Rh = reinterpret_cast<__half*>(smc);

    const int tid = threadIdx.x;
    const int wm  = tid >> 5;
    const int lane = tid & 31;
    const int grp = wm >> 2;               // 0: rows t0, 1: rows t0+64
    const int wg  = wm & 3;
    const int lr = lane & 15;
    const int lc = (lane >> 4) << 3;
    const int gid = lane >> 2, qc = (lane & 3) * 2;

    const int bh = blockIdx.x;
    const int h  = bh & (Hn - 1);
    const int b  = bh >> 3;
    const int t0 = (int)(gridDim.y - 1 - blockIdx.y) * 128;
    const int tq = t0 + 64 * grp;
    const int ntiles = t0 / 64 + 2;

    const __half* qg = g_q + (size_t)bh * Tn * Dn;
    const __half* kg = g_k + (size_t)bh * Tn * Dn;
    const __half* vg = g_v + (size_t)bh * Tn * Dn;
    const __half* rg = g_relh + (size_t)h * Tn * Dn;

    const int jm1 = Tn - 128 - t0;   // >= 0; W'A_j rows = jm1 + 64(j+1)

    // ---- prologue
    #pragma unroll
    for (int i = 0; i < 4; i++) {
        int u = tid + i * 256;
        int row = u >> 3, g = u & 7;
        cpa16(smb + R_BASE + (uint32_t)(row * LDT + g * 16),
              qg + (size_t)(t0 + row) * Dn + g * 8);
    }
    #pragma unroll
    for (int i = 0; i < 2; i++) {
        int u = tid + i * 256;
        int row = u >> 3, g = u & 7;
        uint32_t dst = (uint32_t)(row * LDT + g * 16);
        cpa16(smb + W_SLOT(2) + dst, rg + (size_t)(jm1 + row) * Dn + g * 8);
        cpa16(smb + W_SLOT(0) + dst, rg + (size_t)(jm1 + 64 + row) * Dn + g * 8);
        if (t0 >= 64)
            cpa16(smb + W_SLOT(1) + dst, rg + (size_t)(jm1 + 128 + row) * Dn + g * 8);
        size_t s = (size_t)row * Dn + g * 8;
        cpa16(smb + SBUF(0) + SB_K + dst, kg + s);
        cpa16(smb + SBUF(0) + SB_V + dst, vg + s);
    }
    cpa_wait_all();
    __syncthreads();

    uint32_t q4[4][4];
    #pragma unroll
    for (int ks = 0; ks < 4; ks++) {
        uint32_t aoff = (uint32_t)((grp * 64 + wg * 16 + lr) * LDT + (ks * 16 + lc) * 2);
        ldmx4(q4[ks], smb + R_BASE + aoff);
    }
    __syncthreads();   // Q staging consumed; R region may be written now

    int rprev = R_BASE + grp * 16896;
    int rnew  = rprev + 8448;
    {
        const uint32_t wb = smb + (grp ? W_SLOT(2) : W_SLOT(0));
        float c[8][4] = {};
        #pragma unroll
        for (int ks = 0; ks < 4; ks++) {
            #pragma unroll
            for (int ng = 0; ng < 4; ng++) {
                uint32_t bh4[4];
                uint32_t boff = (uint32_t)((ng * 16 + lr) * LDT + (ks * 16 + lc) * 2);
                ldmx4(bh4, wb + boff);
                mma16816(c[2*ng],   q4[ks], bh4[0], bh4[2]);
                mma16816(c[2*ng+1], q4[ks], bh4[1], bh4[3]);
            }
        }
        __half* Rp = Rh + rprev / 2;
        #pragma unroll
        for (int j = 0; j < 8; j++) {
            *reinterpret_cast<uint32_t*>(Rp + (wg*16 + gid)     * LDRH + j*8 + qc) =
                pack2h(c[j][0], c[j][1]);
            *reinterpret_cast<uint32_t*>(Rp + (wg*16 + gid + 8) * LDRH + j*8 + qc) =
                pack2h(c[j][2], c[j][3]);
        }
        __syncwarp();
    }
    __syncthreads();   // slot2 consumed before tile-0 prefetch may overwrite it

    float o[8][4] = {};
    float mrow[2] = {-1e30f, -1e30f};
    float lrow[2] = {};

    for (int i = 0; i < ntiles; i++) {
        const int s0 = i * 64;

        if (i + 1 < ntiles) {
            const int s1 = s0 + 64;
            const uint32_t nb = smb + SBUF((i + 1) & 1);
            const bool needW = (64 * (i + 2) <= t0);
            #pragma unroll
            for (int u2 = 0; u2 < 2; u2++) {
                int u = tid + u2 * 256;
                int row = u >> 3, g = u & 7;
                uint32_t dst = (uint32_t)(row * LDT + g * 16);
                size_t s = (size_t)(s1 + row) * Dn + g * 8;
                cpa16(nb + SB_K + dst, kg + s);
                cpa16(nb + SB_V + dst, vg + s);
                if (needW)
                    cpa16(smb + W_SLOT((i + 2) % 3) + dst,
                          rg + (size_t)(jm1 + 64 * (i + 3) + row) * Dn + g * 8);
            }
        }
        cpa_commit();
        cpa_wait1();
        __syncthreads();

        const uint32_t kb = smb + SBUF(i & 1);
        const bool act  = (s0 <= tq);
        const bool hasR = (s0 < tq);

        if (act) {
            float c[8][4];

            if (hasR) {
                const uint32_t wb = smb + W_SLOT((i + 1 - grp) % 3);
                #pragma unroll
                for (int j = 0; j < 8; j++)
                    #pragma unroll
                    for (int z = 0; z < 4; z++) c[j][z] = 0.f;
                #pragma unroll
                for (int ks = 0; ks < 4; ks++) {
                    #pragma unroll
                    for (int ng = 0; ng < 4; ng++) {
                        uint32_t bh4[4];
                        uint32_t boff = (uint32_t)((ng * 16 + lr) * LDT + (ks * 16 + lc) * 2);
                        ldmx4(bh4, wb + boff);
                        mma16816(c[2*ng],   q4[ks], bh4[0], bh4[2]);
                        mma16816(c[2*ng+1], q4[ks], bh4[1], bh4[3]);
                    }
                }
                __half* Rp = Rh + rnew / 2;
                #pragma unroll
                for (int j = 0; j < 8; j++) {
                    *reinterpret_cast<uint32_t*>(Rp + (wg*16 + gid)     * LDRH + j*8 + qc) =
                        pack2h(c[j][0], c[j][1]);
                    *reinterpret_cast<uint32_t*>(Rp + (wg*16 + gid + 8) * LDRH + j*8 + qc) =
                        pack2h(c[j][2], c[j][3]);
                }
                __syncwarp();
            }

            #pragma unroll
            for (int j = 0; j < 8; j++)
                #pragma unroll
                for (int z = 0; z < 4; z++) c[j][z] = 0.f;
            #pragma unroll
            for (int ks = 0; ks < 4; ks++) {
                #pragma unroll
                for (int ng = 0; ng < 4; ng++) {
                    uint32_t bh4[4];
                    uint32_t boff = (uint32_t)((ng * 16 + lr) * LDT + (ks * 16 + lc) * 2);
                    ldmx4(bh4, kb + SB_K + boff);
                    mma16816(c[2*ng],   q4[ks], bh4[0], bh4[2]);
                    mma16816(c[2*ng+1], q4[ks], bh4[1], bh4[3]);
                }
            }

            {
                const __half* Rp = Rh + rprev / 2;
                const __half* Rn = Rh + rnew / 2;
                #pragma unroll
                for (int rr = 0; rr < 2; rr++) {
                    int tl = wg*16 + gid + rr*8;
                    #pragma unroll
                    for (int j = 0; j < 8; j++) {
                        #pragma unroll
                        for (int z = 0; z < 2; z++) {
                            int sl = j*8 + qc + z;
                            int jj = sl - tl + 63;
                            if (jj < 64) c[j][rr*2 + z] += __half2float(Rp[tl * LDRH + jj]);
                            else if (hasR) c[j][rr*2 + z] += __half2float(Rn[tl * LDRH + jj - 64]);
                        }
                    }
                }
            }

            if (tq == 0 && s0 == 0 && wg == 0 && gid < 5) {
                int t = gid;
                #pragma unroll
                for (int z = 0; z < 2; z++) {
                    int s = qc + z;
                    if (s > t + 1 && s < 6) {
                        float bd = 0.f;
                        for (int d = 0; d < 64; d++)
                            bd += __half2float(qg[(t + 1) * Dn + d])
                                * __half2float(rg[(size_t)(s - t - 2) * Dn + d]);
                        c[0][z] += bd;
                    }
                }
            }

            #pragma unroll
            for (int rr = 0; rr < 2; rr++) {
                int t = tq + wg*16 + gid + rr*8;
                float rm = -1e30f;
                #pragma unroll
                for (int j = 0; j < 8; j++) {
                    #pragma unroll
                    for (int z = 0; z < 2; z++) {
                        int s = s0 + j*8 + qc + z;
                        float v = (s <= t || s < 6) ? c[j][rr*2+z] * kScale : -1e30f;
                        c[j][rr*2+z] = v;
                        rm = fmaxf(rm, v);
                    }
                }
                rm = fmaxf(rm, __shfl_xor_sync(0xffffffffu, rm, 1));
                rm = fmaxf(rm, __shfl_xor_sync(0xffffffffu, rm, 2));
                float mnew = fmaxf(mrow[rr], rm);
                float alpha = __expf(mrow[rr] - mnew);
                mrow[rr] = mnew;
                float rs = 0.f;
                #pragma unroll
                for (int j = 0; j < 8; j++) {
                    #pragma unroll
                    for (int z = 0; z < 2; z++) {
                        float p = __expf(c[j][rr*2+z] - mnew);
                        c[j][rr*2+z] = p;
                        rs += p;
                    }
                }
                rs += __shfl_xor_sync(0xffffffffu, rs, 1);
                rs += __shfl_xor_sync(0xffffffffu, rs, 2);
                lrow[rr] = lrow[rr] * alpha + rs;
                #pragma unroll
                for (int j = 0; j < 8; j++) {
                    o[j][rr*2]   *= alpha;
                    o[j][rr*2+1] *= alpha;
                }
            }

            #pragma unroll
            for (int kc = 0; kc < 4; kc++) {
                uint32_t p_hi[4], p_lo[4];
                split2h(c[2*kc][0],   c[2*kc][1],   p_hi[0], p_lo[0]);
                split2h(c[2*kc][2],   c[2*kc][3],   p_hi[1], p_lo[1]);
                split2h(c[2*kc+1][0], c[2*kc+1][1], p_hi[2], p_lo[2]);
                split2h(c[2*kc+1][2], c[2*kc+1][3], p_hi[3], p_lo[3]);
                uint32_t vbase = (uint32_t)(kc*16 + (lane & 7) + ((lane & 16) >> 1)) * LDT;
                #pragma unroll
                for (int ng = 0; ng < 4; ng++) {
                    uint32_t bv4[4];
                    uint32_t voff = vbase + (uint32_t)(ng*16 + (lane & 8)) * 2;
                    ldmx4t(bv4, kb + SB_V + voff);
                    mma16816(o[2*ng],   p_hi, bv4[0], bv4[2]);
                    mma16816(o[2*ng],   p_lo, bv4[0], bv4[2]);
                    mma16816(o[2*ng+1], p_hi, bv4[1], bv4[3]);
                    mma16816(o[2*ng+1], p_lo, bv4[1], bv4[3]);
                }
            }

            if (hasR) { int tp = rprev; rprev = rnew; rnew = tp; }
        }
        __syncthreads();
    }

    #pragma unroll
    for (int rr = 0; rr < 2; rr++) {
        int t = tq + wg*16 + gid + rr*8;
        float inv = 1.0f / lrow[rr];
        size_t base = ((size_t)b * Tn + t) * Cn + h * Dn;
        #pragma unroll
        for (int j = 0; j < 8; j++)
            *reinterpret_cast<uint32_t*>(g_att + base + j*8 + qc) =
                pack2h(o[j][rr*2] * inv, o[j][rr*2+1] * inv);
    }
}

// ---------------------------------------------------------------------------
extern "C" void kernel_launch(void* const* d_in, const int* in_sizes, int n_in,
                              void* d_out, int out_size)
{
    const float* x   = (const float*)d_in[0];
    const float* Wq  = (const float*)d_in[1];
    const float* Wk  = (const float*)d_in[2];
    const float* Wv  = (const float*)d_in[3];
    const float* rel = (const float*)d_in[4];
    const float* Wp  = (const float*)d_in[5];
    const float* bp  = (const float*)d_in[6];
    float* out = (float*)d_out;

    static __half *h_xh, *h_relh;
    static bool init = false;
    if (!init) {
        cudaGetSymbolAddress((void**)&h_xh, g_xh);
        cudaGetSymbolAddress((void**)&h_relh, g_relh);
        cudaFuncSetAttribute(qkv_mm,  cudaFuncAttributeMaxDynamicSharedMemorySize, GEMM_SMEM);
        cudaFuncSetAttribute(proj_mm, cudaFuncAttributeMaxDynamicSharedMemorySize, GEMM_SMEM);
        cudaFuncSetAttribute(attn_mm, cudaFuncAttributeMaxDynamicSharedMemorySize, ATT_SMEM);
        init = true;
    }

    conv_f16_2<<<(NX/4 + NR/4 + 255)/256, 256>>>(x, h_xh, NX/4, rel, h_relh, NR/4);
    conv_tr3<<<dim3((Cn*Dn + 255)/256, Hn, 3), 256>>>(Wq, Wk, Wv);
    split_trp<<<(Cn*Cn + 255)/256, 256>>>(Wp);

    qkv_mm<<<dim3(64, 16), 256, GEMM_SMEM>>>();
    attn_mm<<<dim3(Bn * Hn, Tn / 128), 256, ATT_SMEM>>>();
    proj_mm<<<dim3(64, 8), 256, GEMM_SMEM>>>(bp, out);
}

// round 15
// speedup vs baseline: 1.8776x; 1.0126x over previous
#include <cuda_runtime.h>
#include <cuda_fp16.h>
#include <cstdint>

// Problem constants
#define Bn 4
#define Tn 2048
#define Cn 512
#define Hn 8
#define Dn 64
__device__ __constant__ float kScale = 0.04419417382415922f; // 512^-0.5

// ---------------------------------------------------------------------------
// Global scratch (fp16)
// ---------------------------------------------------------------------------
#define NX  (Bn*Tn*Cn)
#define NW  (Hn*Cn*Dn)
#define NR  (Hn*Tn*Dn)
#define NP  (Cn*Cn)
#define NQ  (Bn*Hn*Tn*Dn)

__device__ __align__(16) __half g_xh[NX];
__device__ __align__(16) __half g_wth[3*NW];         // [mat][h][d][k]
__device__ __align__(16) __half g_relh[NR];
__device__ __align__(16) __half g_wpth[NP], g_wptl[NP];
__device__ __align__(16) __half g_q[NQ], g_k[NQ], g_v[NQ];
__device__ __align__(16) __half g_att[NX];

// ---------------------------------------------------------------------------
// helpers
// ---------------------------------------------------------------------------
__device__ __forceinline__ uint32_t smem_u32(const void* p) {
    uint32_t a;
    asm("{ .reg .u64 t; cvta.to.shared.u64 t, %1; cvt.u32.u64 %0, t; }"
        : "=r"(a) : "l"(p));
    return a;
}

__device__ __forceinline__ void ldmx4(uint32_t* r, uint32_t addr) {
    asm volatile("ldmatrix.sync.aligned.m8n8.x4.shared.b16 {%0,%1,%2,%3}, [%4];"
                 : "=r"(r[0]), "=r"(r[1]), "=r"(r[2]), "=r"(r[3]) : "r"(addr));
}
__device__ __forceinline__ void ldmx4t(uint32_t* r, uint32_t addr) {
    asm volatile("ldmatrix.sync.aligned.m8n8.x4.trans.shared.b16 {%0,%1,%2,%3}, [%4];"
                 : "=r"(r[0]), "=r"(r[1]), "=r"(r[2]), "=r"(r[3]) : "r"(addr));
}

__device__ __forceinline__ void mma16816(float* c, const uint32_t* a,
                                         uint32_t b0, uint32_t b1) {
    asm volatile(
        "mma.sync.aligned.m16n8k16.row.col.f32.f16.f16.f32 "
        "{%0,%1,%2,%3}, {%4,%5,%6,%7}, {%8,%9}, {%0,%1,%2,%3};"
        : "+f"(c[0]), "+f"(c[1]), "+f"(c[2]), "+f"(c[3])
        : "r"(a[0]), "r"(a[1]), "r"(a[2]), "r"(a[3]), "r"(b0), "r"(b1));
}

__device__ __forceinline__ uint32_t pack2h(float x0, float x1) {
    __half h0 = __float2half_rn(x0), h1 = __float2half_rn(x1);
    return (uint32_t)__half_as_ushort(h0) | ((uint32_t)__half_as_ushort(h1) << 16);
}

__device__ __forceinline__ void split2h(float x0, float x1, uint32_t& hi2, uint32_t& lo2) {
    __half h0 = __float2half_rn(x0), h1 = __float2half_rn(x1);
    float l0 = x0 - __half2float(h0), l1 = x1 - __half2float(h1);
    hi2 = (uint32_t)__half_as_ushort(h0) | ((uint32_t)__half_as_ushort(h1) << 16);
    lo2 = (uint32_t)__half_as_ushort(__float2half_rn(l0))
        | ((uint32_t)__half_as_ushort(__float2half_rn(l1)) << 16);
}

__device__ __forceinline__ void cpa16(uint32_t dst, const void* src) {
    asm volatile("cp.async.cg.shared.global [%0], [%1], 16;" :: "r"(dst), "l"(src));
}
__device__ __forceinline__ void cpa_wait_all() {
    asm volatile("cp.async.wait_all;" ::: "memory");
}
__device__ __forceinline__ void cpa_commit() {
    asm volatile("cp.async.commit_group;" ::: "memory");
}
__device__ __forceinline__ void cpa_wait1() {
    asm volatile("cp.async.wait_group 1;" ::: "memory");
}

// fp16 smem rows: 64 elems = 128B, padded to 144B (9 x 16B phases -> conflict-free)
#define LDT 144

// ---------------------------------------------------------------------------
// Pre-convert kernels
// ---------------------------------------------------------------------------
// Merged x + rel conversion: flattened float4 index over [x | rel].
__global__ void conv_f16_2(const float* __restrict__ sa, __half* __restrict__ da,
                           int n4a,
                           const float* __restrict__ sb, __half* __restrict__ db,
                           int n4b)
{
    int i = blockIdx.x * blockDim.x + threadIdx.x;
    const float* s;
    __half* d;
    if (i < n4a) { s = sa; d = da; }
    else         { i -= n4a; if (i >= n4b) return; s = sb; d = db; }
    float4 v = reinterpret_cast<const float4*>(s)[i];
    reinterpret_cast<uint2*>(d)[i] = make_uint2(pack2h(v.x, v.y), pack2h(v.z, v.w));
}

// Merged weight converter: z<3 -> transposed convert of Wq/Wk/Wv (y = head);
// z==3 -> transposed hi/lo split of Wp. grid (128, 8, 4) x 256 threads.
__global__ void conv_w(const float* __restrict__ Wq,
                       const float* __restrict__ Wk,
                       const float* __restrict__ Wv,
                       const float* __restrict__ Wp)
{
    int z = blockIdx.z;
    if (z < 3) {
        int hh = blockIdx.y;
        int i = blockIdx.x * blockDim.x + threadIdx.x;
        if (i >= Cn * Dn) return;
        const float* src = (z == 0 ? Wq : (z == 1 ? Wk : Wv));
        int r = i / Dn, cc = i % Dn;
        float w = src[(size_t)hh * Cn * Dn + i];
        g_wth[(size_t)(z * Hn + hh) * Cn * Dn + (size_t)cc * Cn + r] = __float2half_rn(w);
    } else {
        int i = (blockIdx.y * gridDim.x + blockIdx.x) * blockDim.x + threadIdx.x;
        if (i >= Cn * Cn) return;
        int r = i / Cn, cc = i % Cn;
        float w = Wp[i];
        __half hb = __float2half_rn(w);
        size_t o = (size_t)cc * Cn + r;
        g_wpth[o] = hb;
        g_wptl[o] = __float2half_rn(w - __half2float(hb));
    }
}

// ---------------------------------------------------------------------------
// Kernel 1: QKV projection, single fp16, 2-stage pipeline, 4m x 2n warp tiling.
// grid = (64 m-tiles of 128, 16): y<8 -> fused q+k head y; y>=8 -> v head y-8.
// Each warp: 32x32 output tile per matrix. stage 36864 x2 -> 3 CTAs/SM.
// ---------------------------------------------------------------------------
#define GST(s) ((s) * 36864)
#define G_A  0
#define G_B0 18432
#define G_B1 27648
#define GEMM_SMEM 73728

__global__ __launch_bounds__(256) void qkv_mm()
{
    extern __shared__ char smc[];
    const uint32_t smb = smem_u32(smc);
    const int tid = threadIdx.x;
    const int wm  = tid >> 5;
    const int lane = tid & 31;
    const int mw = wm >> 1;          // 0..3: m-subtile of 32 rows
    const int nw = wm & 1;           // 0..1: n-subtile of 32 cols
    const int lr = lane & 15;
    const int lc = (lane >> 4) << 3;

    const int m0   = blockIdx.x * 128;
    const bool isqk = blockIdx.y < 8;
    const int h    = blockIdx.y & 7;
    const __half* W0 = g_wth + (size_t)(isqk ? h : 16 + h) * Cn * Dn;
    const __half* W1 = g_wth + (size_t)(8 + h) * Cn * Dn;

    float c0[2][4][4] = {};
    float c1[2][4][4] = {};

    // prologue: load kb=0 into stage 0, committed as its OWN group
    {
        const uint32_t st = smb + GST(0);
        #pragma unroll
        for (int i = 0; i < 4; i++) {
            int u = tid + i * 256;
            int row = u >> 3, g = u & 7;
            cpa16(st + G_A + (uint32_t)(row * LDT + g * 16),
                  g_xh + (size_t)(m0 + row) * Cn + g * 8);
        }
        #pragma unroll
        for (int i = 0; i < 2; i++) {
            int u = tid + i * 256;
            int d = u >> 3, g = u & 7;
            uint32_t dst = (uint32_t)(d * LDT + g * 16);
            size_t src = (size_t)d * Cn + g * 8;
            cpa16(st + G_B0 + dst, W0 + src);
            if (isqk) cpa16(st + G_B1 + dst, W1 + src);
        }
        cpa_commit();
    }

    for (int kb = 0; kb < 8; kb++) {
        if (kb + 1 < 8) {
            const int c1k = (kb + 1) * 64;
            const uint32_t st = smb + GST((kb + 1) & 1);
            #pragma unroll
            for (int i = 0; i < 4; i++) {
                int u = tid + i * 256;
                int row = u >> 3, g = u & 7;
                cpa16(st + G_A + (uint32_t)(row * LDT + g * 16),
                      g_xh + (size_t)(m0 + row) * Cn + c1k + g * 8);
            }
            #pragma unroll
            for (int i = 0; i < 2; i++) {
                int u = tid + i * 256;
                int d = u >> 3, g = u & 7;
                uint32_t dst = (uint32_t)(d * LDT + g * 16);
                size_t src = (size_t)d * Cn + c1k + g * 8;
                cpa16(st + G_B0 + dst, W0 + src);
                if (isqk) cpa16(st + G_B1 + dst, W1 + src);
            }
        }
        cpa_commit();
        cpa_wait1();
        __syncthreads();

        const uint32_t st = smb + GST(kb & 1);
        #pragma unroll
        for (int ks = 0; ks < 4; ks++) {
            const int k0 = ks * 16;
            uint32_t a4[2][4];
            #pragma unroll
            for (int f = 0; f < 2; f++)
                ldmx4(a4[f], st + G_A +
                      (uint32_t)((mw * 32 + f * 16 + lr) * LDT + (k0 + lc) * 2));
            #pragma unroll
            for (int g = 0; g < 2; g++) {
                uint32_t boff = (uint32_t)((nw * 32 + g * 16 + lr) * LDT + (k0 + lc) * 2);
                uint32_t b4[4];
                ldmx4(b4, st + G_B0 + boff);
                #pragma unroll
                for (int f = 0; f < 2; f++) {
                    mma16816(c0[f][g*2],   a4[f], b4[0], b4[2]);
                    mma16816(c0[f][g*2+1], a4[f], b4[1], b4[3]);
                }
                if (isqk) {
                    uint32_t bk[4];
                    ldmx4(bk, st + G_B1 + boff);
                    #pragma unroll
                    for (int f = 0; f < 2; f++) {
                        mma16816(c1[f][g*2],   a4[f], bk[0], bk[2]);
                        mma16816(c1[f][g*2+1], a4[f], bk[1], bk[3]);
                    }
                }
            }
        }
        __syncthreads();
    }

    const int gid = lane >> 2, qc = (lane & 3) * 2;
    #pragma unroll
    for (int f = 0; f < 2; f++) {
        #pragma unroll
        for (int rr = 0; rr < 2; rr++) {
            int m = m0 + mw * 32 + f * 16 + gid + rr * 8;
            int b = m >> 11, t = m & 2047;
            size_t base = (((size_t)(b * Hn + h)) * Tn + t) * Dn + nw * 32;
            if (isqk) {
                #pragma unroll
                for (int j = 0; j < 4; j++) {
                    *reinterpret_cast<uint32_t*>(g_q + base + j * 8 + qc) =
                        pack2h(c0[f][j][rr*2], c0[f][j][rr*2 + 1]);
                    *reinterpret_cast<uint32_t*>(g_k + base + j * 8 + qc) =
                        pack2h(c1[f][j][rr*2], c1[f][j][rr*2 + 1]);
                }
            } else {
                #pragma unroll
                for (int j = 0; j < 4; j++)
                    *reinterpret_cast<uint32_t*>(g_v + base + j * 8 + qc) =
                        pack2h(c0[f][j][rr*2], c0[f][j][rr*2 + 1]);
            }
        }
    }
}

// ---------------------------------------------------------------------------
// Kernel 3: output projection + bias, 2-stage pipeline, 4m x 2n warp tiling.
// grid = (64, 8). att single fp16; Wp split (2-MMA). 73728 B -> 3 CTAs/SM.
// ---------------------------------------------------------------------------
__global__ __launch_bounds__(256) void proj_mm(
    const float* __restrict__ bp, float* __restrict__ outp)
{
    extern __shared__ char smc[];
    const uint32_t smb = smem_u32(smc);
    const int tid = threadIdx.x;
    const int wm  = tid >> 5;
    const int lane = tid & 31;
    const int mw = wm >> 1;
    const int nw = wm & 1;
    const int lr = lane & 15;
    const int lc = (lane >> 4) << 3;

    const int m0 = blockIdx.x * 128;
    const int n0 = blockIdx.y * 64;

    float c[2][4][4] = {};

    // prologue: kb=0 -> stage 0, own group
    {
        const uint32_t st = smb + GST(0);
        #pragma unroll
        for (int i = 0; i < 4; i++) {
            int u = tid + i * 256;
            int row = u >> 3, g = u & 7;
            cpa16(st + G_A + (uint32_t)(row * LDT + g * 16),
                  g_att + (size_t)(m0 + row) * Cn + g * 8);
        }
        #pragma unroll
        for (int i = 0; i < 2; i++) {
            int u = tid + i * 256;
            int d = u >> 3, g = u & 7;
            uint32_t dst = (uint32_t)(d * LDT + g * 16);
            size_t src = (size_t)(n0 + d) * Cn + g * 8;
            cpa16(st + G_B0 + dst, g_wpth + src);
            cpa16(st + G_B1 + dst, g_wptl + src);
        }
        cpa_commit();
    }

    for (int kb = 0; kb < 8; kb++) {
        if (kb + 1 < 8) {
            const int c1k = (kb + 1) * 64;
            const uint32_t st = smb + GST((kb + 1) & 1);
            #pragma unroll
            for (int i = 0; i < 4; i++) {
                int u = tid + i * 256;
                int row = u >> 3, g = u & 7;
                cpa16(st + G_A + (uint32_t)(row * LDT + g * 16),
                      g_att + (size_t)(m0 + row) * Cn + c1k + g * 8);
            }
            #pragma unroll
            for (int i = 0; i < 2; i++) {
                int u = tid + i * 256;
                int d = u >> 3, g = u & 7;
                uint32_t dst = (uint32_t)(d * LDT + g * 16);
                size_t src = (size_t)(n0 + d) * Cn + c1k + g * 8;
                cpa16(st + G_B0 + dst, g_wpth + src);
                cpa16(st + G_B1 + dst, g_wptl + src);
            }
        }
        cpa_commit();
        cpa_wait1();
        __syncthreads();

        const uint32_t st = smb + GST(kb & 1);
        #pragma unroll
        for (int ks = 0; ks < 4; ks++) {
            const int k0 = ks * 16;
            uint32_t a4[2][4];
            #pragma unroll
            for (int f = 0; f < 2; f++)
                ldmx4(a4[f], st + G_A +
                      (uint32_t)((mw * 32 + f * 16 + lr) * LDT + (k0 + lc) * 2));
            #pragma unroll
            for (int g = 0; g < 2; g++) {
                uint32_t boff = (uint32_t)((nw * 32 + g * 16 + lr) * LDT + (k0 + lc) * 2);
                uint32_t bh[4], bl[4];
                ldmx4(bh, st + G_B0 + boff);
                ldmx4(bl, st + G_B1 + boff);
                #pragma unroll
                for (int f = 0; f < 2; f++) {
                    mma16816(c[f][g*2],   a4[f], bh[0], bh[2]);
                    mma16816(c[f][g*2],   a4[f], bl[0], bl[2]);
                    mma16816(c[f][g*2+1], a4[f], bh[1], bh[3]);
                    mma16816(c[f][g*2+1], a4[f], bl[1], bl[3]);
                }
            }
        }
        __syncthreads();
    }

    const int gid = lane >> 2, qc = (lane & 3) * 2;
    #pragma unroll
    for (int f = 0; f < 2; f++) {
        #pragma unroll
        for (int rr = 0; rr < 2; rr++) {
            int m = m0 + mw * 32 + f * 16 + gid + rr * 8;
            float* op = outp + (size_t)m * Cn + n0 + nw * 32;
            #pragma unroll
            for (int j = 0; j < 4; j++) {
                float2 bv = *reinterpret_cast<const float2*>(
                    bp + n0 + nw * 32 + j * 8 + qc);
                *reinterpret_cast<float2*>(op + j * 8 + qc) =
                    make_float2(c[f][j][rr*2] + bv.x, c[f][j][rr*2 + 1] + bv.y);
            }
        }
    }
}

// ---------------------------------------------------------------------------
// Kernel 2: flash attention, TWO query blocks per CTA. (unchanged from R11)
// smem = 36864 (KV x2) + 27648 (W ring) + 33792 (R x4) = 98304 -> 2 CTAs/SM.
// ---------------------------------------------------------------------------
#define SBUF(s)   ((s) * 18432)             // K +0, V +9216
#define SB_K      0
#define SB_V      9216
#define W_SLOT(w) (36864 + (w) * 9216)
#define R_BASE    64512                     // 4 x 8448; also Q staging alias
#define ATT_SMEM  98304
#define LDRH 66

__global__ __launch_bounds__(256, 2) void attn_mm()
{
    extern __shared__ char smc[];
    const uint32_t smb = smem_u32(smc);
    __half* Rh = reinterpret_cast<__half*>(smc);

    const int tid = threadIdx.x;
    const int wm  = tid >> 5;
    const int lane = tid & 31;
    const int grp = wm >> 2;               // 0: rows t0, 1: rows t0+64
    const int wg  = wm & 3;
    const int lr = lane & 15;
    const int lc = (lane >> 4) << 3;
    const int gid = lane >> 2, qc = (lane & 3) * 2;

    const int bh = blockIdx.x;
    const int h  = bh & (Hn - 1);
    const int b  = bh >> 3;
    const int t0 = (int)(gridDim.y - 1 - blockIdx.y) * 128;
    const int tq = t0 + 64 * grp;
    const int ntiles = t0 / 64 + 2;

    const __half* qg = g_q + (size_t)bh * Tn * Dn;
    const __half* kg = g_k + (size_t)bh * Tn * Dn;
    const __half* vg = g_v + (size_t)bh * Tn * Dn;
    const __half* rg = g_relh + (size_t)h * Tn * Dn;

    const int jm1 = Tn - 128 - t0;   // >= 0; W'A_j rows = jm1 + 64(j+1)

    // ---- prologue
    #pragma unroll
    for (int i = 0; i < 4; i++) {
        int u = tid + i * 256;
        int row = u >> 3, g = u & 7;
        cpa16(smb + R_BASE + (uint32_t)(row * LDT + g * 16),
              qg + (size_t)(t0 + row) * Dn + g * 8);
    }
    #pragma unroll
    for (int i = 0; i < 2; i++) {
        int u = tid + i * 256;
        int row = u >> 3, g = u & 7;
        uint32_t dst = (uint32_t)(row * LDT + g * 16);
        cpa16(smb + W_SLOT(2) + dst, rg + (size_t)(jm1 + row) * Dn + g * 8);
        cpa16(smb + W_SLOT(0) + dst, rg + (size_t)(jm1 + 64 + row) * Dn + g * 8);
        if (t0 >= 64)
            cpa16(smb + W_SLOT(1) + dst, rg + (size_t)(jm1 + 128 + row) * Dn + g * 8);
        size_t s = (size_t)row * Dn + g * 8;
        cpa16(smb + SBUF(0) + SB_K + dst, kg + s);
        cpa16(smb + SBUF(0) + SB_V + dst, vg + s);
    }
    cpa_wait_all();
    __syncthreads();

    uint32_t q4[4][4];
    #pragma unroll
    for (int ks = 0; ks < 4; ks++) {
        uint32_t aoff = (uint32_t)((grp * 64 + wg * 16 + lr) * LDT + (ks * 16 + lc) * 2);
        ldmx4(q4[ks], smb + R_BASE + aoff);
    }
    __syncthreads();   // Q staging consumed; R region may be written now

    int rprev = R_BASE + grp * 16896;
    int rnew  = rprev + 8448;
    {
        const uint32_t wb = smb + (grp ? W_SLOT(2) : W_SLOT(0));
        float c[8][4] = {};
        #pragma unroll
        for (int ks = 0; ks < 4; ks++) {
            #pragma unroll
            for (int ng = 0; ng < 4; ng++) {
                uint32_t bh4[4];
                uint32_t boff = (uint32_t)((ng * 16 + lr) * LDT + (ks * 16 + lc) * 2);
                ldmx4(bh4, wb + boff);
                mma16816(c[2*ng],   q4[ks], bh4[0], bh4[2]);
                mma16816(c[2*ng+1], q4[ks], bh4[1], bh4[3]);
            }
        }
        __half* Rp = Rh + rprev / 2;
        #pragma unroll
        for (int j = 0; j < 8; j++) {
            *reinterpret_cast<uint32_t*>(Rp + (wg*16 + gid)     * LDRH + j*8 + qc) =
                pack2h(c[j][0], c[j][1]);
            *reinterpret_cast<uint32_t*>(Rp + (wg*16 + gid + 8) * LDRH + j*8 + qc) =
                pack2h(c[j][2], c[j][3]);
        }
        __syncwarp();
    }
    __syncthreads();   // slot2 consumed before tile-0 prefetch may overwrite it

    float o[8][4] = {};
    float mrow[2] = {-1e30f, -1e30f};
    float lrow[2] = {};

    for (int i = 0; i < ntiles; i++) {
        const int s0 = i * 64;

        if (i + 1 < ntiles) {
            const int s1 = s0 + 64;
            const uint32_t nb = smb + SBUF((i + 1) & 1);
            const bool needW = (64 * (i + 2) <= t0);
            #pragma unroll
            for (int u2 = 0; u2 < 2; u2++) {
                int u = tid + u2 * 256;
                int row = u >> 3, g = u & 7;
                uint32_t dst = (uint32_t)(row * LDT + g * 16);
                size_t s = (size_t)(s1 + row) * Dn + g * 8;
                cpa16(nb + SB_K + dst, kg + s);
                cpa16(nb + SB_V + dst, vg + s);
                if (needW)
                    cpa16(smb + W_SLOT((i + 2) % 3) + dst,
                          rg + (size_t)(jm1 + 64 * (i + 3) + row) * Dn + g * 8);
            }
        }
        cpa_commit();
        cpa_wait1();
        __syncthreads();

        const uint32_t kb = smb + SBUF(i & 1);
        const bool act  = (s0 <= tq);
        const bool hasR = (s0 < tq);

        if (act) {
            float c[8][4];

            if (hasR) {
                const uint32_t wb = smb + W_SLOT((i + 1 - grp) % 3);
                #pragma unroll
                for (int j = 0; j < 8; j++)
                    #pragma unroll
                    for (int z = 0; z < 4; z++) c[j][z] = 0.f;
                #pragma unroll
                for (int ks = 0; ks < 4; ks++) {
                    #pragma unroll
                    for (int ng = 0; ng < 4; ng++) {
                        uint32_t bh4[4];
                        uint32_t boff = (uint32_t)((ng * 16 + lr) * LDT + (ks * 16 + lc) * 2);
                        ldmx4(bh4, wb + boff);
                        mma16816(c[2*ng],   q4[ks], bh4[0], bh4[2]);
                        mma16816(c[2*ng+1], q4[ks], bh4[1], bh4[3]);
                    }
                }
                __half* Rp = Rh + rnew / 2;
                #pragma unroll
                for (int j = 0; j < 8; j++) {
                    *reinterpret_cast<uint32_t*>(Rp + (wg*16 + gid)     * LDRH + j*8 + qc) =
                        pack2h(c[j][0], c[j][1]);
                    *reinterpret_cast<uint32_t*>(Rp + (wg*16 + gid + 8) * LDRH + j*8 + qc) =
                        pack2h(c[j][2], c[j][3]);
                }
                __syncwarp();
            }

            #pragma unroll
            for (int j = 0; j < 8; j++)
                #pragma unroll
                for (int z = 0; z < 4; z++) c[j][z] = 0.f;
            #pragma unroll
            for (int ks = 0; ks < 4; ks++) {
                #pragma unroll
                for (int ng = 0; ng < 4; ng++) {
                    uint32_t bh4[4];
                    uint32_t boff = (uint32_t)((ng * 16 + lr) * LDT + (ks * 16 + lc) * 2);
                    ldmx4(bh4, kb + SB_K + boff);
                    mma16816(c[2*ng],   q4[ks], bh4[0], bh4[2]);
                    mma16816(c[2*ng+1], q4[ks], bh4[1], bh4[3]);
                }
            }

            {
                const __half* Rp = Rh + rprev / 2;
                const __half* Rn = Rh + rnew / 2;
                #pragma unroll
                for (int rr = 0; rr < 2; rr++) {
                    int tl = wg*16 + gid + rr*8;
                    #pragma unroll
                    for (int j = 0; j < 8; j++) {
                        #pragma unroll
                        for (int z = 0; z < 2; z++) {
                            int sl = j*8 + qc + z;
                            int jj = sl - tl + 63;
                            if (jj < 64) c[j][rr*2 + z] += __half2float(Rp[tl * LDRH + jj]);
                            else if (hasR) c[j][rr*2 + z] += __half2float(Rn[tl * LDRH + jj - 64]);
                        }
                    }
                }
            }

            if (tq == 0 && s0 == 0 && wg == 0 && gid < 5) {
                int t = gid;
                #pragma unroll
                for (int z = 0; z < 2; z++) {
                    int s = qc + z;
                    if (s > t + 1 && s < 6) {
                        float bd = 0.f;
                        for (int d = 0; d < 64; d++)
                            bd += __half2float(qg[(t + 1) * Dn + d])
                                * __half2float(rg[(size_t)(s - t - 2) * Dn + d]);
                        c[0][z] += bd;
                    }
                }
            }

            #pragma unroll
            for (int rr = 0; rr < 2; rr++) {
                int t = tq + wg*16 + gid + rr*8;
                float rm = -1e30f;
                #pragma unroll
                for (int j = 0; j < 8; j++) {
                    #pragma unroll
                    for (int z = 0; z < 2; z++) {
                        int s = s0 + j*8 + qc + z;
                        float v = (s <= t || s < 6) ? c[j][rr*2+z] * kScale : -1e30f;
                        c[j][rr*2+z] = v;
                        rm = fmaxf(rm, v);
                    }
                }
                rm = fmaxf(rm, __shfl_xor_sync(0xffffffffu, rm, 1));
                rm = fmaxf(rm, __shfl_xor_sync(0xffffffffu, rm, 2));
                float mnew = fmaxf(mrow[rr], rm);
                float alpha = __expf(mrow[rr] - mnew);
                mrow[rr] = mnew;
                float rs = 0.f;
                #pragma unroll
                for (int j = 0; j < 8; j++) {
                    #pragma unroll
                    for (int z = 0; z < 2; z++) {
                        float p = __expf(c[j][rr*2+z] - mnew);
                        c[j][rr*2+z] = p;
                        rs += p;
                    }
                }
                rs += __shfl_xor_sync(0xffffffffu, rs, 1);
                rs += __shfl_xor_sync(0xffffffffu, rs, 2);
                lrow[rr] = lrow[rr] * alpha + rs;
                #pragma unroll
                for (int j = 0; j < 8; j++) {
                    o[j][rr*2]   *= alpha;
                    o[j][rr*2+1] *= alpha;
                }
            }

            #pragma unroll
            for (int kc = 0; kc < 4; kc++) {
                uint32_t p_hi[4], p_lo[4];
                split2h(c[2*kc][0],   c[2*kc][1],   p_hi[0], p_lo[0]);
                split2h(c[2*kc][2],   c[2*kc][3],   p_hi[1], p_lo[1]);
                split2h(c[2*kc+1][0], c[2*kc+1][1], p_hi[2], p_lo[2]);
                split2h(c[2*kc+1][2], c[2*kc+1][3], p_hi[3], p_lo[3]);
                uint32_t vbase = (uint32_t)(kc*16 + (lane & 7) + ((lane & 16) >> 1)) * LDT;
                #pragma unroll
                for (int ng = 0; ng < 4; ng++) {
                    uint32_t bv4[4];
                    uint32_t voff = vbase + (uint32_t)(ng*16 + (lane & 8)) * 2;
                    ldmx4t(bv4, kb + SB_V + voff);
                    mma16816(o[2*ng],   p_hi, bv4[0], bv4[2]);
                    mma16816(o[2*ng],   p_lo, bv4[0], bv4[2]);
                    mma16816(o[2*ng+1], p_hi, bv4[1], bv4[3]);
                    mma16816(o[2*ng+1], p_lo, bv4[1], bv4[3]);
                }
            }

            if (hasR) { int tp = rprev; rprev = rnew; rnew = tp; }
        }
        __syncthreads();
    }

    #pragma unroll
    for (int rr = 0; rr < 2; rr++) {
        int t = tq + wg*16 + gid + rr*8;
        float inv = 1.0f / lrow[rr];
        size_t base = ((size_t)b * Tn + t) * Cn + h * Dn;
        #pragma unroll
        for (int j = 0; j < 8; j++)
            *reinterpret_cast<uint32_t*>(g_att + base + j*8 + qc) =
                pack2h(o[j][rr*2] * inv, o[j][rr*2+1] * inv);
    }
}

// ---------------------------------------------------------------------------
extern "C" void kernel_launch(void* const* d_in, const int* in_sizes, int n_in,
                              void* d_out, int out_size)
{
    const float* x   = (const float*)d_in[0];
    const float* Wq  = (const float*)d_in[1];
    const float* Wk  = (const float*)d_in[2];
    const float* Wv  = (const float*)d_in[3];
    const float* rel = (const float*)d_in[4];
    const float* Wp  = (const float*)d_in[5];
    const float* bp  = (const float*)d_in[6];
    float* out = (float*)d_out;

    static __half *h_xh, *h_relh;
    static bool init = false;
    if (!init) {
        cudaGetSymbolAddress((void**)&h_xh, g_xh);
        cudaGetSymbolAddress((void**)&h_relh, g_relh);
        cudaFuncSetAttribute(qkv_mm,  cudaFuncAttributeMaxDynamicSharedMemorySize, GEMM_SMEM);
        cudaFuncSetAttribute(proj_mm, cudaFuncAttributeMaxDynamicSharedMemorySize, GEMM_SMEM);
        cudaFuncSetAttribute(attn_mm, cudaFuncAttributeMaxDynamicSharedMemorySize, ATT_SMEM);
        init = true;
    }

    conv_f16_2<<<(NX/4 + NR/4 + 255)/256, 256>>>(x, h_xh, NX/4, rel, h_relh, NR/4);
    conv_w<<<dim3(128, 8, 4), 256>>>(Wq, Wk, Wv, Wp);

    qkv_mm<<<dim3(64, 16), 256, GEMM_SMEM>>>();
    attn_mm<<<dim3(Bn * Hn, Tn / 128), 256, ATT_SMEM>>>();
    proj_mm<<<dim3(64, 8), 256, GEMM_SMEM>>>(bp, out);
}

// round 17
// speedup vs baseline: 2.1572x; 1.1489x over previous
#include <cuda_runtime.h>
#include <cuda_fp16.h>
#include <cstdint>

// Problem constants
#define Bn 4
#define Tn 2048
#define Cn 512
#define Hn 8
#define Dn 64
__device__ __constant__ float kScale = 0.04419417382415922f; // 512^-0.5

// ---------------------------------------------------------------------------
// Global scratch (fp16)
// ---------------------------------------------------------------------------
#define NX  (Bn*Tn*Cn)
#define NW  (Hn*Cn*Dn)
#define NR  (Hn*Tn*Dn)
#define NP  (Cn*Cn)
#define NQ  (Bn*Hn*Tn*Dn)

__device__ __align__(16) __half g_xh[NX];
__device__ __align__(16) __half g_wth[3*NW];         // [mat][h][d][k]
__device__ __align__(16) __half g_relh[NR];
__device__ __align__(16) __half g_wpth[NP], g_wptl[NP];
__device__ __align__(16) __half g_q[NQ], g_k[NQ], g_v[NQ];   // q pre-scaled by kScale
__device__ __align__(16) __half g_att[NX];

// ---------------------------------------------------------------------------
// helpers
// ---------------------------------------------------------------------------
__device__ __forceinline__ uint32_t smem_u32(const void* p) {
    uint32_t a;
    asm("{ .reg .u64 t; cvta.to.shared.u64 t, %1; cvt.u32.u64 %0, t; }"
        : "=r"(a) : "l"(p));
    return a;
}

__device__ __forceinline__ void ldmx4(uint32_t* r, uint32_t addr) {
    asm volatile("ldmatrix.sync.aligned.m8n8.x4.shared.b16 {%0,%1,%2,%3}, [%4];"
                 : "=r"(r[0]), "=r"(r[1]), "=r"(r[2]), "=r"(r[3]) : "r"(addr));
}
__device__ __forceinline__ void ldmx4t(uint32_t* r, uint32_t addr) {
    asm volatile("ldmatrix.sync.aligned.m8n8.x4.trans.shared.b16 {%0,%1,%2,%3}, [%4];"
                 : "=r"(r[0]), "=r"(r[1]), "=r"(r[2]), "=r"(r[3]) : "r"(addr));
}

__device__ __forceinline__ void mma16816(float* c, const uint32_t* a,
                                         uint32_t b0, uint32_t b1) {
    asm volatile(
        "mma.sync.aligned.m16n8k16.row.col.f32.f16.f16.f32 "
        "{%0,%1,%2,%3}, {%4,%5,%6,%7}, {%8,%9}, {%0,%1,%2,%3};"
        : "+f"(c[0]), "+f"(c[1]), "+f"(c[2]), "+f"(c[3])
        : "r"(a[0]), "r"(a[1]), "r"(a[2]), "r"(a[3]), "r"(b0), "r"(b1));
}

__device__ __forceinline__ uint32_t pack2h(float x0, float x1) {
    __half h0 = __float2half_rn(x0), h1 = __float2half_rn(x1);
    return (uint32_t)__half_as_ushort(h0) | ((uint32_t)__half_as_ushort(h1) << 16);
}

__device__ __forceinline__ void split2h(float x0, float x1, uint32_t& hi2, uint32_t& lo2) {
    __half h0 = __float2half_rn(x0), h1 = __float2half_rn(x1);
    float l0 = x0 - __half2float(h0), l1 = x1 - __half2float(h1);
    hi2 = (uint32_t)__half_as_ushort(h0) | ((uint32_t)__half_as_ushort(h1) << 16);
    lo2 = (uint32_t)__half_as_ushort(__float2half_rn(l0))
        | ((uint32_t)__half_as_ushort(__float2half_rn(l1)) << 16);
}

__device__ __forceinline__ void cpa16(uint32_t dst, const void* src) {
    asm volatile("cp.async.cg.shared.global [%0], [%1], 16;" :: "r"(dst), "l"(src));
}
__device__ __forceinline__ void cpa_wait_all() {
    asm volatile("cp.async.wait_all;" ::: "memory");
}
__device__ __forceinline__ void cpa_commit() {
    asm volatile("cp.async.commit_group;" ::: "memory");
}
__device__ __forceinline__ void cpa_wait1() {
    asm volatile("cp.async.wait_group 1;" ::: "memory");
}

// fp16 smem rows: 64 elems = 128B, padded to 144B (9 x 16B phases -> conflict-free)
#define LDT 144

// ---------------------------------------------------------------------------
// Pre-convert kernels
// ---------------------------------------------------------------------------
__global__ void conv_f16_2(const float* __restrict__ sa, __half* __restrict__ da,
                           int n4a,
                           const float* __restrict__ sb, __half* __restrict__ db,
                           int n4b)
{
    int i = blockIdx.x * blockDim.x + threadIdx.x;
    const float* s;
    __half* d;
    if (i < n4a) { s = sa; d = da; }
    else         { i -= n4a; if (i >= n4b) return; s = sb; d = db; }
    float4 v = reinterpret_cast<const float4*>(s)[i];
    reinterpret_cast<uint2*>(d)[i] = make_uint2(pack2h(v.x, v.y), pack2h(v.z, v.w));
}

__global__ void conv_w(const float* __restrict__ Wq,
                       const float* __restrict__ Wk,
                       const float* __restrict__ Wv,
                       const float* __restrict__ Wp)
{
    int z = blockIdx.z;
    if (z < 3) {
        int hh = blockIdx.y;
        int i = blockIdx.x * blockDim.x + threadIdx.x;
        if (i >= Cn * Dn) return;
        const float* src = (z == 0 ? Wq : (z == 1 ? Wk : Wv));
        int r = i / Dn, cc = i % Dn;
        float w = src[(size_t)hh * Cn * Dn + i];
        g_wth[(size_t)(z * Hn + hh) * Cn * Dn + (size_t)cc * Cn + r] = __float2half_rn(w);
    } else {
        int i = (blockIdx.y * gridDim.x + blockIdx.x) * blockDim.x + threadIdx.x;
        if (i >= Cn * Cn) return;
        int r = i / Cn, cc = i % Cn;
        float w = Wp[i];
        __half hb = __float2half_rn(w);
        size_t o = (size_t)cc * Cn + r;
        g_wpth[o] = hb;
        g_wptl[o] = __float2half_rn(w - __half2float(hb));
    }
}

// ---------------------------------------------------------------------------
// Kernel 1: QKV projection. q output pre-scaled by kScale.
// ---------------------------------------------------------------------------
#define GST(s) ((s) * 36864)
#define G_A  0
#define G_B0 18432
#define G_B1 27648
#define GEMM_SMEM 73728

__global__ __launch_bounds__(256) void qkv_mm()
{
    extern __shared__ char smc[];
    const uint32_t smb = smem_u32(smc);
    const int tid = threadIdx.x;
    const int wm  = tid >> 5;
    const int lane = tid & 31;
    const int mw = wm >> 1;
    const int nw = wm & 1;
    const int lr = lane & 15;
    const int lc = (lane >> 4) << 3;

    const int m0   = blockIdx.x * 128;
    const bool isqk = blockIdx.y < 8;
    const int h    = blockIdx.y & 7;
    const __half* W0 = g_wth + (size_t)(isqk ? h : 16 + h) * Cn * Dn;
    const __half* W1 = g_wth + (size_t)(8 + h) * Cn * Dn;

    float c0[2][4][4] = {};
    float c1[2][4][4] = {};

    {
        const uint32_t st = smb + GST(0);
        #pragma unroll
        for (int i = 0; i < 4; i++) {
            int u = tid + i * 256;
            int row = u >> 3, g = u & 7;
            cpa16(st + G_A + (uint32_t)(row * LDT + g * 16),
                  g_xh + (size_t)(m0 + row) * Cn + g * 8);
        }
        #pragma unroll
        for (int i = 0; i < 2; i++) {
            int u = tid + i * 256;
            int d = u >> 3, g = u & 7;
            uint32_t dst = (uint32_t)(d * LDT + g * 16);
            size_t src = (size_t)d * Cn + g * 8;
            cpa16(st + G_B0 + dst, W0 + src);
            if (isqk) cpa16(st + G_B1 + dst, W1 + src);
        }
        cpa_commit();
    }

    for (int kb = 0; kb < 8; kb++) {
        if (kb + 1 < 8) {
            const int c1k = (kb + 1) * 64;
            const uint32_t st = smb + GST((kb + 1) & 1);
            #pragma unroll
            for (int i = 0; i < 4; i++) {
                int u = tid + i * 256;
                int row = u >> 3, g = u & 7;
                cpa16(st + G_A + (uint32_t)(row * LDT + g * 16),
                      g_xh + (size_t)(m0 + row) * Cn + c1k + g * 8);
            }
            #pragma unroll
            for (int i = 0; i < 2; i++) {
                int u = tid + i * 256;
                int d = u >> 3, g = u & 7;
                uint32_t dst = (uint32_t)(d * LDT + g * 16);
                size_t src = (size_t)d * Cn + c1k + g * 8;
                cpa16(st + G_B0 + dst, W0 + src);
                if (isqk) cpa16(st + G_B1 + dst, W1 + src);
            }
        }
        cpa_commit();
        cpa_wait1();
        __syncthreads();

        const uint32_t st = smb + GST(kb & 1);
        #pragma unroll
        for (int ks = 0; ks < 4; ks++) {
            const int k0 = ks * 16;
            uint32_t a4[2][4];
            #pragma unroll
            for (int f = 0; f < 2; f++)
                ldmx4(a4[f], st + G_A +
                      (uint32_t)((mw * 32 + f * 16 + lr) * LDT + (k0 + lc) * 2));
            #pragma unroll
            for (int g = 0; g < 2; g++) {
                uint32_t boff = (uint32_t)((nw * 32 + g * 16 + lr) * LDT + (k0 + lc) * 2);
                uint32_t b4[4];
                ldmx4(b4, st + G_B0 + boff);
                #pragma unroll
                for (int f = 0; f < 2; f++) {
                    mma16816(c0[f][g*2],   a4[f], b4[0], b4[2]);
                    mma16816(c0[f][g*2+1], a4[f], b4[1], b4[3]);
                }
                if (isqk) {
                    uint32_t bk[4];
                    ldmx4(bk, st + G_B1 + boff);
                    #pragma unroll
                    for (int f = 0; f < 2; f++) {
                        mma16816(c1[f][g*2],   a4[f], bk[0], bk[2]);
                        mma16816(c1[f][g*2+1], a4[f], bk[1], bk[3]);
                    }
                }
            }
        }
        __syncthreads();
    }

    const int gid = lane >> 2, qc = (lane & 3) * 2;
    #pragma unroll
    for (int f = 0; f < 2; f++) {
        #pragma unroll
        for (int rr = 0; rr < 2; rr++) {
            int m = m0 + mw * 32 + f * 16 + gid + rr * 8;
            int b = m >> 11, t = m & 2047;
            size_t base = (((size_t)(b * Hn + h)) * Tn + t) * Dn + nw * 32;
            if (isqk) {
                #pragma unroll
                for (int j = 0; j < 4; j++) {
                    // q pre-scaled by kScale (folds (AC+BD)*scale into the GEMMs)
                    *reinterpret_cast<uint32_t*>(g_q + base + j * 8 + qc) =
                        pack2h(c0[f][j][rr*2] * kScale, c0[f][j][rr*2 + 1] * kScale);
                    *reinterpret_cast<uint32_t*>(g_k + base + j * 8 + qc) =
                        pack2h(c1[f][j][rr*2], c1[f][j][rr*2 + 1]);
                }
            } else {
                #pragma unroll
                for (int j = 0; j < 4; j++)
                    *reinterpret_cast<uint32_t*>(g_v + base + j * 8 + qc) =
                        pack2h(c0[f][j][rr*2], c0[f][j][rr*2 + 1]);
            }
        }
    }
}

// ---------------------------------------------------------------------------
// Kernel 3: output projection + bias. (unchanged from R15)
// ---------------------------------------------------------------------------
__global__ __launch_bounds__(256) void proj_mm(
    const float* __restrict__ bp, float* __restrict__ outp)
{
    extern __shared__ char smc[];
    const uint32_t smb = smem_u32(smc);
    const int tid = threadIdx.x;
    const int wm  = tid >> 5;
    const int lane = tid & 31;
    const int mw = wm >> 1;
    const int nw = wm & 1;
    const int lr = lane & 15;
    const int lc = (lane >> 4) << 3;

    const int m0 = blockIdx.x * 128;
    const int n0 = blockIdx.y * 64;

    float c[2][4][4] = {};

    {
        const uint32_t st = smb + GST(0);
        #pragma unroll
        for (int i = 0; i < 4; i++) {
            int u = tid + i * 256;
            int row = u >> 3, g = u & 7;
            cpa16(st + G_A + (uint32_t)(row * LDT + g * 16),
                  g_att + (size_t)(m0 + row) * Cn + g * 8);
        }
        #pragma unroll
        for (int i = 0; i < 2; i++) {
            int u = tid + i * 256;
            int d = u >> 3, g = u & 7;
            uint32_t dst = (uint32_t)(d * LDT + g * 16);
            size_t src = (size_t)(n0 + d) * Cn + g * 8;
            cpa16(st + G_B0 + dst, g_wpth + src);
            cpa16(st + G_B1 + dst, g_wptl + src);
        }
        cpa_commit();
    }

    for (int kb = 0; kb < 8; kb++) {
        if (kb + 1 < 8) {
            const int c1k = (kb + 1) * 64;
            const uint32_t st = smb + GST((kb + 1) & 1);
            #pragma unroll
            for (int i = 0; i < 4; i++) {
                int u = tid + i * 256;
                int row = u >> 3, g = u & 7;
                cpa16(st + G_A + (uint32_t)(row * LDT + g * 16),
                      g_att + (size_t)(m0 + row) * Cn + c1k + g * 8);
            }
            #pragma unroll
            for (int i = 0; i < 2; i++) {
                int u = tid + i * 256;
                int d = u >> 3, g = u & 7;
                uint32_t dst = (uint32_t)(d * LDT + g * 16);
                size_t src = (size_t)(n0 + d) * Cn + c1k + g * 8;
                cpa16(st + G_B0 + dst, g_wpth + src);
                cpa16(st + G_B1 + dst, g_wptl + src);
            }
        }
        cpa_commit();
        cpa_wait1();
        __syncthreads();

        const uint32_t st = smb + GST(kb & 1);
        #pragma unroll
        for (int ks = 0; ks < 4; ks++) {
            const int k0 = ks * 16;
            uint32_t a4[2][4];
            #pragma unroll
            for (int f = 0; f < 2; f++)
                ldmx4(a4[f], st + G_A +
                      (uint32_t)((mw * 32 + f * 16 + lr) * LDT + (k0 + lc) * 2));
            #pragma unroll
            for (int g = 0; g < 2; g++) {
                uint32_t boff = (uint32_t)((nw * 32 + g * 16 + lr) * LDT + (k0 + lc) * 2);
                uint32_t bh[4], bl[4];
                ldmx4(bh, st + G_B0 + boff);
                ldmx4(bl, st + G_B1 + boff);
                #pragma unroll
                for (int f = 0; f < 2; f++) {
                    mma16816(c[f][g*2],   a4[f], bh[0], bh[2]);
                    mma16816(c[f][g*2],   a4[f], bl[0], bl[2]);
                    mma16816(c[f][g*2+1], a4[f], bh[1], bh[3]);
                    mma16816(c[f][g*2+1], a4[f], bl[1], bl[3]);
                }
            }
        }
        __syncthreads();
    }

    const int gid = lane >> 2, qc = (lane & 3) * 2;
    #pragma unroll
    for (int f = 0; f < 2; f++) {
        #pragma unroll
        for (int rr = 0; rr < 2; rr++) {
            int m = m0 + mw * 32 + f * 16 + gid + rr * 8;
            float* op = outp + (size_t)m * Cn + n0 + nw * 32;
            #pragma unroll
            for (int j = 0; j < 4; j++) {
                float2 bv = *reinterpret_cast<const float2*>(
                    bp + n0 + nw * 32 + j * 8 + qc);
                *reinterpret_cast<float2*>(op + j * 8 + qc) =
                    make_float2(c[f][j][rr*2] + bv.x, c[f][j][rr*2 + 1] + bv.y);
            }
        }
    }
}

// ---------------------------------------------------------------------------
// Kernel 2: flash attention. Shifted-diagonal R ring (phase-indexed), mask
// only on diagonal tiles, q pre-scaled. Two query blocks per CTA.
// smem = 36864 (KV x2) + 27648 (W ring) + 34816 (R ring x2 grp) = 99328.
// ---------------------------------------------------------------------------
#define SBUF(s)   ((s) * 18432)             // K +0, V +9216
#define SB_K      0
#define SB_V      9216
#define W_SLOT(w) (36864 + (w) * 9216)
#define R_BASE    64512                     // 2 x (64 rows x 136 halves); Q alias
#define LDR2      136
#define ATT_SMEM  99328

__global__ __launch_bounds__(256, 2) void attn_mm()
{
    extern __shared__ char smc[];
    const uint32_t smb = smem_u32(smc);

    const int tid = threadIdx.x;
    const int wm  = tid >> 5;
    const int lane = tid & 31;
    const int grp = wm >> 2;               // 0: rows t0, 1: rows t0+64
    const int wg  = wm & 3;
    const int lr = lane & 15;
    const int lc = (lane >> 4) << 3;
    const int gid = lane >> 2, qc = (lane & 3) * 2;

    const int bh = blockIdx.x;
    const int h  = bh & (Hn - 1);
    const int b  = bh >> 3;
    const int t0 = (int)(gridDim.y - 1 - blockIdx.y) * 128;
    const int tq = t0 + 64 * grp;
    const int ntiles = t0 / 64 + 2;

    const __half* qg = g_q + (size_t)bh * Tn * Dn;
    const __half* kg = g_k + (size_t)bh * Tn * Dn;
    const __half* vg = g_v + (size_t)bh * Tn * Dn;
    const __half* rg = g_relh + (size_t)h * Tn * Dn;

    const int jm1 = Tn - 128 - t0;   // >= 0; W'A_j rows = jm1 + 64(j+1)

    // group's R ring (64 rows x 136 halves, shifted-diagonal layout)
    __half* Rg = reinterpret_cast<__half*>(smc + R_BASE) + grp * 8704;

    // ---- prologue: Q -> R region alias; windows; K0/V0
    #pragma unroll
    for (int i = 0; i < 4; i++) {
        int u = tid + i * 256;
        int row = u >> 3, g = u & 7;
        cpa16(smb + R_BASE + (uint32_t)(row * LDT + g * 16),
              qg + (size_t)(t0 + row) * Dn + g * 8);
    }
    #pragma unroll
    for (int i = 0; i < 2; i++) {
        int u = tid + i * 256;
        int row = u >> 3, g = u & 7;
        uint32_t dst = (uint32_t)(row * LDT + g * 16);
        cpa16(smb + W_SLOT(2) + dst, rg + (size_t)(jm1 + row) * Dn + g * 8);
        cpa16(smb + W_SLOT(0) + dst, rg + (size_t)(jm1 + 64 + row) * Dn + g * 8);
        if (t0 >= 64)
            cpa16(smb + W_SLOT(1) + dst, rg + (size_t)(jm1 + 128 + row) * Dn + g * 8);
        size_t s = (size_t)row * Dn + g * 8;
        cpa16(smb + SBUF(0) + SB_K + dst, kg + s);
        cpa16(smb + SBUF(0) + SB_V + dst, vg + s);
    }
    cpa_wait_all();
    __syncthreads();

    uint32_t q4[4][4];
    #pragma unroll
    for (int ks = 0; ks < 4; ks++) {
        uint32_t aoff = (uint32_t)((grp * 64 + wg * 16 + lr) * LDT + (ks * 16 + lc) * 2);
        ldmx4(q4[ks], smb + R_BASE + aoff);
    }
    __syncthreads();   // Q staging consumed; R region may be written now

    // ---- R preload (prev window for tile 0): store col = (jj + tl + 65) & 127
    {
        const uint32_t wb = smb + (grp ? W_SLOT(2) : W_SLOT(0));
        float c[8][4] = {};
        #pragma unroll
        for (int ks = 0; ks < 4; ks++) {
            #pragma unroll
            for (int ng = 0; ng < 4; ng++) {
                uint32_t bh4[4];
                uint32_t boff = (uint32_t)((ng * 16 + lr) * LDT + (ks * 16 + lc) * 2);
                ldmx4(bh4, wb + boff);
                mma16816(c[2*ng],   q4[ks], bh4[0], bh4[2]);
                mma16816(c[2*ng+1], q4[ks], bh4[1], bh4[3]);
            }
        }
        #pragma unroll
        for (int rr = 0; rr < 2; rr++) {
            int tl = wg*16 + gid + rr*8;
            int rowb = tl * LDR2;
            #pragma unroll
            for (int j = 0; j < 8; j++) {
                int jj = j*8 + qc;
                Rg[rowb + ((jj + tl + 65) & 127)]     = __float2half_rn(c[j][rr*2]);
                Rg[rowb + ((jj + 1 + tl + 65) & 127)] = __float2half_rn(c[j][rr*2+1]);
            }
        }
        __syncwarp();
    }
    __syncthreads();   // slot2 consumed before tile-0 prefetch may overwrite it

    float o[8][4] = {};
    float mrow[2] = {-1e30f, -1e30f};
    float lrow[2] = {};

    for (int i = 0; i < ntiles; i++) {
        const int s0 = i * 64;
        const int phs = (i & 1) << 6;      // 64 * tile parity

        if (i + 1 < ntiles) {
            const int s1 = s0 + 64;
            const uint32_t nb = smb + SBUF((i + 1) & 1);
            const bool needW = (64 * (i + 2) <= t0);
            #pragma unroll
            for (int u2 = 0; u2 < 2; u2++) {
                int u = tid + u2 * 256;
                int row = u >> 3, g = u & 7;
                uint32_t dst = (uint32_t)(row * LDT + g * 16);
                size_t s = (size_t)(s1 + row) * Dn + g * 8;
                cpa16(nb + SB_K + dst, kg + s);
                cpa16(nb + SB_V + dst, vg + s);
                if (needW)
                    cpa16(smb + W_SLOT((i + 2) % 3) + dst,
                          rg + (size_t)(jm1 + 64 * (i + 3) + row) * Dn + g * 8);
            }
        }
        cpa_commit();
        cpa_wait1();
        __syncthreads();

        const uint32_t kb = smb + SBUF(i & 1);
        const bool act  = (s0 <= tq);
        const bool hasR = (s0 < tq);

        if (act) {
            float c[8][4];

            // ---- R GEMM (new window): store col = (jjw + tl + 1 + phs) & 127
            if (hasR) {
                const uint32_t wb = smb + W_SLOT((i + 1 - grp) % 3);
                #pragma unroll
                for (int j = 0; j < 8; j++)
                    #pragma unroll
                    for (int z = 0; z < 4; z++) c[j][z] = 0.f;
                #pragma unroll
                for (int ks = 0; ks < 4; ks++) {
                    #pragma unroll
                    for (int ng = 0; ng < 4; ng++) {
                        uint32_t bh4[4];
                        uint32_t boff = (uint32_t)((ng * 16 + lr) * LDT + (ks * 16 + lc) * 2);
                        ldmx4(bh4, wb + boff);
                        mma16816(c[2*ng],   q4[ks], bh4[0], bh4[2]);
                        mma16816(c[2*ng+1], q4[ks], bh4[1], bh4[3]);
                    }
                }
                #pragma unroll
                for (int rr = 0; rr < 2; rr++) {
                    int tl = wg*16 + gid + rr*8;
                    int rowb = tl * LDR2;
                    #pragma unroll
                    for (int j = 0; j < 8; j++) {
                        int jjw = j*8 + qc;
                        Rg[rowb + ((jjw + tl + 1 + phs) & 127)] =
                            __float2half_rn(c[j][rr*2]);
                        Rg[rowb + ((jjw + 1 + tl + 1 + phs) & 127)] =
                            __float2half_rn(c[j][rr*2+1]);
                    }
                }
                __syncwarp();
            }

            // ---- S GEMM ----
            #pragma unroll
            for (int j = 0; j < 8; j++)
                #pragma unroll
                for (int z = 0; z < 4; z++) c[j][z] = 0.f;
            #pragma unroll
            for (int ks = 0; ks < 4; ks++) {
                #pragma unroll
                for (int ng = 0; ng < 4; ng++) {
                    uint32_t bh4[4];
                    uint32_t boff = (uint32_t)((ng * 16 + lr) * LDT + (ks * 16 + lc) * 2);
                    ldmx4(bh4, kb + SB_K + boff);
                    mma16816(c[2*ng],   q4[ks], bh4[0], bh4[2]);
                    mma16816(c[2*ng+1], q4[ks], bh4[1], bh4[3]);
                }
            }

            // ---- gather BD: read col = sl_q + phs (aligned u32, branch-free)
            if (hasR) {
                #pragma unroll
                for (int rr = 0; rr < 2; rr++) {
                    int rowb = (wg*16 + gid + rr*8) * LDR2;
                    #pragma unroll
                    for (int j = 0; j < 8; j++) {
                        uint32_t pr = *reinterpret_cast<const uint32_t*>(
                            Rg + rowb + j*8 + qc + phs);
                        __half2 h2 = *reinterpret_cast<__half2*>(&pr);
                        c[j][rr*2]   += __low2float(h2);
                        c[j][rr*2+1] += __high2float(h2);
                    }
                }
            } else {
                // diag: only prev half (sl <= tl) is valid
                #pragma unroll
                for (int rr = 0; rr < 2; rr++) {
                    int tl = wg*16 + gid + rr*8;
                    int rowb = tl * LDR2;
                    #pragma unroll
                    for (int j = 0; j < 8; j++) {
                        #pragma unroll
                        for (int z = 0; z < 2; z++) {
                            int sl = j*8 + qc + z;
                            if (sl <= tl)
                                c[j][rr*2+z] += __half2float(Rg[rowb + sl + phs]);
                        }
                    }
                }
            }

            // ---- wrap corner (global tile 0,0 only; q pre-scaled) ----
            if (tq == 0 && s0 == 0 && wg == 0 && gid < 5) {
                int t = gid;
                #pragma unroll
                for (int z = 0; z < 2; z++) {
                    int s = qc + z;
                    if (s > t + 1 && s < 6) {
                        float bd = 0.f;
                        for (int d = 0; d < 64; d++)
                            bd += __half2float(qg[(t + 1) * Dn + d])
                                * __half2float(rg[(size_t)(s - t - 2) * Dn + d]);
                        c[0][z] += bd;
                    }
                }
            }

            // ---- mask (diag only) + online softmax (no scale; q pre-scaled) ----
            const bool diagg = (s0 == tq);
            #pragma unroll
            for (int rr = 0; rr < 2; rr++) {
                int t = tq + wg*16 + gid + rr*8;
                float rm = -1e30f;
                if (diagg) {
                    #pragma unroll
                    for (int j = 0; j < 8; j++) {
                        #pragma unroll
                        for (int z = 0; z < 2; z++) {
                            int s = s0 + j*8 + qc + z;
                            float v = (s <= t || s < 6) ? c[j][rr*2+z] : -1e30f;
                            c[j][rr*2+z] = v;
                            rm = fmaxf(rm, v);
                        }
                    }
                } else {
                    #pragma unroll
                    for (int j = 0; j < 8; j++) {
                        rm = fmaxf(rm, fmaxf(c[j][rr*2], c[j][rr*2+1]));
                    }
                }
                rm = fmaxf(rm, __shfl_xor_sync(0xffffffffu, rm, 1));
                rm = fmaxf(rm, __shfl_xor_sync(0xffffffffu, rm, 2));
                float mnew = fmaxf(mrow[rr], rm);
                float alpha = __expf(mrow[rr] - mnew);
                mrow[rr] = mnew;
                float rs = 0.f;
                #pragma unroll
                for (int j = 0; j < 8; j++) {
                    #pragma unroll
                    for (int z = 0; z < 2; z++) {
                        float p = __expf(c[j][rr*2+z] - mnew);
                        c[j][rr*2+z] = p;
                        rs += p;
                    }
                }
                rs += __shfl_xor_sync(0xffffffffu, rs, 1);
                rs += __shfl_xor_sync(0xffffffffu, rs, 2);
                lrow[rr] = lrow[rr] * alpha + rs;
                #pragma unroll
                for (int j = 0; j < 8; j++) {
                    o[j][rr*2]   *= alpha;
                    o[j][rr*2+1] *= alpha;
                }
            }

            // ---- O += P * V (2-MMA: (P_hi + P_lo) x V) ----
            #pragma unroll
            for (int kc = 0; kc < 4; kc++) {
                uint32_t p_hi[4], p_lo[4];
                split2h(c[2*kc][0],   c[2*kc][1],   p_hi[0], p_lo[0]);
                split2h(c[2*kc][2],   c[2*kc][3],   p_hi[1], p_lo[1]);
                split2h(c[2*kc+1][0], c[2*kc+1][1], p_hi[2], p_lo[2]);
                split2h(c[2*kc+1][2], c[2*kc+1][3], p_hi[3], p_lo[3]);
                uint32_t vbase = (uint32_t)(kc*16 + (lane & 7) + ((lane & 16) >> 1)) * LDT;
                #pragma unroll
                for (int ng = 0; ng < 4; ng++) {
                    uint32_t bv4[4];
                    uint32_t voff = vbase + (uint32_t)(ng*16 + (lane & 8)) * 2;
                    ldmx4t(bv4, kb + SB_V + voff);
                    mma16816(o[2*ng],   p_hi, bv4[0], bv4[2]);
                    mma16816(o[2*ng],   p_lo, bv4[0], bv4[2]);
                    mma16816(o[2*ng+1], p_hi, bv4[1], bv4[3]);
                    mma16816(o[2*ng+1], p_lo, bv4[1], bv4[3]);
                }
            }
        }
        __syncthreads();
    }

    // ---- epilogue: att = O / l -> single fp16 ----
    #pragma unroll
    for (int rr = 0; rr < 2; rr++) {
        int t = tq + wg*16 + gid + rr*8;
        float inv = 1.0f / lrow[rr];
        size_t base = ((size_t)b * Tn + t) * Cn + h * Dn;
        #pragma unroll
        for (int j = 0; j < 8; j++)
            *reinterpret_cast<uint32_t*>(g_att + base + j*8 + qc) =
                pack2h(o[j][rr*2] * inv, o[j][rr*2+1] * inv);
    }
}

// ---------------------------------------------------------------------------
extern "C" void kernel_launch(void* const* d_in, const int* in_sizes, int n_in,
                              void* d_out, int out_size)
{
    const float* x   = (const float*)d_in[0];
    const float* Wq  = (const float*)d_in[1];
    const float* Wk  = (const float*)d_in[2];
    const float* Wv  = (const float*)d_in[3];
    const float* rel = (const float*)d_in[4];
    const float* Wp  = (const float*)d_in[5];
    const float* bp  = (const float*)d_in[6];
    float* out = (float*)d_out;

    static __half *h_xh, *h_relh;
    static bool init = false;
    if (!init) {
        cudaGetSymbolAddress((void**)&h_xh, g_xh);
        cudaGetSymbolAddress((void**)&h_relh, g_relh);
        cudaFuncSetAttribute(qkv_mm,  cudaFuncAttributeMaxDynamicSharedMemorySize, GEMM_SMEM);
        cudaFuncSetAttribute(proj_mm, cudaFuncAttributeMaxDynamicSharedMemorySize, GEMM_SMEM);
        cudaFuncSetAttribute(attn_mm, cudaFuncAttributeMaxDynamicSharedMemorySize, ATT_SMEM);
        init = true;
    }

    conv_f16_2<<<(NX/4 + NR/4 + 255)/256, 256>>>(x, h_xh, NX/4, rel, h_relh, NR/4);
    conv_w<<<dim3(128, 8, 4), 256>>>(Wq, Wk, Wv, Wp);

    qkv_mm<<<dim3(64, 16), 256, GEMM_SMEM>>>();
    attn_mm<<<dim3(Bn * Hn, Tn / 128), 256, ATT_SMEM>>>();
    proj_mm<<<dim3(64, 8), 256, GEMM_SMEM>>>(bp, out);
}